// round 1
// baseline (speedup 1.0000x reference)
#include <cuda_runtime.h>
#include <cuda_bf16.h>
#include <math.h>

// Problem constants
#define BB 4
#define SS 1024
#define NN (BB*SS)      // 4096 tokens
#define DD 512
#define HH 8
#define DH 64
#define FFD 2048
#define VV 50257
#define NLAYERS 6

// Scratch (allocation-free: __device__ globals)
__device__ float g_x[NN*DD];
__device__ float g_h[NN*DD];
__device__ float g_q[NN*DD];
__device__ float g_k[NN*DD];
__device__ float g_v[NN*DD];
__device__ float g_ctx[NN*DD];
__device__ float g_ff[NN*FFD];

// ---------------------------------------------------------------------------
// Embedding: x[n] = emb[ids[n]] * sqrt(512) + pe[n % S]
// ---------------------------------------------------------------------------
__global__ void embed_kernel(const int* __restrict__ ids,
                             const float* __restrict__ emb,
                             const float* __restrict__ pe,
                             float* __restrict__ x) {
    int n = blockIdx.x;
    int tid = threadIdx.x;            // 128 threads, 4 floats each
    int id = ids[n];
    int s = n & (SS - 1);
    const float sq = 22.62741699796952f;   // sqrt(512)
    float4 e = reinterpret_cast<const float4*>(emb + (size_t)id * DD)[tid];
    float4 p = reinterpret_cast<const float4*>(pe + (size_t)s * DD)[tid];
    float4 o;
    o.x = e.x * sq + p.x; o.y = e.y * sq + p.y;
    o.z = e.z * sq + p.z; o.w = e.w * sq + p.w;
    reinterpret_cast<float4*>(x + (size_t)n * DD)[tid] = o;
}

// ---------------------------------------------------------------------------
// LayerNorm: one block (128 threads) per row of 512
// ---------------------------------------------------------------------------
__global__ void ln_kernel(const float* __restrict__ in, float* __restrict__ out,
                          const float* __restrict__ g, const float* __restrict__ b) {
    int row = blockIdx.x;
    int tid = threadIdx.x;            // 128
    const float4* xp = reinterpret_cast<const float4*>(in + (size_t)row * DD);
    float4 v = xp[tid];
    float s = v.x + v.y + v.z + v.w;
    float ss = v.x*v.x + v.y*v.y + v.z*v.z + v.w*v.w;
    #pragma unroll
    for (int o = 16; o > 0; o >>= 1) {
        s  += __shfl_xor_sync(0xffffffffu, s, o);
        ss += __shfl_xor_sync(0xffffffffu, ss, o);
    }
    __shared__ float rs[4], rss[4];
    int warp = tid >> 5;
    if ((tid & 31) == 0) { rs[warp] = s; rss[warp] = ss; }
    __syncthreads();
    float tot  = rs[0] + rs[1] + rs[2] + rs[3];
    float tots = rss[0] + rss[1] + rss[2] + rss[3];
    float mean = tot * (1.0f / DD);
    float var  = tots * (1.0f / DD) - mean * mean;
    float rstd = rsqrtf(var + 1e-5f);
    float4 gg = reinterpret_cast<const float4*>(g)[tid];
    float4 bb = reinterpret_cast<const float4*>(b)[tid];
    float4 o;
    o.x = (v.x - mean) * rstd * gg.x + bb.x;
    o.y = (v.y - mean) * rstd * gg.y + bb.y;
    o.z = (v.z - mean) * rstd * gg.z + bb.z;
    o.w = (v.w - mean) * rstd * gg.w + bb.w;
    reinterpret_cast<float4*>(out + (size_t)row * DD)[tid] = o;
}

// ---------------------------------------------------------------------------
// SGEMM: C[M,Nout] = A[M,K] @ B  (+bias, +gelu, +residual)
// TRANSB=false: B stored [K, Nout].   TRANSB=true: B stored [Nout, K].
// 128x128x16 tiles, 256 threads, 8x8 microtile.
// EPI: 1=bias, 2=gelu, 4=residual
// ---------------------------------------------------------------------------
__device__ __forceinline__ float gelu_exact(float v) {
    return 0.5f * v * (1.0f + erff(v * 0.70710678118654752f));
}

template<bool TRANSB, int EPI>
__global__ __launch_bounds__(256)
void gemm_kernel(const float* __restrict__ A, const float* __restrict__ B,
                 const float* __restrict__ bias, const float* __restrict__ resid,
                 float* __restrict__ C, int M, int Nout, int K) {
    __shared__ float As[16][128];
    __shared__ float Bs[16][128];
    int tid = threadIdx.x;
    int tx = tid & 15, ty = tid >> 4;
    int m0 = blockIdx.y * 128, n0 = blockIdx.x * 128;
    float acc[8][8];
    #pragma unroll
    for (int i = 0; i < 8; i++)
        #pragma unroll
        for (int j = 0; j < 8; j++) acc[i][j] = 0.f;

    for (int k0 = 0; k0 < K; k0 += 16) {
        #pragma unroll
        for (int i = 0; i < 2; i++) {
            int idx = tid + i * 256;              // 0..511
            int ar = idx >> 2;                    // 0..127
            int ak = (idx & 3) << 2;              // 0,4,8,12
            float4 av = *reinterpret_cast<const float4*>(
                A + (size_t)(m0 + ar) * K + k0 + ak);
            As[ak + 0][ar] = av.x; As[ak + 1][ar] = av.y;
            As[ak + 2][ar] = av.z; As[ak + 3][ar] = av.w;
            if (TRANSB) {
                int br = ar, bk = ak;
                float4 bv = make_float4(0.f, 0.f, 0.f, 0.f);
                if (n0 + br < Nout)
                    bv = *reinterpret_cast<const float4*>(
                        B + (size_t)(n0 + br) * K + k0 + bk);
                Bs[bk + 0][br] = bv.x; Bs[bk + 1][br] = bv.y;
                Bs[bk + 2][br] = bv.z; Bs[bk + 3][br] = bv.w;
            } else {
                int bk = idx >> 5;                // 0..15
                int bn = (idx & 31) << 2;         // 0..124
                *reinterpret_cast<float4*>(&Bs[bk][bn]) =
                    *reinterpret_cast<const float4*>(
                        B + (size_t)(k0 + bk) * Nout + n0 + bn);
            }
        }
        __syncthreads();
        #pragma unroll
        for (int k = 0; k < 16; k++) {
            float af[8], bf[8];
            *reinterpret_cast<float4*>(&af[0]) =
                *reinterpret_cast<float4*>(&As[k][ty * 8]);
            *reinterpret_cast<float4*>(&af[4]) =
                *reinterpret_cast<float4*>(&As[k][ty * 8 + 4]);
            *reinterpret_cast<float4*>(&bf[0]) =
                *reinterpret_cast<float4*>(&Bs[k][tx * 8]);
            *reinterpret_cast<float4*>(&bf[4]) =
                *reinterpret_cast<float4*>(&Bs[k][tx * 8 + 4]);
            #pragma unroll
            for (int i = 0; i < 8; i++)
                #pragma unroll
                for (int j = 0; j < 8; j++)
                    acc[i][j] += af[i] * bf[j];
        }
        __syncthreads();
    }

    #pragma unroll
    for (int i = 0; i < 8; i++) {
        int m = m0 + ty * 8 + i;
        #pragma unroll
        for (int j = 0; j < 8; j++) {
            int n = n0 + tx * 8 + j;
            if (!TRANSB || n < Nout) {
                float val = acc[i][j];
                if (EPI & 1) val += bias[n];
                if (EPI & 2) val = gelu_exact(val);
                size_t cidx = (size_t)m * Nout + n;
                if (EPI & 4) val += resid[cidx];
                C[cidx] = val;
            }
        }
    }
}

// ---------------------------------------------------------------------------
// Causal flash attention: one thread per query row, 128 rows per block.
// grid = (S/128, B*H). K/V tiles of 64 keys in smem.
// ---------------------------------------------------------------------------
__global__ __launch_bounds__(128)
void attn_kernel(const float* __restrict__ Q, const float* __restrict__ Km,
                 const float* __restrict__ Vm, float* __restrict__ ctx) {
    __shared__ float4 ks[64][16];
    __shared__ float4 vs[64][16];
    int bh = blockIdx.y;
    int b = bh >> 3, h = bh & 7;
    int r = blockIdx.x * 128 + threadIdx.x;      // query row in [0,S)

    const float* qp = Q + ((size_t)(b * SS + r) * DD + h * DH);
    float4 qf[16];
    #pragma unroll
    for (int c = 0; c < 16; c++) qf[c] = reinterpret_cast<const float4*>(qp)[c];

    float4 acc[16];
    #pragma unroll
    for (int c = 0; c < 16; c++) acc[c] = make_float4(0.f, 0.f, 0.f, 0.f);
    float m = -1e30f, l = 0.f;

    int ntiles = (blockIdx.x * 128) / 64 + 2;    // key tiles covering rows of this block
    for (int t = 0; t < ntiles; t++) {
        int kbase = t * 64;
        #pragma unroll
        for (int i = 0; i < 8; i++) {
            int idx = threadIdx.x + i * 128;     // 0..1023
            int j = idx >> 4, c = idx & 15;
            size_t off = (size_t)(b * SS + kbase + j) * DD + h * DH;
            ks[j][c] = reinterpret_cast<const float4*>(Km + off)[c];
            vs[j][c] = reinterpret_cast<const float4*>(Vm + off)[c];
        }
        __syncthreads();
        int jmax = r - kbase + 1;
        if (jmax > 64) jmax = 64;
        for (int j = 0; j < jmax; j++) {
            float s = 0.f;
            #pragma unroll
            for (int c = 0; c < 16; c++) {
                float4 kk = ks[j][c];
                s += qf[c].x * kk.x + qf[c].y * kk.y
                   + qf[c].z * kk.z + qf[c].w * kk.w;
            }
            s *= 0.125f;                          // / sqrt(D/H) = /8
            if (s > m) {
                float sc = __expf(m - s);
                l *= sc;
                #pragma unroll
                for (int c = 0; c < 16; c++) {
                    acc[c].x *= sc; acc[c].y *= sc;
                    acc[c].z *= sc; acc[c].w *= sc;
                }
                m = s;
            }
            float p = __expf(s - m);
            l += p;
            #pragma unroll
            for (int c = 0; c < 16; c++) {
                float4 vv = vs[j][c];
                acc[c].x += p * vv.x; acc[c].y += p * vv.y;
                acc[c].z += p * vv.z; acc[c].w += p * vv.w;
            }
        }
        __syncthreads();
    }

    float inv = 1.0f / l;
    float* op = ctx + ((size_t)(b * SS + r) * DD + h * DH);
    #pragma unroll
    for (int c = 0; c < 16; c++) {
        float4 o;
        o.x = acc[c].x * inv; o.y = acc[c].y * inv;
        o.z = acc[c].z * inv; o.w = acc[c].w * inv;
        reinterpret_cast<float4*>(op)[c] = o;
    }
}

// ---------------------------------------------------------------------------
// Host launch
// ---------------------------------------------------------------------------
extern "C" void kernel_launch(void* const* d_in, const int* in_sizes, int n_in,
                              void* d_out, int out_size) {
    const int*   ids   = (const int*)  d_in[0];
    const float* emb   = (const float*)d_in[1];
    const float* pe    = (const float*)d_in[2];
    const float* wq    = (const float*)d_in[3];
    const float* wk    = (const float*)d_in[4];
    const float* wv    = (const float*)d_in[5];
    const float* wo    = (const float*)d_in[6];
    const float* wo_b  = (const float*)d_in[7];
    const float* w1    = (const float*)d_in[8];
    const float* b1    = (const float*)d_in[9];
    const float* w2    = (const float*)d_in[10];
    const float* b2    = (const float*)d_in[11];
    const float* ln1_g = (const float*)d_in[12];
    const float* ln1_b = (const float*)d_in[13];
    const float* ln2_g = (const float*)d_in[14];
    const float* ln2_b = (const float*)d_in[15];
    const float* lnf_g = (const float*)d_in[16];
    const float* lnf_b = (const float*)d_in[17];
    float* out = (float*)d_out;

    float *x, *h, *q, *k, *v, *ctx, *ff;
    cudaGetSymbolAddress((void**)&x,   g_x);
    cudaGetSymbolAddress((void**)&h,   g_h);
    cudaGetSymbolAddress((void**)&q,   g_q);
    cudaGetSymbolAddress((void**)&k,   g_k);
    cudaGetSymbolAddress((void**)&v,   g_v);
    cudaGetSymbolAddress((void**)&ctx, g_ctx);
    cudaGetSymbolAddress((void**)&ff,  g_ff);

    embed_kernel<<<NN, 128>>>(ids, emb, pe, x);

    dim3 gProj(DD / 128, NN / 128);      // (4, 32)
    dim3 gFF1(FFD / 128, NN / 128);      // (16, 32)
    dim3 gAttn(SS / 128, BB * HH);       // (8, 32)

    for (int layer = 0; layer < NLAYERS; layer++) {
        ln_kernel<<<NN, 128>>>(x, h, ln1_g, ln1_b);
        gemm_kernel<false, 0><<<gProj, 256>>>(h, wq, nullptr, nullptr, q,   NN, DD, DD);
        gemm_kernel<false, 0><<<gProj, 256>>>(h, wk, nullptr, nullptr, k,   NN, DD, DD);
        gemm_kernel<false, 0><<<gProj, 256>>>(h, wv, nullptr, nullptr, v,   NN, DD, DD);
        attn_kernel<<<gAttn, 128>>>(q, k, v, ctx);
        gemm_kernel<false, 5><<<gProj, 256>>>(ctx, wo, wo_b, x, x, NN, DD, DD);
        ln_kernel<<<NN, 128>>>(x, h, ln2_g, ln2_b);
        gemm_kernel<false, 3><<<gFF1, 256>>>(h, w1, b1, nullptr, ff, NN, FFD, DD);
        gemm_kernel<false, 5><<<gProj, 256>>>(ff, w2, b2, x, x, NN, DD, FFD);
    }

    ln_kernel<<<NN, 128>>>(x, h, lnf_g, lnf_b);

    dim3 gLM((VV + 127) / 128, NN / 128);   // (393, 32)
    gemm_kernel<true, 0><<<gLM, 256>>>(h, emb, nullptr, nullptr, out, NN, VV, DD);
}

// round 4
// speedup vs baseline: 1.9089x; 1.9089x over previous
#include <cuda_runtime.h>
#include <cuda_bf16.h>
#include <math.h>
#include <stdint.h>

// Problem constants
#define BB 4
#define SS 1024
#define NN (BB*SS)      // 4096 tokens
#define DD 512
#define HH 8
#define DH 64
#define FFD 2048
#define VV 50257
#define NLAYERS 6
#define QKVD 1536       // fused qkv width

// ---------------------------------------------------------------------------
// Scratch (allocation-free: __device__ globals)
// ---------------------------------------------------------------------------
__device__ float g_x[NN*DD];
__device__ __nv_bfloat16 g_h_hi[NN*DD],  g_h_lo[NN*DD];
__device__ float g_qkv[NN*QKVD];
__device__ __nv_bfloat16 g_ctx_hi[NN*DD], g_ctx_lo[NN*DD];
__device__ __nv_bfloat16 g_ff_hi[NN*FFD], g_ff_lo[NN*FFD];
// transposed bf16 weights [N,K]
__device__ __nv_bfloat16 g_wqkvT_hi[3*DD*DD], g_wqkvT_lo[3*DD*DD];
__device__ __nv_bfloat16 g_woT_hi[DD*DD],     g_woT_lo[DD*DD];
__device__ __nv_bfloat16 g_w1T_hi[FFD*DD],    g_w1T_lo[FFD*DD];
__device__ __nv_bfloat16 g_w2T_hi[DD*FFD],    g_w2T_lo[DD*FFD];
__device__ __nv_bfloat16 g_embB_hi[VV*DD],    g_embB_lo[VV*DD];

// ---------------------------------------------------------------------------
// Helpers
// ---------------------------------------------------------------------------
__device__ __forceinline__ uint32_t smem_u32(const void* p) {
    uint32_t a;
    asm("{ .reg .u64 t; cvta.to.shared.u64 t, %1; cvt.u32.u64 %0, t; }"
        : "=r"(a) : "l"(p));
    return a;
}

__device__ __forceinline__ void ldm4(uint32_t* r, uint32_t addr) {
    asm volatile("ldmatrix.sync.aligned.m8n8.x4.shared.b16 {%0,%1,%2,%3}, [%4];"
                 : "=r"(r[0]), "=r"(r[1]), "=r"(r[2]), "=r"(r[3]) : "r"(addr));
}

__device__ __forceinline__ void mma16816(float* c, const uint32_t* a,
                                         uint32_t b0, uint32_t b1) {
    asm volatile(
        "mma.sync.aligned.m16n8k16.row.col.f32.bf16.bf16.f32 "
        "{%0,%1,%2,%3}, {%4,%5,%6,%7}, {%8,%9}, {%0,%1,%2,%3};"
        : "+f"(c[0]), "+f"(c[1]), "+f"(c[2]), "+f"(c[3])
        : "r"(a[0]), "r"(a[1]), "r"(a[2]), "r"(a[3]), "r"(b0), "r"(b1));
}

__device__ __forceinline__ void cp_async16(uint32_t dst, const void* src, int szbytes) {
    asm volatile("cp.async.cg.shared.global [%0], [%1], 16, %2;"
                 :: "r"(dst), "l"(src), "r"(szbytes));
}
#define CP_COMMIT() asm volatile("cp.async.commit_group;" ::: "memory")
template<int N>
__device__ __forceinline__ void cp_wait() {
    asm volatile("cp.async.wait_group %0;" :: "n"(N) : "memory");
}

// hi/lo split helper (2 floats -> packed bf16x2 hi and lo)
__device__ __forceinline__ void split2(float x, float y, uint32_t& h, uint32_t& l) {
    __nv_bfloat16 h0 = __float2bfloat16_rn(x);
    __nv_bfloat16 h1 = __float2bfloat16_rn(y);
    __nv_bfloat16 l0 = __float2bfloat16_rn(x - __bfloat162float(h0));
    __nv_bfloat16 l1 = __float2bfloat16_rn(y - __bfloat162float(h1));
    h = (uint32_t)__bfloat16_as_ushort(h0) | ((uint32_t)__bfloat16_as_ushort(h1) << 16);
    l = (uint32_t)__bfloat16_as_ushort(l0) | ((uint32_t)__bfloat16_as_ushort(l1) << 16);
}
__device__ __forceinline__ void split4(float4 v, uint2& h, uint2& l) {
    split2(v.x, v.y, h.x, l.x);
    split2(v.z, v.w, h.y, l.y);
}

__device__ __forceinline__ float gelu_exact(float v) {
    return 0.5f * v * (1.0f + erff(v * 0.70710678118654752f));
}

// ---------------------------------------------------------------------------
// Weight conversion: W [K,N] fp32 -> hi/lo [N,K] bf16 (transpose)
// ---------------------------------------------------------------------------
__global__ void conv_wT(const float* __restrict__ W, __nv_bfloat16* __restrict__ hi,
                        __nv_bfloat16* __restrict__ lo, int K, int N) {
    __shared__ float t[32][33];
    int n0 = blockIdx.x * 32, k0 = blockIdx.y * 32;
    int tx = threadIdx.x, ty = threadIdx.y;
    #pragma unroll
    for (int r = 0; r < 4; r++)
        t[ty + r*8][tx] = W[(size_t)(k0 + ty + r*8) * N + n0 + tx];
    __syncthreads();
    #pragma unroll
    for (int r = 0; r < 4; r++) {
        float v = t[tx][ty + r*8];
        __nv_bfloat16 h = __float2bfloat16_rn(v);
        size_t o = (size_t)(n0 + ty + r*8) * K + k0 + tx;
        hi[o] = h;
        lo[o] = __float2bfloat16_rn(v - __bfloat162float(h));
    }
}

// Elementwise split (no transpose), float4 granularity
__global__ void conv_split4(const float* __restrict__ src,
                            __nv_bfloat16* __restrict__ hi,
                            __nv_bfloat16* __restrict__ lo, int n4) {
    int i = blockIdx.x * 256 + threadIdx.x;
    if (i >= n4) return;
    float4 v = reinterpret_cast<const float4*>(src)[i];
    uint2 h, l;
    split4(v, h, l);
    reinterpret_cast<uint2*>(hi)[i] = h;
    reinterpret_cast<uint2*>(lo)[i] = l;
}

// ---------------------------------------------------------------------------
// Embedding
// ---------------------------------------------------------------------------
__global__ void embed_kernel(const int* __restrict__ ids,
                             const float* __restrict__ emb,
                             const float* __restrict__ pe,
                             float* __restrict__ x) {
    int n = blockIdx.x;
    int tid = threadIdx.x;
    int id = ids[n];
    int s = n & (SS - 1);
    const float sq = 22.62741699796952f;
    float4 e = reinterpret_cast<const float4*>(emb + (size_t)id * DD)[tid];
    float4 p = reinterpret_cast<const float4*>(pe + (size_t)s * DD)[tid];
    float4 o;
    o.x = e.x * sq + p.x; o.y = e.y * sq + p.y;
    o.z = e.z * sq + p.z; o.w = e.w * sq + p.w;
    reinterpret_cast<float4*>(x + (size_t)n * DD)[tid] = o;
}

// ---------------------------------------------------------------------------
// LayerNorm -> bf16 hi/lo
// ---------------------------------------------------------------------------
__global__ void ln_kernel(const float* __restrict__ in,
                          __nv_bfloat16* __restrict__ out_hi,
                          __nv_bfloat16* __restrict__ out_lo,
                          const float* __restrict__ g, const float* __restrict__ b) {
    int row = blockIdx.x;
    int tid = threadIdx.x;    // 128
    float4 v = reinterpret_cast<const float4*>(in + (size_t)row * DD)[tid];
    float s = v.x + v.y + v.z + v.w;
    float ss = v.x*v.x + v.y*v.y + v.z*v.z + v.w*v.w;
    #pragma unroll
    for (int o = 16; o > 0; o >>= 1) {
        s  += __shfl_xor_sync(0xffffffffu, s, o);
        ss += __shfl_xor_sync(0xffffffffu, ss, o);
    }
    __shared__ float rs[4], rss[4];
    int warp = tid >> 5;
    if ((tid & 31) == 0) { rs[warp] = s; rss[warp] = ss; }
    __syncthreads();
    float mean = (rs[0]+rs[1]+rs[2]+rs[3]) * (1.0f/DD);
    float var  = (rss[0]+rss[1]+rss[2]+rss[3]) * (1.0f/DD) - mean*mean;
    float rstd = rsqrtf(var + 1e-5f);
    float4 gg = reinterpret_cast<const float4*>(g)[tid];
    float4 bb = reinterpret_cast<const float4*>(b)[tid];
    float4 o;
    o.x = (v.x - mean)*rstd*gg.x + bb.x;
    o.y = (v.y - mean)*rstd*gg.y + bb.y;
    o.z = (v.z - mean)*rstd*gg.z + bb.z;
    o.w = (v.w - mean)*rstd*gg.w + bb.w;
    uint2 h, l;
    split4(o, h, l);
    reinterpret_cast<uint2*>(out_hi + (size_t)row * DD)[tid] = h;
    reinterpret_cast<uint2*>(out_lo + (size_t)row * DD)[tid] = l;
}

// ---------------------------------------------------------------------------
// bf16-split GEMM via mma.sync (HMMA): C[M,Nout] = A[M,K] @ B^T (B is [Nout,K])
// CTA tile 128x128, K-chunk 64, cp.async double-buffered, 8 warps (4Mx2N),
// warp tile 32x64, mma.m16n8k16. 3 passes: Ah*Bh + Ah*Bl + Al*Bh (same acc).
// EPI bits: 1=bias, 2=gelu, 4=resid.  SPLIT: write bf16 hi/lo instead of fp32.
// ---------------------------------------------------------------------------
#define KC 64
#define SUBT 16384                      // bytes per sub-tile (128 rows x 128B)
#define STAGE (4*SUBT)                  // Ahi,Alo,Bhi,Blo
#define GEMM_SMEM_BYTES (2*STAGE)       // 131072

template<int EPI, bool SPLIT>
__global__ __launch_bounds__(256, 1)
void gemm_mma(const __nv_bfloat16* __restrict__ Ahi, const __nv_bfloat16* __restrict__ Alo,
              const __nv_bfloat16* __restrict__ Bhi, const __nv_bfloat16* __restrict__ Blo,
              const float* __restrict__ bias, const float* __restrict__ resid,
              float* __restrict__ C, __nv_bfloat16* __restrict__ Chi,
              __nv_bfloat16* __restrict__ Clo, int Nout, int K) {
    extern __shared__ char smem[];
    uint32_t sb = smem_u32(smem);
    const int tid = threadIdx.x;
    const int lane = tid & 31, wid = tid >> 5;
    const int m0 = blockIdx.y * 128, n0 = blockIdx.x * 128;
    const int warp_m = (wid >> 1) * 32;
    const int warp_n = (wid & 1) * 64;

    float acc[2][8][4];
    #pragma unroll
    for (int i = 0; i < 2; i++)
        #pragma unroll
        for (int j = 0; j < 8; j++)
            #pragma unroll
            for (int e = 0; e < 4; e++) acc[i][j][e] = 0.f;

    const int nch = K >> 6;

    // ---- stage loader (cp.async): 4 sub-tiles of 128x64 bf16, SW128 swizzle
    auto load_stage = [&](int buf, int k0) {
        uint32_t base = sb + buf * STAGE;
        const __nv_bfloat16* srcs[4] = {Ahi, Alo, Bhi, Blo};
        #pragma unroll
        for (int sub = 0; sub < 4; sub++) {
            const __nv_bfloat16* P = srcs[sub];
            int row0 = (sub < 2) ? m0 : n0;
            bool guard = (sub >= 2);
            uint32_t dbase = base + sub * SUBT;
            #pragma unroll
            for (int it = 0; it < 4; it++) {
                int u = tid + it * 256;           // 0..1023
                int row = u >> 3, c = u & 7;
                uint32_t dst = dbase + row * 128 + ((c ^ (row & 7)) * 16);
                const __nv_bfloat16* g = P + (size_t)(row0 + row) * K + k0 + c * 8;
                int sz = 16;
                if (guard && (row0 + row >= Nout)) { g = P; sz = 0; }
                cp_async16(dst, g, sz);
            }
        }
    };

    // per-thread fragment rows (precompute)
    int ra[2];
    ra[0] = warp_m + (lane & 15);
    ra[1] = ra[0] + 16;
    const int ca = lane >> 4;              // 0/1: k-halves for A ldmatrix
    int rB[4];
    #pragma unroll
    for (int nb = 0; nb < 4; nb++)
        rB[nb] = warp_n + nb * 16 + ((lane >> 4) & 1) * 8 + (lane & 7);
    const int kcB = (lane >> 3) & 1;

    auto compute = [&](int buf) {
        uint32_t base = sb + buf * STAGE;
        #pragma unroll
        for (int ks = 0; ks < 4; ks++) {
            uint32_t ah[2][4], al[2][4], bb[4][4];
            #pragma unroll
            for (int mb = 0; mb < 2; mb++) {
                uint32_t off = ra[mb] * 128 + (((ks*2 + ca) ^ (ra[mb] & 7)) * 16);
                ldm4(ah[mb], base + off);
                ldm4(al[mb], base + SUBT + off);
            }
            #pragma unroll
            for (int nb = 0; nb < 4; nb++) {
                uint32_t off = rB[nb] * 128 + (((ks*2 + kcB) ^ (rB[nb] & 7)) * 16);
                ldm4(bb[nb], base + 2*SUBT + off);
            }
            #pragma unroll
            for (int mb = 0; mb < 2; mb++)
                #pragma unroll
                for (int nb = 0; nb < 4; nb++) {
                    mma16816(acc[mb][nb*2],   ah[mb], bb[nb][0], bb[nb][1]);
                    mma16816(acc[mb][nb*2+1], ah[mb], bb[nb][2], bb[nb][3]);
                }
            #pragma unroll
            for (int mb = 0; mb < 2; mb++)
                #pragma unroll
                for (int nb = 0; nb < 4; nb++) {
                    mma16816(acc[mb][nb*2],   al[mb], bb[nb][0], bb[nb][1]);
                    mma16816(acc[mb][nb*2+1], al[mb], bb[nb][2], bb[nb][3]);
                }
            #pragma unroll
            for (int nb = 0; nb < 4; nb++) {
                uint32_t off = rB[nb] * 128 + (((ks*2 + kcB) ^ (rB[nb] & 7)) * 16);
                ldm4(bb[nb], base + 3*SUBT + off);
            }
            #pragma unroll
            for (int mb = 0; mb < 2; mb++)
                #pragma unroll
                for (int nb = 0; nb < 4; nb++) {
                    mma16816(acc[mb][nb*2],   ah[mb], bb[nb][0], bb[nb][1]);
                    mma16816(acc[mb][nb*2+1], ah[mb], bb[nb][2], bb[nb][3]);
                }
        }
    };

    // ---- pipeline
    load_stage(0, 0);
    CP_COMMIT();
    for (int c = 0; c < nch; c++) {
        if (c + 1 < nch) {
            load_stage((c + 1) & 1, (c + 1) << 6);
            CP_COMMIT();
            cp_wait<1>();
        } else {
            cp_wait<0>();
        }
        __syncthreads();
        compute(c & 1);
        __syncthreads();
    }

    // ---- epilogue from accumulator fragments
    const int gid = lane >> 2, qid = lane & 3;
    #pragma unroll
    for (int mb = 0; mb < 2; mb++) {
        #pragma unroll
        for (int nf = 0; nf < 8; nf++) {
            int n = n0 + warp_n + nf * 8 + qid * 2;
            #pragma unroll
            for (int hh = 0; hh < 2; hh++) {
                int m = m0 + warp_m + mb * 16 + gid + hh * 8;
                float vx = acc[mb][nf][hh*2];
                float vy = acc[mb][nf][hh*2 + 1];
                if (EPI & 1) { vx += bias[n]; vy += bias[n + 1]; }
                if (EPI & 2) { vx = gelu_exact(vx); vy = gelu_exact(vy); }
                size_t o = (size_t)m * Nout + n;
                if (EPI & 4) {
                    float2 r = *reinterpret_cast<const float2*>(resid + o);
                    vx += r.x; vy += r.y;
                }
                if (SPLIT) {
                    uint32_t h, l;
                    split2(vx, vy, h, l);
                    *reinterpret_cast<uint32_t*>(Chi + o) = h;
                    *reinterpret_cast<uint32_t*>(Clo + o) = l;
                } else {
                    // scalar stores: o may be odd (Nout=50257 LM head) -> no
                    // 8-byte vector stores allowed here (misaligned address)
                    if (n < Nout)     C[o]     = vx;
                    if (n + 1 < Nout) C[o + 1] = vy;
                }
            }
        }
    }
}

// ---------------------------------------------------------------------------
// Causal flash attention (fp32), qkv fused layout [M, 1536], out -> bf16 hi/lo
// ---------------------------------------------------------------------------
__global__ __launch_bounds__(128)
void attn_kernel(const float* __restrict__ qkv,
                 __nv_bfloat16* __restrict__ ctx_hi,
                 __nv_bfloat16* __restrict__ ctx_lo) {
    __shared__ float4 ks[64][16];
    __shared__ float4 vs[64][16];
    int bh = blockIdx.y;
    int b = bh >> 3, h = bh & 7;
    int r = blockIdx.x * 128 + threadIdx.x;

    const float* qp = qkv + ((size_t)(b * SS + r) * QKVD + h * DH);
    float4 qf[16];
    #pragma unroll
    for (int c = 0; c < 16; c++) qf[c] = reinterpret_cast<const float4*>(qp)[c];

    float4 acc[16];
    #pragma unroll
    for (int c = 0; c < 16; c++) acc[c] = make_float4(0.f, 0.f, 0.f, 0.f);
    float m = -1e30f, l = 0.f;

    int ntiles = (blockIdx.x * 128) / 64 + 2;
    for (int t = 0; t < ntiles; t++) {
        int kbase = t * 64;
        #pragma unroll
        for (int i = 0; i < 8; i++) {
            int idx = threadIdx.x + i * 128;
            int j = idx >> 4, c = idx & 15;
            size_t off = (size_t)(b * SS + kbase + j) * QKVD + h * DH;
            ks[j][c] = reinterpret_cast<const float4*>(qkv + off + DD)[c];
            vs[j][c] = reinterpret_cast<const float4*>(qkv + off + 2*DD)[c];
        }
        __syncthreads();
        int jmax = r - kbase + 1;
        if (jmax > 64) jmax = 64;
        for (int j = 0; j < jmax; j++) {
            float s = 0.f;
            #pragma unroll
            for (int c = 0; c < 16; c++) {
                float4 kk = ks[j][c];
                s += qf[c].x*kk.x + qf[c].y*kk.y + qf[c].z*kk.z + qf[c].w*kk.w;
            }
            s *= 0.125f;
            if (s > m) {
                float sc = __expf(m - s);
                l *= sc;
                #pragma unroll
                for (int c = 0; c < 16; c++) {
                    acc[c].x *= sc; acc[c].y *= sc; acc[c].z *= sc; acc[c].w *= sc;
                }
                m = s;
            }
            float p = __expf(s - m);
            l += p;
            #pragma unroll
            for (int c = 0; c < 16; c++) {
                float4 vv = vs[j][c];
                acc[c].x += p*vv.x; acc[c].y += p*vv.y;
                acc[c].z += p*vv.z; acc[c].w += p*vv.w;
            }
        }
        __syncthreads();
    }

    float inv = 1.0f / l;
    size_t off = (size_t)(b * SS + r) * DD + h * DH;
    #pragma unroll
    for (int c = 0; c < 16; c++) {
        float4 o;
        o.x = acc[c].x*inv; o.y = acc[c].y*inv; o.z = acc[c].z*inv; o.w = acc[c].w*inv;
        uint2 hh, ll;
        split4(o, hh, ll);
        reinterpret_cast<uint2*>(ctx_hi + off)[c] = hh;
        reinterpret_cast<uint2*>(ctx_lo + off)[c] = ll;
    }
}

// ---------------------------------------------------------------------------
// Host launch
// ---------------------------------------------------------------------------
extern "C" void kernel_launch(void* const* d_in, const int* in_sizes, int n_in,
                              void* d_out, int out_size) {
    const int*   ids   = (const int*)  d_in[0];
    const float* emb   = (const float*)d_in[1];
    const float* pe    = (const float*)d_in[2];
    const float* wq    = (const float*)d_in[3];
    const float* wk    = (const float*)d_in[4];
    const float* wv    = (const float*)d_in[5];
    const float* wo    = (const float*)d_in[6];
    const float* wo_b  = (const float*)d_in[7];
    const float* w1    = (const float*)d_in[8];
    const float* b1    = (const float*)d_in[9];
    const float* w2    = (const float*)d_in[10];
    const float* b2    = (const float*)d_in[11];
    const float* ln1_g = (const float*)d_in[12];
    const float* ln1_b = (const float*)d_in[13];
    const float* ln2_g = (const float*)d_in[14];
    const float* ln2_b = (const float*)d_in[15];
    const float* lnf_g = (const float*)d_in[16];
    const float* lnf_b = (const float*)d_in[17];
    float* out = (float*)d_out;

    float *x, *qkv;
    __nv_bfloat16 *h_hi, *h_lo, *ctx_hi, *ctx_lo, *ff_hi, *ff_lo;
    __nv_bfloat16 *wqkvT_hi, *wqkvT_lo, *woT_hi, *woT_lo;
    __nv_bfloat16 *w1T_hi, *w1T_lo, *w2T_hi, *w2T_lo, *embB_hi, *embB_lo;
    cudaGetSymbolAddress((void**)&x, g_x);
    cudaGetSymbolAddress((void**)&qkv, g_qkv);
    cudaGetSymbolAddress((void**)&h_hi, g_h_hi);
    cudaGetSymbolAddress((void**)&h_lo, g_h_lo);
    cudaGetSymbolAddress((void**)&ctx_hi, g_ctx_hi);
    cudaGetSymbolAddress((void**)&ctx_lo, g_ctx_lo);
    cudaGetSymbolAddress((void**)&ff_hi, g_ff_hi);
    cudaGetSymbolAddress((void**)&ff_lo, g_ff_lo);
    cudaGetSymbolAddress((void**)&wqkvT_hi, g_wqkvT_hi);
    cudaGetSymbolAddress((void**)&wqkvT_lo, g_wqkvT_lo);
    cudaGetSymbolAddress((void**)&woT_hi, g_woT_hi);
    cudaGetSymbolAddress((void**)&woT_lo, g_woT_lo);
    cudaGetSymbolAddress((void**)&w1T_hi, g_w1T_hi);
    cudaGetSymbolAddress((void**)&w1T_lo, g_w1T_lo);
    cudaGetSymbolAddress((void**)&w2T_hi, g_w2T_hi);
    cudaGetSymbolAddress((void**)&w2T_lo, g_w2T_lo);
    cudaGetSymbolAddress((void**)&embB_hi, g_embB_hi);
    cudaGetSymbolAddress((void**)&embB_lo, g_embB_lo);

    cudaFuncSetAttribute(gemm_mma<0, false>, cudaFuncAttributeMaxDynamicSharedMemorySize, GEMM_SMEM_BYTES);
    cudaFuncSetAttribute(gemm_mma<5, false>, cudaFuncAttributeMaxDynamicSharedMemorySize, GEMM_SMEM_BYTES);
    cudaFuncSetAttribute(gemm_mma<3, true >, cudaFuncAttributeMaxDynamicSharedMemorySize, GEMM_SMEM_BYTES);

    // weight conversions (run each replay; cheap)
    dim3 cb(32, 8);
    conv_wT<<<dim3(DD/32, DD/32), cb>>>(wq, wqkvT_hi,            wqkvT_lo,            DD, DD);
    conv_wT<<<dim3(DD/32, DD/32), cb>>>(wk, wqkvT_hi + DD*DD,    wqkvT_lo + DD*DD,    DD, DD);
    conv_wT<<<dim3(DD/32, DD/32), cb>>>(wv, wqkvT_hi + 2*DD*DD,  wqkvT_lo + 2*DD*DD,  DD, DD);
    conv_wT<<<dim3(DD/32, DD/32), cb>>>(wo, woT_hi, woT_lo, DD, DD);
    conv_wT<<<dim3(FFD/32, DD/32), cb>>>(w1, w1T_hi, w1T_lo, DD, FFD);
    conv_wT<<<dim3(DD/32, FFD/32), cb>>>(w2, w2T_hi, w2T_lo, FFD, DD);
    {
        int n4 = VV * DD / 4;
        conv_split4<<<(n4 + 255) / 256, 256>>>(emb, embB_hi, embB_lo, n4);
    }

    embed_kernel<<<NN, 128>>>(ids, emb, pe, x);

    dim3 gQKV(QKVD/128, NN/128);     // (12, 32)
    dim3 gProj(DD/128, NN/128);      // (4, 32)
    dim3 gFF1(FFD/128, NN/128);      // (16, 32)
    dim3 gAttn(SS/128, BB*HH);       // (8, 32)

    for (int layer = 0; layer < NLAYERS; layer++) {
        ln_kernel<<<NN, 128>>>(x, h_hi, h_lo, ln1_g, ln1_b);
        gemm_mma<0, false><<<gQKV, 256, GEMM_SMEM_BYTES>>>(
            h_hi, h_lo, wqkvT_hi, wqkvT_lo, nullptr, nullptr,
            qkv, nullptr, nullptr, QKVD, DD);
        attn_kernel<<<gAttn, 128>>>(qkv, ctx_hi, ctx_lo);
        gemm_mma<5, false><<<gProj, 256, GEMM_SMEM_BYTES>>>(
            ctx_hi, ctx_lo, woT_hi, woT_lo, wo_b, x,
            x, nullptr, nullptr, DD, DD);
        ln_kernel<<<NN, 128>>>(x, h_hi, h_lo, ln2_g, ln2_b);
        gemm_mma<3, true><<<gFF1, 256, GEMM_SMEM_BYTES>>>(
            h_hi, h_lo, w1T_hi, w1T_lo, b1, nullptr,
            nullptr, ff_hi, ff_lo, FFD, DD);
        gemm_mma<5, false><<<gProj, 256, GEMM_SMEM_BYTES>>>(
            ff_hi, ff_lo, w2T_hi, w2T_lo, b2, x,
            x, nullptr, nullptr, DD, FFD);
    }

    ln_kernel<<<NN, 128>>>(x, h_hi, h_lo, lnf_g, lnf_b);

    dim3 gLM((VV + 127) / 128, NN / 128);   // (393, 32)
    gemm_mma<0, false><<<gLM, 256, GEMM_SMEM_BYTES>>>(
        h_hi, h_lo, embB_hi, embB_lo, nullptr, nullptr,
        out, nullptr, nullptr, VV, DD);
}

// round 5
// speedup vs baseline: 1.9296x; 1.0109x over previous
#include <cuda_runtime.h>
#include <cuda_bf16.h>
#include <math.h>
#include <stdint.h>

// Problem constants
#define BB 4
#define SS 1024
#define NN (BB*SS)      // 4096 tokens
#define DD 512
#define HH 8
#define DH 64
#define FFD 2048
#define VV 50257
#define NLAYERS 6
#define QKVD 1536       // fused qkv width

// ---------------------------------------------------------------------------
// Scratch (allocation-free: __device__ globals)
// ---------------------------------------------------------------------------
__device__ float g_x[NN*DD];
__device__ __nv_bfloat16 g_h_hi[NN*DD],  g_h_lo[NN*DD];
__device__ float g_qkv[NN*QKVD];
__device__ __nv_bfloat16 g_ctx_hi[NN*DD], g_ctx_lo[NN*DD];
__device__ __nv_bfloat16 g_ff_hi[NN*FFD], g_ff_lo[NN*FFD];
// transposed bf16 weights [N,K]
__device__ __nv_bfloat16 g_wqkvT_hi[3*DD*DD], g_wqkvT_lo[3*DD*DD];
__device__ __nv_bfloat16 g_woT_hi[DD*DD],     g_woT_lo[DD*DD];
__device__ __nv_bfloat16 g_w1T_hi[FFD*DD],    g_w1T_lo[FFD*DD];
__device__ __nv_bfloat16 g_w2T_hi[DD*FFD],    g_w2T_lo[DD*FFD];
__device__ __nv_bfloat16 g_embB_hi[VV*DD],    g_embB_lo[VV*DD];

// ---------------------------------------------------------------------------
// Helpers
// ---------------------------------------------------------------------------
__device__ __forceinline__ uint32_t smem_u32(const void* p) {
    uint32_t a;
    asm("{ .reg .u64 t; cvta.to.shared.u64 t, %1; cvt.u32.u64 %0, t; }"
        : "=r"(a) : "l"(p));
    return a;
}

__device__ __forceinline__ void ldm4(uint32_t* r, uint32_t addr) {
    asm volatile("ldmatrix.sync.aligned.m8n8.x4.shared.b16 {%0,%1,%2,%3}, [%4];"
                 : "=r"(r[0]), "=r"(r[1]), "=r"(r[2]), "=r"(r[3]) : "r"(addr));
}

__device__ __forceinline__ void mma16816(float* c, const uint32_t* a,
                                         uint32_t b0, uint32_t b1) {
    asm volatile(
        "mma.sync.aligned.m16n8k16.row.col.f32.bf16.bf16.f32 "
        "{%0,%1,%2,%3}, {%4,%5,%6,%7}, {%8,%9}, {%0,%1,%2,%3};"
        : "+f"(c[0]), "+f"(c[1]), "+f"(c[2]), "+f"(c[3])
        : "r"(a[0]), "r"(a[1]), "r"(a[2]), "r"(a[3]), "r"(b0), "r"(b1));
}

__device__ __forceinline__ void cp_async16(uint32_t dst, const void* src, int szbytes) {
    asm volatile("cp.async.cg.shared.global [%0], [%1], 16, %2;"
                 :: "r"(dst), "l"(src), "r"(szbytes));
}
#define CP_COMMIT() asm volatile("cp.async.commit_group;" ::: "memory")
template<int N>
__device__ __forceinline__ void cp_wait() {
    asm volatile("cp.async.wait_group %0;" :: "n"(N) : "memory");
}

// hi/lo split helper (2 floats -> packed bf16x2 hi and lo)
__device__ __forceinline__ void split2(float x, float y, uint32_t& h, uint32_t& l) {
    __nv_bfloat16 h0 = __float2bfloat16_rn(x);
    __nv_bfloat16 h1 = __float2bfloat16_rn(y);
    __nv_bfloat16 l0 = __float2bfloat16_rn(x - __bfloat162float(h0));
    __nv_bfloat16 l1 = __float2bfloat16_rn(y - __bfloat162float(h1));
    h = (uint32_t)__bfloat16_as_ushort(h0) | ((uint32_t)__bfloat16_as_ushort(h1) << 16);
    l = (uint32_t)__bfloat16_as_ushort(l0) | ((uint32_t)__bfloat16_as_ushort(l1) << 16);
}
__device__ __forceinline__ void split4(float4 v, uint2& h, uint2& l) {
    split2(v.x, v.y, h.x, l.x);
    split2(v.z, v.w, h.y, l.y);
}

__device__ __forceinline__ float gelu_exact(float v) {
    return 0.5f * v * (1.0f + erff(v * 0.70710678118654752f));
}

// ---------------------------------------------------------------------------
// Weight conversion: W [K,N] fp32 -> hi/lo [N,K] bf16 (transpose)
// ---------------------------------------------------------------------------
__global__ void conv_wT(const float* __restrict__ W, __nv_bfloat16* __restrict__ hi,
                        __nv_bfloat16* __restrict__ lo, int K, int N) {
    __shared__ float t[32][33];
    int n0 = blockIdx.x * 32, k0 = blockIdx.y * 32;
    int tx = threadIdx.x, ty = threadIdx.y;
    #pragma unroll
    for (int r = 0; r < 4; r++)
        t[ty + r*8][tx] = W[(size_t)(k0 + ty + r*8) * N + n0 + tx];
    __syncthreads();
    #pragma unroll
    for (int r = 0; r < 4; r++) {
        float v = t[tx][ty + r*8];
        __nv_bfloat16 h = __float2bfloat16_rn(v);
        size_t o = (size_t)(n0 + ty + r*8) * K + k0 + tx;
        hi[o] = h;
        lo[o] = __float2bfloat16_rn(v - __bfloat162float(h));
    }
}

// Elementwise split (no transpose), float4 granularity
__global__ void conv_split4(const float* __restrict__ src,
                            __nv_bfloat16* __restrict__ hi,
                            __nv_bfloat16* __restrict__ lo, int n4) {
    int i = blockIdx.x * 256 + threadIdx.x;
    if (i >= n4) return;
    float4 v = reinterpret_cast<const float4*>(src)[i];
    uint2 h, l;
    split4(v, h, l);
    reinterpret_cast<uint2*>(hi)[i] = h;
    reinterpret_cast<uint2*>(lo)[i] = l;
}

// ---------------------------------------------------------------------------
// Embedding
// ---------------------------------------------------------------------------
__global__ void embed_kernel(const int* __restrict__ ids,
                             const float* __restrict__ emb,
                             const float* __restrict__ pe,
                             float* __restrict__ x) {
    int n = blockIdx.x;
    int tid = threadIdx.x;
    int id = ids[n];
    int s = n & (SS - 1);
    const float sq = 22.62741699796952f;
    float4 e = reinterpret_cast<const float4*>(emb + (size_t)id * DD)[tid];
    float4 p = reinterpret_cast<const float4*>(pe + (size_t)s * DD)[tid];
    float4 o;
    o.x = e.x * sq + p.x; o.y = e.y * sq + p.y;
    o.z = e.z * sq + p.z; o.w = e.w * sq + p.w;
    reinterpret_cast<float4*>(x + (size_t)n * DD)[tid] = o;
}

// ---------------------------------------------------------------------------
// LayerNorm -> bf16 hi/lo
// ---------------------------------------------------------------------------
__global__ void ln_kernel(const float* __restrict__ in,
                          __nv_bfloat16* __restrict__ out_hi,
                          __nv_bfloat16* __restrict__ out_lo,
                          const float* __restrict__ g, const float* __restrict__ b) {
    int row = blockIdx.x;
    int tid = threadIdx.x;    // 128
    float4 v = reinterpret_cast<const float4*>(in + (size_t)row * DD)[tid];
    float s = v.x + v.y + v.z + v.w;
    float ss = v.x*v.x + v.y*v.y + v.z*v.z + v.w*v.w;
    #pragma unroll
    for (int o = 16; o > 0; o >>= 1) {
        s  += __shfl_xor_sync(0xffffffffu, s, o);
        ss += __shfl_xor_sync(0xffffffffu, ss, o);
    }
    __shared__ float rs[4], rss[4];
    int warp = tid >> 5;
    if ((tid & 31) == 0) { rs[warp] = s; rss[warp] = ss; }
    __syncthreads();
    float mean = (rs[0]+rs[1]+rs[2]+rs[3]) * (1.0f/DD);
    float var  = (rss[0]+rss[1]+rss[2]+rss[3]) * (1.0f/DD) - mean*mean;
    float rstd = rsqrtf(var + 1e-5f);
    float4 gg = reinterpret_cast<const float4*>(g)[tid];
    float4 bb = reinterpret_cast<const float4*>(b)[tid];
    float4 o;
    o.x = (v.x - mean)*rstd*gg.x + bb.x;
    o.y = (v.y - mean)*rstd*gg.y + bb.y;
    o.z = (v.z - mean)*rstd*gg.z + bb.z;
    o.w = (v.w - mean)*rstd*gg.w + bb.w;
    uint2 h, l;
    split4(o, h, l);
    reinterpret_cast<uint2*>(out_hi + (size_t)row * DD)[tid] = h;
    reinterpret_cast<uint2*>(out_lo + (size_t)row * DD)[tid] = l;
}

// ---------------------------------------------------------------------------
// bf16-split GEMM via mma.sync (HMMA): C[M,Nout] = A[M,K] @ B^T (B is [Nout,K])
// CTA tile 128x128, K-chunk 64, 3-stage cp.async pipeline (one sync/chunk),
// 8 warps (4Mx2N), warp tile 32x64, mma.m16n8k16.
// 3 passes: Ah*Bh + Al*Bh + Ah*Bl accumulate into the same fp32 registers.
// EPI bits: 1=bias, 2=gelu, 4=resid.  SPLIT: write bf16 hi/lo instead of fp32.
// ---------------------------------------------------------------------------
#define SUBT 16384                      // bytes per sub-tile (128 rows x 128B)
#define STAGE (4*SUBT)                  // Ahi,Alo,Bhi,Blo = 64KB
#define NST 3                           // pipeline stages
#define GEMM_SMEM_BYTES (NST*STAGE)     // 196608

template<int EPI, bool SPLIT>
__global__ __launch_bounds__(256, 1)
void gemm_mma(const __nv_bfloat16* __restrict__ Ahi, const __nv_bfloat16* __restrict__ Alo,
              const __nv_bfloat16* __restrict__ Bhi, const __nv_bfloat16* __restrict__ Blo,
              const float* __restrict__ bias, const float* __restrict__ resid,
              float* __restrict__ C, __nv_bfloat16* __restrict__ Chi,
              __nv_bfloat16* __restrict__ Clo, int Nout, int K) {
    extern __shared__ char smem[];
    uint32_t sb = smem_u32(smem);
    const int tid = threadIdx.x;
    const int lane = tid & 31, wid = tid >> 5;
    const int m0 = blockIdx.y * 128, n0 = blockIdx.x * 128;
    const int warp_m = (wid >> 1) * 32;
    const int warp_n = (wid & 1) * 64;

    float acc[2][8][4];
    #pragma unroll
    for (int i = 0; i < 2; i++)
        #pragma unroll
        for (int j = 0; j < 8; j++)
            #pragma unroll
            for (int e = 0; e < 4; e++) acc[i][j][e] = 0.f;

    const int nch = K >> 6;

    // ---- stage loader (cp.async): 4 sub-tiles of 128x64 bf16, SW128 swizzle
    auto load_stage = [&](int buf, int k0) {
        uint32_t base = sb + buf * STAGE;
        const __nv_bfloat16* srcs[4] = {Ahi, Alo, Bhi, Blo};
        #pragma unroll
        for (int sub = 0; sub < 4; sub++) {
            const __nv_bfloat16* P = srcs[sub];
            int row0 = (sub < 2) ? m0 : n0;
            bool guard = (sub >= 2);
            uint32_t dbase = base + sub * SUBT;
            #pragma unroll
            for (int it = 0; it < 4; it++) {
                int u = tid + it * 256;           // 0..1023
                int row = u >> 3, c = u & 7;
                uint32_t dst = dbase + row * 128 + ((c ^ (row & 7)) * 16);
                const __nv_bfloat16* g = P + (size_t)(row0 + row) * K + k0 + c * 8;
                int sz = 16;
                if (guard && (row0 + row >= Nout)) { g = P; sz = 0; }
                cp_async16(dst, g, sz);
            }
        }
    };

    // per-thread fragment rows (precompute)
    int ra[2];
    ra[0] = warp_m + (lane & 15);
    ra[1] = ra[0] + 16;
    const int ca = lane >> 4;              // 0/1: k-halves for A ldmatrix
    int rB[4];
    #pragma unroll
    for (int nb = 0; nb < 4; nb++)
        rB[nb] = warp_n + nb * 16 + ((lane >> 4) & 1) * 8 + (lane & 7);
    const int kcB = (lane >> 3) & 1;

    auto compute = [&](int buf) {
        uint32_t base = sb + buf * STAGE;
        #pragma unroll
        for (int ks = 0; ks < 4; ks++) {
            // ---- load ALL fragments for this k-step first (no mid-loop LDSM)
            uint32_t ah[2][4], al[2][4], bh[4][4], bl[4][4];
            #pragma unroll
            for (int mb = 0; mb < 2; mb++) {
                uint32_t off = ra[mb] * 128 + (((ks*2 + ca) ^ (ra[mb] & 7)) * 16);
                ldm4(ah[mb], base + off);
                ldm4(al[mb], base + SUBT + off);
            }
            #pragma unroll
            for (int nb = 0; nb < 4; nb++) {
                uint32_t off = rB[nb] * 128 + (((ks*2 + kcB) ^ (rB[nb] & 7)) * 16);
                ldm4(bh[nb], base + 2*SUBT + off);
                ldm4(bl[nb], base + 3*SUBT + off);
            }
            // ---- 48 dense MMAs
            #pragma unroll
            for (int mb = 0; mb < 2; mb++)
                #pragma unroll
                for (int nb = 0; nb < 4; nb++) {
                    mma16816(acc[mb][nb*2],   ah[mb], bh[nb][0], bh[nb][1]);
                    mma16816(acc[mb][nb*2+1], ah[mb], bh[nb][2], bh[nb][3]);
                }
            #pragma unroll
            for (int mb = 0; mb < 2; mb++)
                #pragma unroll
                for (int nb = 0; nb < 4; nb++) {
                    mma16816(acc[mb][nb*2],   al[mb], bh[nb][0], bh[nb][1]);
                    mma16816(acc[mb][nb*2+1], al[mb], bh[nb][2], bh[nb][3]);
                }
            #pragma unroll
            for (int mb = 0; mb < 2; mb++)
                #pragma unroll
                for (int nb = 0; nb < 4; nb++) {
                    mma16816(acc[mb][nb*2],   ah[mb], bl[nb][0], bl[nb][1]);
                    mma16816(acc[mb][nb*2+1], ah[mb], bl[nb][2], bl[nb][3]);
                }
        }
    };

    // ---- 3-stage pipeline, one __syncthreads per chunk
    load_stage(0, 0);
    CP_COMMIT();
    if (nch > 1) { load_stage(1, 64); CP_COMMIT(); }
    for (int c = 0; c < nch; c++) {
        if (c == nch - 1) cp_wait<0>(); else cp_wait<1>();
        __syncthreads();
        compute(c % NST);
        int nx = c + 2;
        if (nx < nch) { load_stage(nx % NST, nx << 6); CP_COMMIT(); }
    }

    // ---- epilogue from accumulator fragments
    const int gid = lane >> 2, qid = lane & 3;
    #pragma unroll
    for (int mb = 0; mb < 2; mb++) {
        #pragma unroll
        for (int nf = 0; nf < 8; nf++) {
            int n = n0 + warp_n + nf * 8 + qid * 2;
            #pragma unroll
            for (int hh = 0; hh < 2; hh++) {
                int m = m0 + warp_m + mb * 16 + gid + hh * 8;
                float vx = acc[mb][nf][hh*2];
                float vy = acc[mb][nf][hh*2 + 1];
                if (EPI & 1) { vx += bias[n]; vy += bias[n + 1]; }
                if (EPI & 2) { vx = gelu_exact(vx); vy = gelu_exact(vy); }
                size_t o = (size_t)m * Nout + n;
                if (EPI & 4) {
                    float2 r = *reinterpret_cast<const float2*>(resid + o);
                    vx += r.x; vy += r.y;
                }
                if (SPLIT) {
                    uint32_t h, l;
                    split2(vx, vy, h, l);
                    *reinterpret_cast<uint32_t*>(Chi + o) = h;
                    *reinterpret_cast<uint32_t*>(Clo + o) = l;
                } else {
                    // scalar stores: o may be odd (Nout=50257 LM head) -> no
                    // 8-byte vector stores allowed here (misaligned address)
                    if (n < Nout)     C[o]     = vx;
                    if (n + 1 < Nout) C[o + 1] = vy;
                }
            }
        }
    }
}

// ---------------------------------------------------------------------------
// Causal flash attention (fp32), qkv fused layout [M, 1536], out -> bf16 hi/lo
// ---------------------------------------------------------------------------
__global__ __launch_bounds__(128)
void attn_kernel(const float* __restrict__ qkv,
                 __nv_bfloat16* __restrict__ ctx_hi,
                 __nv_bfloat16* __restrict__ ctx_lo) {
    __shared__ float4 ks[64][16];
    __shared__ float4 vs[64][16];
    int bh = blockIdx.y;
    int b = bh >> 3, h = bh & 7;
    int r = blockIdx.x * 128 + threadIdx.x;

    const float* qp = qkv + ((size_t)(b * SS + r) * QKVD + h * DH);
    float4 qf[16];
    #pragma unroll
    for (int c = 0; c < 16; c++) qf[c] = reinterpret_cast<const float4*>(qp)[c];

    float4 acc[16];
    #pragma unroll
    for (int c = 0; c < 16; c++) acc[c] = make_float4(0.f, 0.f, 0.f, 0.f);
    float m = -1e30f, l = 0.f;

    int ntiles = (blockIdx.x * 128) / 64 + 2;
    for (int t = 0; t < ntiles; t++) {
        int kbase = t * 64;
        #pragma unroll
        for (int i = 0; i < 8; i++) {
            int idx = threadIdx.x + i * 128;
            int j = idx >> 4, c = idx & 15;
            size_t off = (size_t)(b * SS + kbase + j) * QKVD + h * DH;
            ks[j][c] = reinterpret_cast<const float4*>(qkv + off + DD)[c];
            vs[j][c] = reinterpret_cast<const float4*>(qkv + off + 2*DD)[c];
        }
        __syncthreads();
        int jmax = r - kbase + 1;
        if (jmax > 64) jmax = 64;
        for (int j = 0; j < jmax; j++) {
            float s = 0.f;
            #pragma unroll
            for (int c = 0; c < 16; c++) {
                float4 kk = ks[j][c];
                s += qf[c].x*kk.x + qf[c].y*kk.y + qf[c].z*kk.z + qf[c].w*kk.w;
            }
            s *= 0.125f;
            if (s > m) {
                float sc = __expf(m - s);
                l *= sc;
                #pragma unroll
                for (int c = 0; c < 16; c++) {
                    acc[c].x *= sc; acc[c].y *= sc; acc[c].z *= sc; acc[c].w *= sc;
                }
                m = s;
            }
            float p = __expf(s - m);
            l += p;
            #pragma unroll
            for (int c = 0; c < 16; c++) {
                float4 vv = vs[j][c];
                acc[c].x += p*vv.x; acc[c].y += p*vv.y;
                acc[c].z += p*vv.z; acc[c].w += p*vv.w;
            }
        }
        __syncthreads();
    }

    float inv = 1.0f / l;
    size_t off = (size_t)(b * SS + r) * DD + h * DH;
    #pragma unroll
    for (int c = 0; c < 16; c++) {
        float4 o;
        o.x = acc[c].x*inv; o.y = acc[c].y*inv; o.z = acc[c].z*inv; o.w = acc[c].w*inv;
        uint2 hh, ll;
        split4(o, hh, ll);
        reinterpret_cast<uint2*>(ctx_hi + off)[c] = hh;
        reinterpret_cast<uint2*>(ctx_lo + off)[c] = ll;
    }
}

// ---------------------------------------------------------------------------
// Host launch
// ---------------------------------------------------------------------------
extern "C" void kernel_launch(void* const* d_in, const int* in_sizes, int n_in,
                              void* d_out, int out_size) {
    const int*   ids   = (const int*)  d_in[0];
    const float* emb   = (const float*)d_in[1];
    const float* pe    = (const float*)d_in[2];
    const float* wq    = (const float*)d_in[3];
    const float* wk    = (const float*)d_in[4];
    const float* wv    = (const float*)d_in[5];
    const float* wo    = (const float*)d_in[6];
    const float* wo_b  = (const float*)d_in[7];
    const float* w1    = (const float*)d_in[8];
    const float* b1    = (const float*)d_in[9];
    const float* w2    = (const float*)d_in[10];
    const float* b2    = (const float*)d_in[11];
    const float* ln1_g = (const float*)d_in[12];
    const float* ln1_b = (const float*)d_in[13];
    const float* ln2_g = (const float*)d_in[14];
    const float* ln2_b = (const float*)d_in[15];
    const float* lnf_g = (const float*)d_in[16];
    const float* lnf_b = (const float*)d_in[17];
    float* out = (float*)d_out;

    float *x, *qkv;
    __nv_bfloat16 *h_hi, *h_lo, *ctx_hi, *ctx_lo, *ff_hi, *ff_lo;
    __nv_bfloat16 *wqkvT_hi, *wqkvT_lo, *woT_hi, *woT_lo;
    __nv_bfloat16 *w1T_hi, *w1T_lo, *w2T_hi, *w2T_lo, *embB_hi, *embB_lo;
    cudaGetSymbolAddress((void**)&x, g_x);
    cudaGetSymbolAddress((void**)&qkv, g_qkv);
    cudaGetSymbolAddress((void**)&h_hi, g_h_hi);
    cudaGetSymbolAddress((void**)&h_lo, g_h_lo);
    cudaGetSymbolAddress((void**)&ctx_hi, g_ctx_hi);
    cudaGetSymbolAddress((void**)&ctx_lo, g_ctx_lo);
    cudaGetSymbolAddress((void**)&ff_hi, g_ff_hi);
    cudaGetSymbolAddress((void**)&ff_lo, g_ff_lo);
    cudaGetSymbolAddress((void**)&wqkvT_hi, g_wqkvT_hi);
    cudaGetSymbolAddress((void**)&wqkvT_lo, g_wqkvT_lo);
    cudaGetSymbolAddress((void**)&woT_hi, g_woT_hi);
    cudaGetSymbolAddress((void**)&woT_lo, g_woT_lo);
    cudaGetSymbolAddress((void**)&w1T_hi, g_w1T_hi);
    cudaGetSymbolAddress((void**)&w1T_lo, g_w1T_lo);
    cudaGetSymbolAddress((void**)&w2T_hi, g_w2T_hi);
    cudaGetSymbolAddress((void**)&w2T_lo, g_w2T_lo);
    cudaGetSymbolAddress((void**)&embB_hi, g_embB_hi);
    cudaGetSymbolAddress((void**)&embB_lo, g_embB_lo);

    cudaFuncSetAttribute(gemm_mma<0, false>, cudaFuncAttributeMaxDynamicSharedMemorySize, GEMM_SMEM_BYTES);
    cudaFuncSetAttribute(gemm_mma<5, false>, cudaFuncAttributeMaxDynamicSharedMemorySize, GEMM_SMEM_BYTES);
    cudaFuncSetAttribute(gemm_mma<3, true >, cudaFuncAttributeMaxDynamicSharedMemorySize, GEMM_SMEM_BYTES);

    // weight conversions (run each replay; cheap)
    dim3 cb(32, 8);
    conv_wT<<<dim3(DD/32, DD/32), cb>>>(wq, wqkvT_hi,            wqkvT_lo,            DD, DD);
    conv_wT<<<dim3(DD/32, DD/32), cb>>>(wk, wqkvT_hi + DD*DD,    wqkvT_lo + DD*DD,    DD, DD);
    conv_wT<<<dim3(DD/32, DD/32), cb>>>(wv, wqkvT_hi + 2*DD*DD,  wqkvT_lo + 2*DD*DD,  DD, DD);
    conv_wT<<<dim3(DD/32, DD/32), cb>>>(wo, woT_hi, woT_lo, DD, DD);
    conv_wT<<<dim3(FFD/32, DD/32), cb>>>(w1, w1T_hi, w1T_lo, DD, FFD);
    conv_wT<<<dim3(DD/32, FFD/32), cb>>>(w2, w2T_hi, w2T_lo, FFD, DD);
    {
        int n4 = VV * DD / 4;
        conv_split4<<<(n4 + 255) / 256, 256>>>(emb, embB_hi, embB_lo, n4);
    }

    embed_kernel<<<NN, 128>>>(ids, emb, pe, x);

    dim3 gQKV(QKVD/128, NN/128);     // (12, 32)
    dim3 gProj(DD/128, NN/128);      // (4, 32)
    dim3 gFF1(FFD/128, NN/128);      // (16, 32)
    dim3 gAttn(SS/128, BB*HH);       // (8, 32)

    for (int layer = 0; layer < NLAYERS; layer++) {
        ln_kernel<<<NN, 128>>>(x, h_hi, h_lo, ln1_g, ln1_b);
        gemm_mma<0, false><<<gQKV, 256, GEMM_SMEM_BYTES>>>(
            h_hi, h_lo, wqkvT_hi, wqkvT_lo, nullptr, nullptr,
            qkv, nullptr, nullptr, QKVD, DD);
        attn_kernel<<<gAttn, 128>>>(qkv, ctx_hi, ctx_lo);
        gemm_mma<5, false><<<gProj, 256, GEMM_SMEM_BYTES>>>(
            ctx_hi, ctx_lo, woT_hi, woT_lo, wo_b, x,
            x, nullptr, nullptr, DD, DD);
        ln_kernel<<<NN, 128>>>(x, h_hi, h_lo, ln2_g, ln2_b);
        gemm_mma<3, true><<<gFF1, 256, GEMM_SMEM_BYTES>>>(
            h_hi, h_lo, w1T_hi, w1T_lo, b1, nullptr,
            nullptr, ff_hi, ff_lo, FFD, DD);
        gemm_mma<5, false><<<gProj, 256, GEMM_SMEM_BYTES>>>(
            ff_hi, ff_lo, w2T_hi, w2T_lo, b2, x,
            x, nullptr, nullptr, DD, FFD);
    }

    ln_kernel<<<NN, 128>>>(x, h_hi, h_lo, lnf_g, lnf_b);

    dim3 gLM((VV + 127) / 128, NN / 128);   // (393, 32)
    gemm_mma<0, false><<<gLM, 256, GEMM_SMEM_BYTES>>>(
        h_hi, h_lo, embB_hi, embB_lo, nullptr, nullptr,
        out, nullptr, nullptr, VV, DD);
}

// round 6
// speedup vs baseline: 2.1347x; 1.1063x over previous
#include <cuda_runtime.h>
#include <cuda_bf16.h>
#include <cuda_fp16.h>
#include <math.h>
#include <stdint.h>

// Problem constants
#define BB 4
#define SS 1024
#define NN (BB*SS)      // 4096 tokens
#define DD 512
#define HH 8
#define DH 64
#define FFD 2048
#define VV 50257
#define NLAYERS 6
#define QKVD 1536       // fused qkv width

// ---------------------------------------------------------------------------
// Scratch (allocation-free: __device__ globals)
// ---------------------------------------------------------------------------
__device__ float g_x[NN*DD];
__device__ __nv_bfloat16 g_h_hi[NN*DD],  g_h_lo[NN*DD];
__device__ float g_qkv[NN*QKVD];
__device__ __nv_bfloat16 g_ctx_hi[NN*DD], g_ctx_lo[NN*DD];
__device__ __nv_bfloat16 g_ff_hi[NN*FFD], g_ff_lo[NN*FFD];
// transposed bf16 weights [N,K]
__device__ __nv_bfloat16 g_wqkvT_hi[3*DD*DD], g_wqkvT_lo[3*DD*DD];
__device__ __nv_bfloat16 g_woT_hi[DD*DD],     g_woT_lo[DD*DD];
__device__ __nv_bfloat16 g_w1T_hi[FFD*DD],    g_w1T_lo[FFD*DD];
__device__ __nv_bfloat16 g_w2T_hi[DD*FFD],    g_w2T_lo[DD*FFD];
// LM head (fp16 2-pass): A split hi/lo, B single fp16
__device__ __half g_hf_hi[NN*DD], g_hf_lo[NN*DD];
__device__ __half g_embH[VV*DD];

// ---------------------------------------------------------------------------
// Helpers
// ---------------------------------------------------------------------------
__device__ __forceinline__ uint32_t smem_u32(const void* p) {
    uint32_t a;
    asm("{ .reg .u64 t; cvta.to.shared.u64 t, %1; cvt.u32.u64 %0, t; }"
        : "=r"(a) : "l"(p));
    return a;
}

__device__ __forceinline__ void ldm4(uint32_t* r, uint32_t addr) {
    asm volatile("ldmatrix.sync.aligned.m8n8.x4.shared.b16 {%0,%1,%2,%3}, [%4];"
                 : "=r"(r[0]), "=r"(r[1]), "=r"(r[2]), "=r"(r[3]) : "r"(addr));
}

__device__ __forceinline__ void mma16816(float* c, const uint32_t* a,
                                         uint32_t b0, uint32_t b1) {
    asm volatile(
        "mma.sync.aligned.m16n8k16.row.col.f32.bf16.bf16.f32 "
        "{%0,%1,%2,%3}, {%4,%5,%6,%7}, {%8,%9}, {%0,%1,%2,%3};"
        : "+f"(c[0]), "+f"(c[1]), "+f"(c[2]), "+f"(c[3])
        : "r"(a[0]), "r"(a[1]), "r"(a[2]), "r"(a[3]), "r"(b0), "r"(b1));
}
__device__ __forceinline__ void mma16816h(float* c, const uint32_t* a,
                                          uint32_t b0, uint32_t b1) {
    asm volatile(
        "mma.sync.aligned.m16n8k16.row.col.f32.f16.f16.f32 "
        "{%0,%1,%2,%3}, {%4,%5,%6,%7}, {%8,%9}, {%0,%1,%2,%3};"
        : "+f"(c[0]), "+f"(c[1]), "+f"(c[2]), "+f"(c[3])
        : "r"(a[0]), "r"(a[1]), "r"(a[2]), "r"(a[3]), "r"(b0), "r"(b1));
}

__device__ __forceinline__ void cp_async16(uint32_t dst, const void* src, int szbytes) {
    asm volatile("cp.async.cg.shared.global [%0], [%1], 16, %2;"
                 :: "r"(dst), "l"(src), "r"(szbytes));
}
#define CP_COMMIT() asm volatile("cp.async.commit_group;" ::: "memory")
template<int N>
__device__ __forceinline__ void cp_wait() {
    asm volatile("cp.async.wait_group %0;" :: "n"(N) : "memory");
}

// bf16 hi/lo split helpers
__device__ __forceinline__ void split2(float x, float y, uint32_t& h, uint32_t& l) {
    __nv_bfloat16 h0 = __float2bfloat16_rn(x);
    __nv_bfloat16 h1 = __float2bfloat16_rn(y);
    __nv_bfloat16 l0 = __float2bfloat16_rn(x - __bfloat162float(h0));
    __nv_bfloat16 l1 = __float2bfloat16_rn(y - __bfloat162float(h1));
    h = (uint32_t)__bfloat16_as_ushort(h0) | ((uint32_t)__bfloat16_as_ushort(h1) << 16);
    l = (uint32_t)__bfloat16_as_ushort(l0) | ((uint32_t)__bfloat16_as_ushort(l1) << 16);
}
__device__ __forceinline__ void split4(float4 v, uint2& h, uint2& l) {
    split2(v.x, v.y, h.x, l.x);
    split2(v.z, v.w, h.y, l.y);
}
// fp16 hi/lo split
__device__ __forceinline__ void split2h(float x, float y, uint32_t& h, uint32_t& l) {
    __half h0 = __float2half_rn(x);
    __half h1 = __float2half_rn(y);
    __half l0 = __float2half_rn(x - __half2float(h0));
    __half l1 = __float2half_rn(y - __half2float(h1));
    h = (uint32_t)__half_as_ushort(h0) | ((uint32_t)__half_as_ushort(h1) << 16);
    l = (uint32_t)__half_as_ushort(l0) | ((uint32_t)__half_as_ushort(l1) << 16);
}

__device__ __forceinline__ float gelu_exact(float v) {
    return 0.5f * v * (1.0f + erff(v * 0.70710678118654752f));
}

// ---------------------------------------------------------------------------
// Weight conversion: W [K,N] fp32 -> hi/lo [N,K] bf16 (transpose)
// ---------------------------------------------------------------------------
__global__ void conv_wT(const float* __restrict__ W, __nv_bfloat16* __restrict__ hi,
                        __nv_bfloat16* __restrict__ lo, int K, int N) {
    __shared__ float t[32][33];
    int n0 = blockIdx.x * 32, k0 = blockIdx.y * 32;
    int tx = threadIdx.x, ty = threadIdx.y;
    #pragma unroll
    for (int r = 0; r < 4; r++)
        t[ty + r*8][tx] = W[(size_t)(k0 + ty + r*8) * N + n0 + tx];
    __syncthreads();
    #pragma unroll
    for (int r = 0; r < 4; r++) {
        float v = t[tx][ty + r*8];
        __nv_bfloat16 h = __float2bfloat16_rn(v);
        size_t o = (size_t)(n0 + ty + r*8) * K + k0 + tx;
        hi[o] = h;
        lo[o] = __float2bfloat16_rn(v - __bfloat162float(h));
    }
}

// Elementwise fp32 -> fp16 (no transpose), float4 granularity
__global__ void conv_half4(const float* __restrict__ src,
                           __half* __restrict__ dst, int n4) {
    int i = blockIdx.x * 256 + threadIdx.x;
    if (i >= n4) return;
    float4 v = reinterpret_cast<const float4*>(src)[i];
    __half2 a = __floats2half2_rn(v.x, v.y);
    __half2 b = __floats2half2_rn(v.z, v.w);
    uint2 o;
    o.x = *reinterpret_cast<uint32_t*>(&a);
    o.y = *reinterpret_cast<uint32_t*>(&b);
    reinterpret_cast<uint2*>(dst)[i] = o;
}

// ---------------------------------------------------------------------------
// Embedding
// ---------------------------------------------------------------------------
__global__ void embed_kernel(const int* __restrict__ ids,
                             const float* __restrict__ emb,
                             const float* __restrict__ pe,
                             float* __restrict__ x) {
    int n = blockIdx.x;
    int tid = threadIdx.x;
    int id = ids[n];
    int s = n & (SS - 1);
    const float sq = 22.62741699796952f;
    float4 e = reinterpret_cast<const float4*>(emb + (size_t)id * DD)[tid];
    float4 p = reinterpret_cast<const float4*>(pe + (size_t)s * DD)[tid];
    float4 o;
    o.x = e.x * sq + p.x; o.y = e.y * sq + p.y;
    o.z = e.z * sq + p.z; o.w = e.w * sq + p.w;
    reinterpret_cast<float4*>(x + (size_t)n * DD)[tid] = o;
}

// ---------------------------------------------------------------------------
// LayerNorm -> bf16 hi/lo  (F16=false)  or fp16 hi/lo (F16=true)
// ---------------------------------------------------------------------------
template<bool F16>
__global__ void ln_kernel(const float* __restrict__ in,
                          uint32_t* __restrict__ out_hi,   // packed 2-elem words
                          uint32_t* __restrict__ out_lo,
                          const float* __restrict__ g, const float* __restrict__ b) {
    int row = blockIdx.x;
    int tid = threadIdx.x;    // 128
    float4 v = reinterpret_cast<const float4*>(in + (size_t)row * DD)[tid];
    float s = v.x + v.y + v.z + v.w;
    float ss = v.x*v.x + v.y*v.y + v.z*v.z + v.w*v.w;
    #pragma unroll
    for (int o = 16; o > 0; o >>= 1) {
        s  += __shfl_xor_sync(0xffffffffu, s, o);
        ss += __shfl_xor_sync(0xffffffffu, ss, o);
    }
    __shared__ float rs[4], rss[4];
    int warp = tid >> 5;
    if ((tid & 31) == 0) { rs[warp] = s; rss[warp] = ss; }
    __syncthreads();
    float mean = (rs[0]+rs[1]+rs[2]+rs[3]) * (1.0f/DD);
    float var  = (rss[0]+rss[1]+rss[2]+rss[3]) * (1.0f/DD) - mean*mean;
    float rstd = rsqrtf(var + 1e-5f);
    float4 gg = reinterpret_cast<const float4*>(g)[tid];
    float4 bb = reinterpret_cast<const float4*>(b)[tid];
    float4 o;
    o.x = (v.x - mean)*rstd*gg.x + bb.x;
    o.y = (v.y - mean)*rstd*gg.y + bb.y;
    o.z = (v.z - mean)*rstd*gg.z + bb.z;
    o.w = (v.w - mean)*rstd*gg.w + bb.w;
    uint2 h, l;
    if (F16) { split2h(o.x, o.y, h.x, l.x); split2h(o.z, o.w, h.y, l.y); }
    else     { split4(o, h, l); }
    reinterpret_cast<uint2*>(out_hi)[(size_t)row * (DD/4) + tid] = h;
    reinterpret_cast<uint2*>(out_lo)[(size_t)row * (DD/4) + tid] = l;
}

// ---------------------------------------------------------------------------
// bf16-split GEMM via mma.sync (HMMA): C[M,Nout] = A[M,K] @ B^T (B is [Nout,K])
// CTA tile 128x128, K-chunk 64, 3-stage cp.async pipeline, 8 warps (4Mx2N).
// 3 passes: Ah*Bh + Al*Bh + Ah*Bl.
// ---------------------------------------------------------------------------
#define SUBT 16384                      // bytes per sub-tile (128 rows x 128B)
#define STAGE (4*SUBT)                  // Ahi,Alo,Bhi,Blo = 64KB
#define NST 3                           // pipeline stages
#define GEMM_SMEM_BYTES (NST*STAGE)     // 196608

template<int EPI, bool SPLIT>
__global__ __launch_bounds__(256, 1)
void gemm_mma(const __nv_bfloat16* __restrict__ Ahi, const __nv_bfloat16* __restrict__ Alo,
              const __nv_bfloat16* __restrict__ Bhi, const __nv_bfloat16* __restrict__ Blo,
              const float* __restrict__ bias, const float* __restrict__ resid,
              float* __restrict__ C, __nv_bfloat16* __restrict__ Chi,
              __nv_bfloat16* __restrict__ Clo, int Nout, int K) {
    extern __shared__ char smem[];
    uint32_t sb = smem_u32(smem);
    const int tid = threadIdx.x;
    const int lane = tid & 31, wid = tid >> 5;
    const int m0 = blockIdx.y * 128, n0 = blockIdx.x * 128;
    const int warp_m = (wid >> 1) * 32;
    const int warp_n = (wid & 1) * 64;

    float acc[2][8][4];
    #pragma unroll
    for (int i = 0; i < 2; i++)
        #pragma unroll
        for (int j = 0; j < 8; j++)
            #pragma unroll
            for (int e = 0; e < 4; e++) acc[i][j][e] = 0.f;

    const int nch = K >> 6;

    auto load_stage = [&](int buf, int k0) {
        uint32_t base = sb + buf * STAGE;
        const __nv_bfloat16* srcs[4] = {Ahi, Alo, Bhi, Blo};
        #pragma unroll
        for (int sub = 0; sub < 4; sub++) {
            const __nv_bfloat16* P = srcs[sub];
            int row0 = (sub < 2) ? m0 : n0;
            uint32_t dbase = base + sub * SUBT;
            #pragma unroll
            for (int it = 0; it < 4; it++) {
                int u = tid + it * 256;
                int row = u >> 3, c = u & 7;
                uint32_t dst = dbase + row * 128 + ((c ^ (row & 7)) * 16);
                const __nv_bfloat16* g = P + (size_t)(row0 + row) * K + k0 + c * 8;
                cp_async16(dst, g, 16);
            }
        }
    };

    int ra[2];
    ra[0] = warp_m + (lane & 15);
    ra[1] = ra[0] + 16;
    const int ca = lane >> 4;
    int rB[4];
    #pragma unroll
    for (int nb = 0; nb < 4; nb++)
        rB[nb] = warp_n + nb * 16 + ((lane >> 4) & 1) * 8 + (lane & 7);
    const int kcB = (lane >> 3) & 1;

    auto compute = [&](int buf) {
        uint32_t base = sb + buf * STAGE;
        #pragma unroll
        for (int ks = 0; ks < 4; ks++) {
            uint32_t ah[2][4], al[2][4], bh[4][4], bl[4][4];
            #pragma unroll
            for (int mb = 0; mb < 2; mb++) {
                uint32_t off = ra[mb] * 128 + (((ks*2 + ca) ^ (ra[mb] & 7)) * 16);
                ldm4(ah[mb], base + off);
                ldm4(al[mb], base + SUBT + off);
            }
            #pragma unroll
            for (int nb = 0; nb < 4; nb++) {
                uint32_t off = rB[nb] * 128 + (((ks*2 + kcB) ^ (rB[nb] & 7)) * 16);
                ldm4(bh[nb], base + 2*SUBT + off);
                ldm4(bl[nb], base + 3*SUBT + off);
            }
            #pragma unroll
            for (int mb = 0; mb < 2; mb++)
                #pragma unroll
                for (int nb = 0; nb < 4; nb++) {
                    mma16816(acc[mb][nb*2],   ah[mb], bh[nb][0], bh[nb][1]);
                    mma16816(acc[mb][nb*2+1], ah[mb], bh[nb][2], bh[nb][3]);
                }
            #pragma unroll
            for (int mb = 0; mb < 2; mb++)
                #pragma unroll
                for (int nb = 0; nb < 4; nb++) {
                    mma16816(acc[mb][nb*2],   al[mb], bh[nb][0], bh[nb][1]);
                    mma16816(acc[mb][nb*2+1], al[mb], bh[nb][2], bh[nb][3]);
                }
            #pragma unroll
            for (int mb = 0; mb < 2; mb++)
                #pragma unroll
                for (int nb = 0; nb < 4; nb++) {
                    mma16816(acc[mb][nb*2],   ah[mb], bl[nb][0], bl[nb][1]);
                    mma16816(acc[mb][nb*2+1], ah[mb], bl[nb][2], bl[nb][3]);
                }
        }
    };

    load_stage(0, 0);
    CP_COMMIT();
    if (nch > 1) { load_stage(1, 64); CP_COMMIT(); }
    for (int c = 0; c < nch; c++) {
        if (c == nch - 1) cp_wait<0>(); else cp_wait<1>();
        __syncthreads();
        compute(c % NST);
        int nx = c + 2;
        if (nx < nch) { load_stage(nx % NST, nx << 6); CP_COMMIT(); }
    }

    const int gid = lane >> 2, qid = lane & 3;
    #pragma unroll
    for (int mb = 0; mb < 2; mb++) {
        #pragma unroll
        for (int nf = 0; nf < 8; nf++) {
            int n = n0 + warp_n + nf * 8 + qid * 2;
            #pragma unroll
            for (int hh = 0; hh < 2; hh++) {
                int m = m0 + warp_m + mb * 16 + gid + hh * 8;
                float vx = acc[mb][nf][hh*2];
                float vy = acc[mb][nf][hh*2 + 1];
                if (EPI & 1) { vx += bias[n]; vy += bias[n + 1]; }
                if (EPI & 2) { vx = gelu_exact(vx); vy = gelu_exact(vy); }
                size_t o = (size_t)m * Nout + n;
                if (EPI & 4) {
                    float2 r = *reinterpret_cast<const float2*>(resid + o);
                    vx += r.x; vy += r.y;
                }
                if (SPLIT) {
                    uint32_t h, l;
                    split2(vx, vy, h, l);
                    *reinterpret_cast<uint32_t*>(Chi + o) = h;
                    *reinterpret_cast<uint32_t*>(Clo + o) = l;
                } else {
                    *reinterpret_cast<float2*>(C + o) = make_float2(vx, vy);
                }
            }
        }
    }
}

// ---------------------------------------------------------------------------
// LM-head GEMM (fp16, 2-pass): C[M,V] = (Ah+Al)[M,K] @ Bh^T, B=[V,K] fp16
// 3 sub-tiles per stage (Ahi, Alo, Bh), 32 MMAs per k-step.
// ---------------------------------------------------------------------------
#define STAGE_LM (3*SUBT)               // 48KB
#define LM_SMEM_BYTES (NST*STAGE_LM)    // 147456

__global__ __launch_bounds__(256, 1)
void gemm_lm(const __half* __restrict__ Ahi, const __half* __restrict__ Alo,
             const __half* __restrict__ Bh,
             float* __restrict__ C, int Nout, int K) {
    extern __shared__ char smem[];
    uint32_t sb = smem_u32(smem);
    const int tid = threadIdx.x;
    const int lane = tid & 31, wid = tid >> 5;
    const int m0 = blockIdx.y * 128, n0 = blockIdx.x * 128;
    const int warp_m = (wid >> 1) * 32;
    const int warp_n = (wid & 1) * 64;

    float acc[2][8][4];
    #pragma unroll
    for (int i = 0; i < 2; i++)
        #pragma unroll
        for (int j = 0; j < 8; j++)
            #pragma unroll
            for (int e = 0; e < 4; e++) acc[i][j][e] = 0.f;

    const int nch = K >> 6;   // 8

    auto load_stage = [&](int buf, int k0) {
        uint32_t base = sb + buf * STAGE_LM;
        const __half* srcs[3] = {Ahi, Alo, Bh};
        #pragma unroll
        for (int sub = 0; sub < 3; sub++) {
            const __half* P = srcs[sub];
            int row0 = (sub < 2) ? m0 : n0;
            bool guard = (sub == 2);
            uint32_t dbase = base + sub * SUBT;
            #pragma unroll
            for (int it = 0; it < 4; it++) {
                int u = tid + it * 256;
                int row = u >> 3, c = u & 7;
                uint32_t dst = dbase + row * 128 + ((c ^ (row & 7)) * 16);
                const __half* g = P + (size_t)(row0 + row) * K + k0 + c * 8;
                int sz = 16;
                if (guard && (row0 + row >= Nout)) { g = P; sz = 0; }
                cp_async16(dst, g, sz);
            }
        }
    };

    int ra[2];
    ra[0] = warp_m + (lane & 15);
    ra[1] = ra[0] + 16;
    const int ca = lane >> 4;
    int rB[4];
    #pragma unroll
    for (int nb = 0; nb < 4; nb++)
        rB[nb] = warp_n + nb * 16 + ((lane >> 4) & 1) * 8 + (lane & 7);
    const int kcB = (lane >> 3) & 1;

    auto compute = [&](int buf) {
        uint32_t base = sb + buf * STAGE_LM;
        #pragma unroll
        for (int ks = 0; ks < 4; ks++) {
            uint32_t ah[2][4], al[2][4], bh[4][4];
            #pragma unroll
            for (int mb = 0; mb < 2; mb++) {
                uint32_t off = ra[mb] * 128 + (((ks*2 + ca) ^ (ra[mb] & 7)) * 16);
                ldm4(ah[mb], base + off);
                ldm4(al[mb], base + SUBT + off);
            }
            #pragma unroll
            for (int nb = 0; nb < 4; nb++) {
                uint32_t off = rB[nb] * 128 + (((ks*2 + kcB) ^ (rB[nb] & 7)) * 16);
                ldm4(bh[nb], base + 2*SUBT + off);
            }
            #pragma unroll
            for (int mb = 0; mb < 2; mb++)
                #pragma unroll
                for (int nb = 0; nb < 4; nb++) {
                    mma16816h(acc[mb][nb*2],   ah[mb], bh[nb][0], bh[nb][1]);
                    mma16816h(acc[mb][nb*2+1], ah[mb], bh[nb][2], bh[nb][3]);
                }
            #pragma unroll
            for (int mb = 0; mb < 2; mb++)
                #pragma unroll
                for (int nb = 0; nb < 4; nb++) {
                    mma16816h(acc[mb][nb*2],   al[mb], bh[nb][0], bh[nb][1]);
                    mma16816h(acc[mb][nb*2+1], al[mb], bh[nb][2], bh[nb][3]);
                }
        }
    };

    load_stage(0, 0);
    CP_COMMIT();
    load_stage(1, 64);
    CP_COMMIT();
    for (int c = 0; c < nch; c++) {
        if (c == nch - 1) cp_wait<0>(); else cp_wait<1>();
        __syncthreads();
        compute(c % NST);
        int nx = c + 2;
        if (nx < nch) { load_stage(nx % NST, nx << 6); CP_COMMIT(); }
    }

    const int gid = lane >> 2, qid = lane & 3;
    #pragma unroll
    for (int mb = 0; mb < 2; mb++) {
        #pragma unroll
        for (int nf = 0; nf < 8; nf++) {
            int n = n0 + warp_n + nf * 8 + qid * 2;
            #pragma unroll
            for (int hh = 0; hh < 2; hh++) {
                int m = m0 + warp_m + mb * 16 + gid + hh * 8;
                float vx = acc[mb][nf][hh*2];
                float vy = acc[mb][nf][hh*2 + 1];
                size_t o = (size_t)m * Nout + n;
                // scalar stores: o may be odd (Nout=50257) -> no vector stores
                if (n < Nout)     C[o]     = vx;
                if (n + 1 < Nout) C[o + 1] = vy;
            }
        }
    }
}

// ---------------------------------------------------------------------------
// Causal flash attention (fp32), qkv fused layout [M, 1536], out -> bf16 hi/lo
// ---------------------------------------------------------------------------
__global__ __launch_bounds__(128)
void attn_kernel(const float* __restrict__ qkv,
                 __nv_bfloat16* __restrict__ ctx_hi,
                 __nv_bfloat16* __restrict__ ctx_lo) {
    __shared__ float4 ks[64][16];
    __shared__ float4 vs[64][16];
    int bh = blockIdx.y;
    int b = bh >> 3, h = bh & 7;
    int r = blockIdx.x * 128 + threadIdx.x;

    const float* qp = qkv + ((size_t)(b * SS + r) * QKVD + h * DH);
    float4 qf[16];
    #pragma unroll
    for (int c = 0; c < 16; c++) qf[c] = reinterpret_cast<const float4*>(qp)[c];

    float4 acc[16];
    #pragma unroll
    for (int c = 0; c < 16; c++) acc[c] = make_float4(0.f, 0.f, 0.f, 0.f);
    float m = -1e30f, l = 0.f;

    int ntiles = (blockIdx.x * 128) / 64 + 2;
    for (int t = 0; t < ntiles; t++) {
        int kbase = t * 64;
        #pragma unroll
        for (int i = 0; i < 8; i++) {
            int idx = threadIdx.x + i * 128;
            int j = idx >> 4, c = idx & 15;
            size_t off = (size_t)(b * SS + kbase + j) * QKVD + h * DH;
            ks[j][c] = reinterpret_cast<const float4*>(qkv + off + DD)[c];
            vs[j][c] = reinterpret_cast<const float4*>(qkv + off + 2*DD)[c];
        }
        __syncthreads();
        int jmax = r - kbase + 1;
        if (jmax > 64) jmax = 64;
        for (int j = 0; j < jmax; j++) {
            float s = 0.f;
            #pragma unroll
            for (int c = 0; c < 16; c++) {
                float4 kk = ks[j][c];
                s += qf[c].x*kk.x + qf[c].y*kk.y + qf[c].z*kk.z + qf[c].w*kk.w;
            }
            s *= 0.125f;
            if (s > m) {
                float sc = __expf(m - s);
                l *= sc;
                #pragma unroll
                for (int c = 0; c < 16; c++) {
                    acc[c].x *= sc; acc[c].y *= sc; acc[c].z *= sc; acc[c].w *= sc;
                }
                m = s;
            }
            float p = __expf(s - m);
            l += p;
            #pragma unroll
            for (int c = 0; c < 16; c++) {
                float4 vv = vs[j][c];
                acc[c].x += p*vv.x; acc[c].y += p*vv.y;
                acc[c].z += p*vv.z; acc[c].w += p*vv.w;
            }
        }
        __syncthreads();
    }

    float inv = 1.0f / l;
    size_t off = (size_t)(b * SS + r) * DD + h * DH;
    #pragma unroll
    for (int c = 0; c < 16; c++) {
        float4 o;
        o.x = acc[c].x*inv; o.y = acc[c].y*inv; o.z = acc[c].z*inv; o.w = acc[c].w*inv;
        uint2 hh, ll;
        split4(o, hh, ll);
        reinterpret_cast<uint2*>(ctx_hi + off)[c] = hh;
        reinterpret_cast<uint2*>(ctx_lo + off)[c] = ll;
    }
}

// ---------------------------------------------------------------------------
// Host launch
// ---------------------------------------------------------------------------
extern "C" void kernel_launch(void* const* d_in, const int* in_sizes, int n_in,
                              void* d_out, int out_size) {
    const int*   ids   = (const int*)  d_in[0];
    const float* emb   = (const float*)d_in[1];
    const float* pe    = (const float*)d_in[2];
    const float* wq    = (const float*)d_in[3];
    const float* wk    = (const float*)d_in[4];
    const float* wv    = (const float*)d_in[5];
    const float* wo    = (const float*)d_in[6];
    const float* wo_b  = (const float*)d_in[7];
    const float* w1    = (const float*)d_in[8];
    const float* b1    = (const float*)d_in[9];
    const float* w2    = (const float*)d_in[10];
    const float* b2    = (const float*)d_in[11];
    const float* ln1_g = (const float*)d_in[12];
    const float* ln1_b = (const float*)d_in[13];
    const float* ln2_g = (const float*)d_in[14];
    const float* ln2_b = (const float*)d_in[15];
    const float* lnf_g = (const float*)d_in[16];
    const float* lnf_b = (const float*)d_in[17];
    float* out = (float*)d_out;

    float *x, *qkv;
    __nv_bfloat16 *h_hi, *h_lo, *ctx_hi, *ctx_lo, *ff_hi, *ff_lo;
    __nv_bfloat16 *wqkvT_hi, *wqkvT_lo, *woT_hi, *woT_lo;
    __nv_bfloat16 *w1T_hi, *w1T_lo, *w2T_hi, *w2T_lo;
    __half *hf_hi, *hf_lo, *embH;
    cudaGetSymbolAddress((void**)&x, g_x);
    cudaGetSymbolAddress((void**)&qkv, g_qkv);
    cudaGetSymbolAddress((void**)&h_hi, g_h_hi);
    cudaGetSymbolAddress((void**)&h_lo, g_h_lo);
    cudaGetSymbolAddress((void**)&ctx_hi, g_ctx_hi);
    cudaGetSymbolAddress((void**)&ctx_lo, g_ctx_lo);
    cudaGetSymbolAddress((void**)&ff_hi, g_ff_hi);
    cudaGetSymbolAddress((void**)&ff_lo, g_ff_lo);
    cudaGetSymbolAddress((void**)&wqkvT_hi, g_wqkvT_hi);
    cudaGetSymbolAddress((void**)&wqkvT_lo, g_wqkvT_lo);
    cudaGetSymbolAddress((void**)&woT_hi, g_woT_hi);
    cudaGetSymbolAddress((void**)&woT_lo, g_woT_lo);
    cudaGetSymbolAddress((void**)&w1T_hi, g_w1T_hi);
    cudaGetSymbolAddress((void**)&w1T_lo, g_w1T_lo);
    cudaGetSymbolAddress((void**)&w2T_hi, g_w2T_hi);
    cudaGetSymbolAddress((void**)&w2T_lo, g_w2T_lo);
    cudaGetSymbolAddress((void**)&hf_hi, g_hf_hi);
    cudaGetSymbolAddress((void**)&hf_lo, g_hf_lo);
    cudaGetSymbolAddress((void**)&embH, g_embH);

    cudaFuncSetAttribute(gemm_mma<0, false>, cudaFuncAttributeMaxDynamicSharedMemorySize, GEMM_SMEM_BYTES);
    cudaFuncSetAttribute(gemm_mma<5, false>, cudaFuncAttributeMaxDynamicSharedMemorySize, GEMM_SMEM_BYTES);
    cudaFuncSetAttribute(gemm_mma<3, true >, cudaFuncAttributeMaxDynamicSharedMemorySize, GEMM_SMEM_BYTES);
    cudaFuncSetAttribute(gemm_lm, cudaFuncAttributeMaxDynamicSharedMemorySize, LM_SMEM_BYTES);

    // weight conversions (run each replay; cheap)
    dim3 cb(32, 8);
    conv_wT<<<dim3(DD/32, DD/32), cb>>>(wq, wqkvT_hi,            wqkvT_lo,            DD, DD);
    conv_wT<<<dim3(DD/32, DD/32), cb>>>(wk, wqkvT_hi + DD*DD,    wqkvT_lo + DD*DD,    DD, DD);
    conv_wT<<<dim3(DD/32, DD/32), cb>>>(wv, wqkvT_hi + 2*DD*DD,  wqkvT_lo + 2*DD*DD,  DD, DD);
    conv_wT<<<dim3(DD/32, DD/32), cb>>>(wo, woT_hi, woT_lo, DD, DD);
    conv_wT<<<dim3(FFD/32, DD/32), cb>>>(w1, w1T_hi, w1T_lo, DD, FFD);
    conv_wT<<<dim3(DD/32, FFD/32), cb>>>(w2, w2T_hi, w2T_lo, FFD, DD);
    {
        int n4 = VV * DD / 4;
        conv_half4<<<(n4 + 255) / 256, 256>>>(emb, embH, n4);
    }

    embed_kernel<<<NN, 128>>>(ids, emb, pe, x);

    dim3 gQKV(QKVD/128, NN/128);     // (12, 32)
    dim3 gProj(DD/128, NN/128);      // (4, 32)
    dim3 gFF1(FFD/128, NN/128);      // (16, 32)
    dim3 gAttn(SS/128, BB*HH);       // (8, 32)

    for (int layer = 0; layer < NLAYERS; layer++) {
        ln_kernel<false><<<NN, 128>>>(x, (uint32_t*)h_hi, (uint32_t*)h_lo, ln1_g, ln1_b);
        gemm_mma<0, false><<<gQKV, 256, GEMM_SMEM_BYTES>>>(
            h_hi, h_lo, wqkvT_hi, wqkvT_lo, nullptr, nullptr,
            qkv, nullptr, nullptr, QKVD, DD);
        attn_kernel<<<gAttn, 128>>>(qkv, ctx_hi, ctx_lo);
        gemm_mma<5, false><<<gProj, 256, GEMM_SMEM_BYTES>>>(
            ctx_hi, ctx_lo, woT_hi, woT_lo, wo_b, x,
            x, nullptr, nullptr, DD, DD);
        ln_kernel<false><<<NN, 128>>>(x, (uint32_t*)h_hi, (uint32_t*)h_lo, ln2_g, ln2_b);
        gemm_mma<3, true><<<gFF1, 256, GEMM_SMEM_BYTES>>>(
            h_hi, h_lo, w1T_hi, w1T_lo, b1, nullptr,
            nullptr, ff_hi, ff_lo, FFD, DD);
        gemm_mma<5, false><<<gProj, 256, GEMM_SMEM_BYTES>>>(
            ff_hi, ff_lo, w2T_hi, w2T_lo, b2, x,
            x, nullptr, nullptr, DD, FFD);
    }

    ln_kernel<true><<<NN, 128>>>(x, (uint32_t*)hf_hi, (uint32_t*)hf_lo, lnf_g, lnf_b);

    dim3 gLM((VV + 127) / 128, NN / 128);   // (393, 32)
    gemm_lm<<<gLM, 256, LM_SMEM_BYTES>>>(hf_hi, hf_lo, embH, out, VV, DD);
}

// round 7
// speedup vs baseline: 2.2345x; 1.0468x over previous
#include <cuda_runtime.h>
#include <cuda_bf16.h>
#include <cuda_fp16.h>
#include <math.h>
#include <stdint.h>

// Problem constants
#define BB 4
#define SS 1024
#define NN (BB*SS)      // 4096 tokens
#define DD 512
#define HH 8
#define DH 64
#define FFD 2048
#define VV 50257
#define NLAYERS 6
#define QKVD 1536       // fused qkv width

// ---------------------------------------------------------------------------
// Scratch (allocation-free: __device__ globals)
// ---------------------------------------------------------------------------
__device__ float g_x[NN*DD];
__device__ __nv_bfloat16 g_h_hi[NN*DD],  g_h_lo[NN*DD];
__device__ float g_qkv[NN*QKVD];
__device__ __nv_bfloat16 g_ctx_hi[NN*DD], g_ctx_lo[NN*DD];
__device__ __nv_bfloat16 g_ff_hi[NN*FFD], g_ff_lo[NN*FFD];
// transposed bf16 weights [N,K]
__device__ __nv_bfloat16 g_wqkvT_hi[3*DD*DD], g_wqkvT_lo[3*DD*DD];
__device__ __nv_bfloat16 g_woT_hi[DD*DD],     g_woT_lo[DD*DD];
__device__ __nv_bfloat16 g_w1T_hi[FFD*DD],    g_w1T_lo[FFD*DD];
__device__ __nv_bfloat16 g_w2T_hi[DD*FFD],    g_w2T_lo[DD*FFD];
// LM head (fp16 1-pass): A single fp16, B single fp16
__device__ __half g_hf[NN*DD];
__device__ __half g_embH[VV*DD];

// ---------------------------------------------------------------------------
// Helpers
// ---------------------------------------------------------------------------
__device__ __forceinline__ uint32_t smem_u32(const void* p) {
    uint32_t a;
    asm("{ .reg .u64 t; cvta.to.shared.u64 t, %1; cvt.u32.u64 %0, t; }"
        : "=r"(a) : "l"(p));
    return a;
}

__device__ __forceinline__ void ldm4(uint32_t* r, uint32_t addr) {
    asm volatile("ldmatrix.sync.aligned.m8n8.x4.shared.b16 {%0,%1,%2,%3}, [%4];"
                 : "=r"(r[0]), "=r"(r[1]), "=r"(r[2]), "=r"(r[3]) : "r"(addr));
}

__device__ __forceinline__ void mma16816(float* c, const uint32_t* a,
                                         uint32_t b0, uint32_t b1) {
    asm volatile(
        "mma.sync.aligned.m16n8k16.row.col.f32.bf16.bf16.f32 "
        "{%0,%1,%2,%3}, {%4,%5,%6,%7}, {%8,%9}, {%0,%1,%2,%3};"
        : "+f"(c[0]), "+f"(c[1]), "+f"(c[2]), "+f"(c[3])
        : "r"(a[0]), "r"(a[1]), "r"(a[2]), "r"(a[3]), "r"(b0), "r"(b1));
}
__device__ __forceinline__ void mma16816h(float* c, const uint32_t* a,
                                          uint32_t b0, uint32_t b1) {
    asm volatile(
        "mma.sync.aligned.m16n8k16.row.col.f32.f16.f16.f32 "
        "{%0,%1,%2,%3}, {%4,%5,%6,%7}, {%8,%9}, {%0,%1,%2,%3};"
        : "+f"(c[0]), "+f"(c[1]), "+f"(c[2]), "+f"(c[3])
        : "r"(a[0]), "r"(a[1]), "r"(a[2]), "r"(a[3]), "r"(b0), "r"(b1));
}

__device__ __forceinline__ void cp_async16(uint32_t dst, const void* src, int szbytes) {
    asm volatile("cp.async.cg.shared.global [%0], [%1], 16, %2;"
                 :: "r"(dst), "l"(src), "r"(szbytes));
}
#define CP_COMMIT() asm volatile("cp.async.commit_group;" ::: "memory")
template<int N>
__device__ __forceinline__ void cp_wait() {
    asm volatile("cp.async.wait_group %0;" :: "n"(N) : "memory");
}

// bf16 hi/lo split helpers
__device__ __forceinline__ void split2(float x, float y, uint32_t& h, uint32_t& l) {
    __nv_bfloat16 h0 = __float2bfloat16_rn(x);
    __nv_bfloat16 h1 = __float2bfloat16_rn(y);
    __nv_bfloat16 l0 = __float2bfloat16_rn(x - __bfloat162float(h0));
    __nv_bfloat16 l1 = __float2bfloat16_rn(y - __bfloat162float(h1));
    h = (uint32_t)__bfloat16_as_ushort(h0) | ((uint32_t)__bfloat16_as_ushort(h1) << 16);
    l = (uint32_t)__bfloat16_as_ushort(l0) | ((uint32_t)__bfloat16_as_ushort(l1) << 16);
}
__device__ __forceinline__ void split4(float4 v, uint2& h, uint2& l) {
    split2(v.x, v.y, h.x, l.x);
    split2(v.z, v.w, h.y, l.y);
}

__device__ __forceinline__ float gelu_exact(float v) {
    return 0.5f * v * (1.0f + erff(v * 0.70710678118654752f));
}

// ---------------------------------------------------------------------------
// Weight conversion: W [K,N] fp32 -> hi/lo [N,K] bf16 (transpose)
// ---------------------------------------------------------------------------
__global__ void conv_wT(const float* __restrict__ W, __nv_bfloat16* __restrict__ hi,
                        __nv_bfloat16* __restrict__ lo, int K, int N) {
    __shared__ float t[32][33];
    int n0 = blockIdx.x * 32, k0 = blockIdx.y * 32;
    int tx = threadIdx.x, ty = threadIdx.y;
    #pragma unroll
    for (int r = 0; r < 4; r++)
        t[ty + r*8][tx] = W[(size_t)(k0 + ty + r*8) * N + n0 + tx];
    __syncthreads();
    #pragma unroll
    for (int r = 0; r < 4; r++) {
        float v = t[tx][ty + r*8];
        __nv_bfloat16 h = __float2bfloat16_rn(v);
        size_t o = (size_t)(n0 + ty + r*8) * K + k0 + tx;
        hi[o] = h;
        lo[o] = __float2bfloat16_rn(v - __bfloat162float(h));
    }
}

// Elementwise fp32 -> fp16 (no transpose), float4 granularity
__global__ void conv_half4(const float* __restrict__ src,
                           __half* __restrict__ dst, int n4) {
    int i = blockIdx.x * 256 + threadIdx.x;
    if (i >= n4) return;
    float4 v = reinterpret_cast<const float4*>(src)[i];
    __half2 a = __floats2half2_rn(v.x, v.y);
    __half2 b = __floats2half2_rn(v.z, v.w);
    uint2 o;
    o.x = *reinterpret_cast<uint32_t*>(&a);
    o.y = *reinterpret_cast<uint32_t*>(&b);
    reinterpret_cast<uint2*>(dst)[i] = o;
}

// ---------------------------------------------------------------------------
// Embedding
// ---------------------------------------------------------------------------
__global__ void embed_kernel(const int* __restrict__ ids,
                             const float* __restrict__ emb,
                             const float* __restrict__ pe,
                             float* __restrict__ x) {
    int n = blockIdx.x;
    int tid = threadIdx.x;
    int id = ids[n];
    int s = n & (SS - 1);
    const float sq = 22.62741699796952f;
    float4 e = reinterpret_cast<const float4*>(emb + (size_t)id * DD)[tid];
    float4 p = reinterpret_cast<const float4*>(pe + (size_t)s * DD)[tid];
    float4 o;
    o.x = e.x * sq + p.x; o.y = e.y * sq + p.y;
    o.z = e.z * sq + p.z; o.w = e.w * sq + p.w;
    reinterpret_cast<float4*>(x + (size_t)n * DD)[tid] = o;
}

// ---------------------------------------------------------------------------
// LayerNorm.  MODE 0: bf16 hi/lo split.  MODE 2: single fp16.
// ---------------------------------------------------------------------------
template<int MODE>
__global__ void ln_kernel(const float* __restrict__ in,
                          uint32_t* __restrict__ out_hi,
                          uint32_t* __restrict__ out_lo,
                          const float* __restrict__ g, const float* __restrict__ b) {
    int row = blockIdx.x;
    int tid = threadIdx.x;    // 128
    float4 v = reinterpret_cast<const float4*>(in + (size_t)row * DD)[tid];
    float s = v.x + v.y + v.z + v.w;
    float ss = v.x*v.x + v.y*v.y + v.z*v.z + v.w*v.w;
    #pragma unroll
    for (int o = 16; o > 0; o >>= 1) {
        s  += __shfl_xor_sync(0xffffffffu, s, o);
        ss += __shfl_xor_sync(0xffffffffu, ss, o);
    }
    __shared__ float rs[4], rss[4];
    int warp = tid >> 5;
    if ((tid & 31) == 0) { rs[warp] = s; rss[warp] = ss; }
    __syncthreads();
    float mean = (rs[0]+rs[1]+rs[2]+rs[3]) * (1.0f/DD);
    float var  = (rss[0]+rss[1]+rss[2]+rss[3]) * (1.0f/DD) - mean*mean;
    float rstd = rsqrtf(var + 1e-5f);
    float4 gg = reinterpret_cast<const float4*>(g)[tid];
    float4 bb = reinterpret_cast<const float4*>(b)[tid];
    float4 o;
    o.x = (v.x - mean)*rstd*gg.x + bb.x;
    o.y = (v.y - mean)*rstd*gg.y + bb.y;
    o.z = (v.z - mean)*rstd*gg.z + bb.z;
    o.w = (v.w - mean)*rstd*gg.w + bb.w;
    if (MODE == 0) {
        uint2 h, l;
        split4(o, h, l);
        reinterpret_cast<uint2*>(out_hi)[(size_t)row * (DD/4) + tid] = h;
        reinterpret_cast<uint2*>(out_lo)[(size_t)row * (DD/4) + tid] = l;
    } else {
        __half2 a = __floats2half2_rn(o.x, o.y);
        __half2 c = __floats2half2_rn(o.z, o.w);
        uint2 hh;
        hh.x = *reinterpret_cast<uint32_t*>(&a);
        hh.y = *reinterpret_cast<uint32_t*>(&c);
        reinterpret_cast<uint2*>(out_hi)[(size_t)row * (DD/4) + tid] = hh;
    }
}

// ---------------------------------------------------------------------------
// Layer GEMM: bf16 3-pass HMMA, CTA 128x128, 4 warps (2x2), warp tile 64x64.
// 12 LDSM / 96 MMA per k-step -> MMA-bound (smem 256cyc < tensor 384cyc).
// EPI bits: 1=bias, 2=gelu, 4=resid. SPLIT: write bf16 hi/lo.
// All layer Nout are multiples of 128; no guards.
// ---------------------------------------------------------------------------
#define SUBT 16384                      // 128 rows x 128B
#define STG3 (4*SUBT)                   // Ahi,Alo,Bhi,Blo = 64KB
#define NST3 3
#define G3_SMEM (NST3*STG3)             // 196608

template<int EPI, bool SPLIT>
__global__ __launch_bounds__(128, 1)
void gemm3(const __nv_bfloat16* __restrict__ Ahi, const __nv_bfloat16* __restrict__ Alo,
           const __nv_bfloat16* __restrict__ Bhi, const __nv_bfloat16* __restrict__ Blo,
           const float* __restrict__ bias, const float* __restrict__ resid,
           float* __restrict__ C, __nv_bfloat16* __restrict__ Chi,
           __nv_bfloat16* __restrict__ Clo, int Nout, int K) {
    extern __shared__ char smem[];
    uint32_t sb = smem_u32(smem);
    const int tid = threadIdx.x;
    const int lane = tid & 31, wid = tid >> 5;
    const int m0 = blockIdx.y * 128, n0 = blockIdx.x * 128;
    const int warp_m = (wid >> 1) * 64;
    const int warp_n = (wid & 1) * 64;

    float acc[4][8][4];
    #pragma unroll
    for (int i = 0; i < 4; i++)
        #pragma unroll
        for (int j = 0; j < 8; j++)
            #pragma unroll
            for (int e = 0; e < 4; e++) acc[i][j][e] = 0.f;

    const int nch = K >> 6;

    auto load_stage = [&](int buf, int k0) {
        uint32_t base = sb + buf * STG3;
        const __nv_bfloat16* srcs[4] = {Ahi, Alo, Bhi, Blo};
        #pragma unroll
        for (int sub = 0; sub < 4; sub++) {
            const __nv_bfloat16* P = srcs[sub];
            int row0 = (sub < 2) ? m0 : n0;
            uint32_t dbase = base + sub * SUBT;
            #pragma unroll
            for (int it = 0; it < 8; it++) {
                int u = tid + it * 128;
                int row = u >> 3, c = u & 7;
                uint32_t dst = dbase + row * 128 + ((c ^ (row & 7)) * 16);
                const __nv_bfloat16* g = P + (size_t)(row0 + row) * K + k0 + c * 8;
                cp_async16(dst, g, 16);
            }
        }
    };

    int ra[4];
    #pragma unroll
    for (int mb = 0; mb < 4; mb++) ra[mb] = warp_m + mb * 16 + (lane & 15);
    const int ca = lane >> 4;
    int rB[4];
    #pragma unroll
    for (int nb = 0; nb < 4; nb++)
        rB[nb] = warp_n + nb * 16 + ((lane >> 4) & 1) * 8 + (lane & 7);
    const int kcB = (lane >> 3) & 1;

    auto compute = [&](int buf) {
        uint32_t base = sb + buf * STG3;
        #pragma unroll
        for (int ks = 0; ks < 4; ks++) {
            uint32_t ah[4][4], al[4][4], bb[4][4];
            uint32_t offb[4];
            #pragma unroll
            for (int mb = 0; mb < 4; mb++) {
                uint32_t off = ra[mb] * 128 + (((ks*2 + ca) ^ (ra[mb] & 7)) * 16);
                ldm4(ah[mb], base + off);
                ldm4(al[mb], base + SUBT + off);
            }
            #pragma unroll
            for (int nb = 0; nb < 4; nb++) {
                offb[nb] = rB[nb] * 128 + (((ks*2 + kcB) ^ (rB[nb] & 7)) * 16);
                ldm4(bb[nb], base + 2*SUBT + offb[nb]);
            }
            // pass 1: Ah * Bh
            #pragma unroll
            for (int mb = 0; mb < 4; mb++)
                #pragma unroll
                for (int nb = 0; nb < 4; nb++) {
                    mma16816(acc[mb][nb*2],   ah[mb], bb[nb][0], bb[nb][1]);
                    mma16816(acc[mb][nb*2+1], ah[mb], bb[nb][2], bb[nb][3]);
                }
            // pass 2: Al * Bh
            #pragma unroll
            for (int mb = 0; mb < 4; mb++)
                #pragma unroll
                for (int nb = 0; nb < 4; nb++) {
                    mma16816(acc[mb][nb*2],   al[mb], bb[nb][0], bb[nb][1]);
                    mma16816(acc[mb][nb*2+1], al[mb], bb[nb][2], bb[nb][3]);
                }
            // reload B as Bl, pass 3: Ah * Bl
            #pragma unroll
            for (int nb = 0; nb < 4; nb++)
                ldm4(bb[nb], base + 3*SUBT + offb[nb]);
            #pragma unroll
            for (int mb = 0; mb < 4; mb++)
                #pragma unroll
                for (int nb = 0; nb < 4; nb++) {
                    mma16816(acc[mb][nb*2],   ah[mb], bb[nb][0], bb[nb][1]);
                    mma16816(acc[mb][nb*2+1], ah[mb], bb[nb][2], bb[nb][3]);
                }
        }
    };

    load_stage(0, 0);
    CP_COMMIT();
    if (nch > 1) { load_stage(1, 64); CP_COMMIT(); }
    for (int c = 0; c < nch; c++) {
        if (c == nch - 1) cp_wait<0>(); else cp_wait<1>();
        __syncthreads();
        compute(c % NST3);
        int nx = c + 2;
        if (nx < nch) { load_stage(nx % NST3, nx << 6); CP_COMMIT(); }
    }

    const int gid = lane >> 2, qid = lane & 3;
    #pragma unroll
    for (int mb = 0; mb < 4; mb++) {
        #pragma unroll
        for (int nf = 0; nf < 8; nf++) {
            int n = n0 + warp_n + nf * 8 + qid * 2;
            #pragma unroll
            for (int hh = 0; hh < 2; hh++) {
                int m = m0 + warp_m + mb * 16 + gid + hh * 8;
                float vx = acc[mb][nf][hh*2];
                float vy = acc[mb][nf][hh*2 + 1];
                if (EPI & 1) { vx += bias[n]; vy += bias[n + 1]; }
                if (EPI & 2) { vx = gelu_exact(vx); vy = gelu_exact(vy); }
                size_t o = (size_t)m * Nout + n;
                if (EPI & 4) {
                    float2 r = *reinterpret_cast<const float2*>(resid + o);
                    vx += r.x; vy += r.y;
                }
                if (SPLIT) {
                    uint32_t h, l;
                    split2(vx, vy, h, l);
                    *reinterpret_cast<uint32_t*>(Chi + o) = h;
                    *reinterpret_cast<uint32_t*>(Clo + o) = l;
                } else {
                    *reinterpret_cast<float2*>(C + o) = make_float2(vx, vy);
                }
            }
        }
    }
}

// ---------------------------------------------------------------------------
// LM-head GEMM: fp16 1-pass, CTA 128x256, 8 warps (2x4), warp tile 64x64.
// C[M,V] = A[M,K] @ B^T, A fp16 (lnf output), B fp16 emb. N guard (V odd).
// ---------------------------------------------------------------------------
#define STGL (3*SUBT)                   // A 16KB + B 32KB = 48KB
#define NSTL 3
#define GL_SMEM (NSTL*STGL)             // 147456

__global__ __launch_bounds__(256, 1)
void gemm_lm(const __half* __restrict__ A, const __half* __restrict__ B,
             float* __restrict__ C, int Nout, int K) {
    extern __shared__ char smem[];
    uint32_t sb = smem_u32(smem);
    const int tid = threadIdx.x;
    const int lane = tid & 31, wid = tid >> 5;
    const int m0 = blockIdx.y * 128, n0 = blockIdx.x * 256;
    const int warp_m = (wid >> 2) * 64;
    const int warp_n = (wid & 3) * 64;

    float acc[4][8][4];
    #pragma unroll
    for (int i = 0; i < 4; i++)
        #pragma unroll
        for (int j = 0; j < 8; j++)
            #pragma unroll
            for (int e = 0; e < 4; e++) acc[i][j][e] = 0.f;

    const int nch = K >> 6;   // 8

    auto load_stage = [&](int buf, int k0) {
        uint32_t base = sb + buf * STGL;
        // A sub-tile: 128 rows
        #pragma unroll
        for (int it = 0; it < 4; it++) {
            int u = tid + it * 256;
            int row = u >> 3, c = u & 7;
            uint32_t dst = base + row * 128 + ((c ^ (row & 7)) * 16);
            cp_async16(dst, A + (size_t)(m0 + row) * K + k0 + c * 8, 16);
        }
        // B sub-tile: 256 rows, guarded
        #pragma unroll
        for (int it = 0; it < 8; it++) {
            int u = tid + it * 256;
            int row = u >> 3, c = u & 7;
            uint32_t dst = base + SUBT + row * 128 + ((c ^ (row & 7)) * 16);
            const __half* g = B + (size_t)(n0 + row) * K + k0 + c * 8;
            int sz = 16;
            if (n0 + row >= Nout) { g = B; sz = 0; }
            cp_async16(dst, g, sz);
        }
    };

    int ra[4];
    #pragma unroll
    for (int mb = 0; mb < 4; mb++) ra[mb] = warp_m + mb * 16 + (lane & 15);
    const int ca = lane >> 4;
    int rB[4];
    #pragma unroll
    for (int nb = 0; nb < 4; nb++)
        rB[nb] = warp_n + nb * 16 + ((lane >> 4) & 1) * 8 + (lane & 7);
    const int kcB = (lane >> 3) & 1;

    auto compute = [&](int buf) {
        uint32_t base = sb + buf * STGL;
        #pragma unroll
        for (int ks = 0; ks < 4; ks++) {
            uint32_t a[4][4], b[4][4];
            #pragma unroll
            for (int mb = 0; mb < 4; mb++) {
                uint32_t off = ra[mb] * 128 + (((ks*2 + ca) ^ (ra[mb] & 7)) * 16);
                ldm4(a[mb], base + off);
            }
            #pragma unroll
            for (int nb = 0; nb < 4; nb++) {
                uint32_t off = rB[nb] * 128 + (((ks*2 + kcB) ^ (rB[nb] & 7)) * 16);
                ldm4(b[nb], base + SUBT + off);
            }
            #pragma unroll
            for (int mb = 0; mb < 4; mb++)
                #pragma unroll
                for (int nb = 0; nb < 4; nb++) {
                    mma16816h(acc[mb][nb*2],   a[mb], b[nb][0], b[nb][1]);
                    mma16816h(acc[mb][nb*2+1], a[mb], b[nb][2], b[nb][3]);
                }
        }
    };

    load_stage(0, 0);
    CP_COMMIT();
    load_stage(1, 64);
    CP_COMMIT();
    for (int c = 0; c < nch; c++) {
        if (c == nch - 1) cp_wait<0>(); else cp_wait<1>();
        __syncthreads();
        compute(c % NSTL);
        int nx = c + 2;
        if (nx < nch) { load_stage(nx % NSTL, nx << 6); CP_COMMIT(); }
    }

    const int gid = lane >> 2, qid = lane & 3;
    #pragma unroll
    for (int mb = 0; mb < 4; mb++) {
        #pragma unroll
        for (int nf = 0; nf < 8; nf++) {
            int n = n0 + warp_n + nf * 8 + qid * 2;
            #pragma unroll
            for (int hh = 0; hh < 2; hh++) {
                int m = m0 + warp_m + mb * 16 + gid + hh * 8;
                float vx = acc[mb][nf][hh*2];
                float vy = acc[mb][nf][hh*2 + 1];
                size_t o = (size_t)m * Nout + n;
                // scalar stores: o may be odd (Nout=50257) -> no vector stores
                if (n < Nout)     C[o]     = vx;
                if (n + 1 < Nout) C[o + 1] = vy;
            }
        }
    }
}

// ---------------------------------------------------------------------------
// Causal flash attention (fp32), qkv fused layout [M, 1536], out -> bf16 hi/lo
// ---------------------------------------------------------------------------
__global__ __launch_bounds__(128)
void attn_kernel(const float* __restrict__ qkv,
                 __nv_bfloat16* __restrict__ ctx_hi,
                 __nv_bfloat16* __restrict__ ctx_lo) {
    __shared__ float4 ks[64][16];
    __shared__ float4 vs[64][16];
    int bh = blockIdx.y;
    int b = bh >> 3, h = bh & 7;
    int r = blockIdx.x * 128 + threadIdx.x;

    const float* qp = qkv + ((size_t)(b * SS + r) * QKVD + h * DH);
    float4 qf[16];
    #pragma unroll
    for (int c = 0; c < 16; c++) qf[c] = reinterpret_cast<const float4*>(qp)[c];

    float4 acc[16];
    #pragma unroll
    for (int c = 0; c < 16; c++) acc[c] = make_float4(0.f, 0.f, 0.f, 0.f);
    float m = -1e30f, l = 0.f;

    int ntiles = (blockIdx.x * 128) / 64 + 2;
    for (int t = 0; t < ntiles; t++) {
        int kbase = t * 64;
        #pragma unroll
        for (int i = 0; i < 8; i++) {
            int idx = threadIdx.x + i * 128;
            int j = idx >> 4, c = idx & 15;
            size_t off = (size_t)(b * SS + kbase + j) * QKVD + h * DH;
            ks[j][c] = reinterpret_cast<const float4*>(qkv + off + DD)[c];
            vs[j][c] = reinterpret_cast<const float4*>(qkv + off + 2*DD)[c];
        }
        __syncthreads();
        int jmax = r - kbase + 1;
        if (jmax > 64) jmax = 64;
        for (int j = 0; j < jmax; j++) {
            float s = 0.f;
            #pragma unroll
            for (int c = 0; c < 16; c++) {
                float4 kk = ks[j][c];
                s += qf[c].x*kk.x + qf[c].y*kk.y + qf[c].z*kk.z + qf[c].w*kk.w;
            }
            s *= 0.125f;
            if (s > m) {
                float sc = __expf(m - s);
                l *= sc;
                #pragma unroll
                for (int c = 0; c < 16; c++) {
                    acc[c].x *= sc; acc[c].y *= sc; acc[c].z *= sc; acc[c].w *= sc;
                }
                m = s;
            }
            float p = __expf(s - m);
            l += p;
            #pragma unroll
            for (int c = 0; c < 16; c++) {
                float4 vv = vs[j][c];
                acc[c].x += p*vv.x; acc[c].y += p*vv.y;
                acc[c].z += p*vv.z; acc[c].w += p*vv.w;
            }
        }
        __syncthreads();
    }

    float inv = 1.0f / l;
    size_t off = (size_t)(b * SS + r) * DD + h * DH;
    #pragma unroll
    for (int c = 0; c < 16; c++) {
        float4 o;
        o.x = acc[c].x*inv; o.y = acc[c].y*inv; o.z = acc[c].z*inv; o.w = acc[c].w*inv;
        uint2 hh, ll;
        split4(o, hh, ll);
        reinterpret_cast<uint2*>(ctx_hi + off)[c] = hh;
        reinterpret_cast<uint2*>(ctx_lo + off)[c] = ll;
    }
}

// ---------------------------------------------------------------------------
// Host launch
// ---------------------------------------------------------------------------
extern "C" void kernel_launch(void* const* d_in, const int* in_sizes, int n_in,
                              void* d_out, int out_size) {
    const int*   ids   = (const int*)  d_in[0];
    const float* emb   = (const float*)d_in[1];
    const float* pe    = (const float*)d_in[2];
    const float* wq    = (const float*)d_in[3];
    const float* wk    = (const float*)d_in[4];
    const float* wv    = (const float*)d_in[5];
    const float* wo    = (const float*)d_in[6];
    const float* wo_b  = (const float*)d_in[7];
    const float* w1    = (const float*)d_in[8];
    const float* b1    = (const float*)d_in[9];
    const float* w2    = (const float*)d_in[10];
    const float* b2    = (const float*)d_in[11];
    const float* ln1_g = (const float*)d_in[12];
    const float* ln1_b = (const float*)d_in[13];
    const float* ln2_g = (const float*)d_in[14];
    const float* ln2_b = (const float*)d_in[15];
    const float* lnf_g = (const float*)d_in[16];
    const float* lnf_b = (const float*)d_in[17];
    float* out = (float*)d_out;

    float *x, *qkv;
    __nv_bfloat16 *h_hi, *h_lo, *ctx_hi, *ctx_lo, *ff_hi, *ff_lo;
    __nv_bfloat16 *wqkvT_hi, *wqkvT_lo, *woT_hi, *woT_lo;
    __nv_bfloat16 *w1T_hi, *w1T_lo, *w2T_hi, *w2T_lo;
    __half *hf, *embH;
    cudaGetSymbolAddress((void**)&x, g_x);
    cudaGetSymbolAddress((void**)&qkv, g_qkv);
    cudaGetSymbolAddress((void**)&h_hi, g_h_hi);
    cudaGetSymbolAddress((void**)&h_lo, g_h_lo);
    cudaGetSymbolAddress((void**)&ctx_hi, g_ctx_hi);
    cudaGetSymbolAddress((void**)&ctx_lo, g_ctx_lo);
    cudaGetSymbolAddress((void**)&ff_hi, g_ff_hi);
    cudaGetSymbolAddress((void**)&ff_lo, g_ff_lo);
    cudaGetSymbolAddress((void**)&wqkvT_hi, g_wqkvT_hi);
    cudaGetSymbolAddress((void**)&wqkvT_lo, g_wqkvT_lo);
    cudaGetSymbolAddress((void**)&woT_hi, g_woT_hi);
    cudaGetSymbolAddress((void**)&woT_lo, g_woT_lo);
    cudaGetSymbolAddress((void**)&w1T_hi, g_w1T_hi);
    cudaGetSymbolAddress((void**)&w1T_lo, g_w1T_lo);
    cudaGetSymbolAddress((void**)&w2T_hi, g_w2T_hi);
    cudaGetSymbolAddress((void**)&w2T_lo, g_w2T_lo);
    cudaGetSymbolAddress((void**)&hf, g_hf);
    cudaGetSymbolAddress((void**)&embH, g_embH);

    cudaFuncSetAttribute(gemm3<0, false>, cudaFuncAttributeMaxDynamicSharedMemorySize, G3_SMEM);
    cudaFuncSetAttribute(gemm3<5, false>, cudaFuncAttributeMaxDynamicSharedMemorySize, G3_SMEM);
    cudaFuncSetAttribute(gemm3<3, true >, cudaFuncAttributeMaxDynamicSharedMemorySize, G3_SMEM);
    cudaFuncSetAttribute(gemm_lm, cudaFuncAttributeMaxDynamicSharedMemorySize, GL_SMEM);

    // weight conversions (run each replay; cheap)
    dim3 cb(32, 8);
    conv_wT<<<dim3(DD/32, DD/32), cb>>>(wq, wqkvT_hi,            wqkvT_lo,            DD, DD);
    conv_wT<<<dim3(DD/32, DD/32), cb>>>(wk, wqkvT_hi + DD*DD,    wqkvT_lo + DD*DD,    DD, DD);
    conv_wT<<<dim3(DD/32, DD/32), cb>>>(wv, wqkvT_hi + 2*DD*DD,  wqkvT_lo + 2*DD*DD,  DD, DD);
    conv_wT<<<dim3(DD/32, DD/32), cb>>>(wo, woT_hi, woT_lo, DD, DD);
    conv_wT<<<dim3(FFD/32, DD/32), cb>>>(w1, w1T_hi, w1T_lo, DD, FFD);
    conv_wT<<<dim3(DD/32, FFD/32), cb>>>(w2, w2T_hi, w2T_lo, FFD, DD);
    {
        int n4 = VV * DD / 4;
        conv_half4<<<(n4 + 255) / 256, 256>>>(emb, embH, n4);
    }

    embed_kernel<<<NN, 128>>>(ids, emb, pe, x);

    dim3 gQKV(QKVD/128, NN/128);     // (12, 32)
    dim3 gProj(DD/128, NN/128);      // (4, 32)
    dim3 gFF1(FFD/128, NN/128);      // (16, 32)
    dim3 gAttn(SS/128, BB*HH);       // (8, 32)

    for (int layer = 0; layer < NLAYERS; layer++) {
        ln_kernel<0><<<NN, 128>>>(x, (uint32_t*)h_hi, (uint32_t*)h_lo, ln1_g, ln1_b);
        gemm3<0, false><<<gQKV, 128, G3_SMEM>>>(
            h_hi, h_lo, wqkvT_hi, wqkvT_lo, nullptr, nullptr,
            qkv, nullptr, nullptr, QKVD, DD);
        attn_kernel<<<gAttn, 128>>>(qkv, ctx_hi, ctx_lo);
        gemm3<5, false><<<gProj, 128, G3_SMEM>>>(
            ctx_hi, ctx_lo, woT_hi, woT_lo, wo_b, x,
            x, nullptr, nullptr, DD, DD);
        ln_kernel<0><<<NN, 128>>>(x, (uint32_t*)h_hi, (uint32_t*)h_lo, ln2_g, ln2_b);
        gemm3<3, true><<<gFF1, 128, G3_SMEM>>>(
            h_hi, h_lo, w1T_hi, w1T_lo, b1, nullptr,
            nullptr, ff_hi, ff_lo, FFD, DD);
        gemm3<5, false><<<gProj, 128, G3_SMEM>>>(
            ff_hi, ff_lo, w2T_hi, w2T_lo, b2, x,
            x, nullptr, nullptr, DD, FFD);
    }

    ln_kernel<2><<<NN, 128>>>(x, (uint32_t*)hf, nullptr, lnf_g, lnf_b);

    dim3 gLM((VV + 255) / 256, NN / 128);   // (197, 32)
    gemm_lm<<<gLM, 256, GL_SMEM>>>(hf, embH, out, VV, DD);
}

// round 8
// speedup vs baseline: 2.6779x; 1.1984x over previous
#include <cuda_runtime.h>
#include <cuda_bf16.h>
#include <cuda_fp16.h>
#include <math.h>
#include <stdint.h>

// Problem constants
#define BB 4
#define SS 1024
#define NN (BB*SS)      // 4096 tokens
#define DD 512
#define HH 8
#define DH 64
#define FFD 2048
#define VV 50257
#define NLAYERS 6
#define QKVD 1536       // fused qkv width

// ---------------------------------------------------------------------------
// Scratch (allocation-free: __device__ globals)
// ---------------------------------------------------------------------------
__device__ float g_x[NN*DD];
__device__ __nv_bfloat16 g_h_hi[NN*DD],  g_h_lo[NN*DD];
__device__ float g_qkv[NN*QKVD];
__device__ __nv_bfloat16 g_ctx_hi[NN*DD], g_ctx_lo[NN*DD];
__device__ __nv_bfloat16 g_ff_hi[NN*FFD], g_ff_lo[NN*FFD];
// transposed bf16 weights [N,K]
__device__ __nv_bfloat16 g_wqkvT_hi[3*DD*DD], g_wqkvT_lo[3*DD*DD];
__device__ __nv_bfloat16 g_woT_hi[DD*DD],     g_woT_lo[DD*DD];
__device__ __nv_bfloat16 g_w1T_hi[FFD*DD],    g_w1T_lo[FFD*DD];
__device__ __nv_bfloat16 g_w2T_hi[DD*FFD],    g_w2T_lo[DD*FFD];
// LM head (fp16 1-pass)
__device__ __half g_hf[NN*DD];
__device__ __half g_embH[VV*DD];

// ---------------------------------------------------------------------------
// Helpers
// ---------------------------------------------------------------------------
__device__ __forceinline__ uint32_t smem_u32(const void* p) {
    uint32_t a;
    asm("{ .reg .u64 t; cvta.to.shared.u64 t, %1; cvt.u32.u64 %0, t; }"
        : "=r"(a) : "l"(p));
    return a;
}

__device__ __forceinline__ void ldm4(uint32_t* r, uint32_t addr) {
    asm volatile("ldmatrix.sync.aligned.m8n8.x4.shared.b16 {%0,%1,%2,%3}, [%4];"
                 : "=r"(r[0]), "=r"(r[1]), "=r"(r[2]), "=r"(r[3]) : "r"(addr));
}

__device__ __forceinline__ void mma16816(float* c, const uint32_t* a,
                                         uint32_t b0, uint32_t b1) {
    asm volatile(
        "mma.sync.aligned.m16n8k16.row.col.f32.bf16.bf16.f32 "
        "{%0,%1,%2,%3}, {%4,%5,%6,%7}, {%8,%9}, {%0,%1,%2,%3};"
        : "+f"(c[0]), "+f"(c[1]), "+f"(c[2]), "+f"(c[3])
        : "r"(a[0]), "r"(a[1]), "r"(a[2]), "r"(a[3]), "r"(b0), "r"(b1));
}
__device__ __forceinline__ void mma16816h(float* c, const uint32_t* a,
                                          uint32_t b0, uint32_t b1) {
    asm volatile(
        "mma.sync.aligned.m16n8k16.row.col.f32.f16.f16.f32 "
        "{%0,%1,%2,%3}, {%4,%5,%6,%7}, {%8,%9}, {%0,%1,%2,%3};"
        : "+f"(c[0]), "+f"(c[1]), "+f"(c[2]), "+f"(c[3])
        : "r"(a[0]), "r"(a[1]), "r"(a[2]), "r"(a[3]), "r"(b0), "r"(b1));
}

__device__ __forceinline__ void cp_async16(uint32_t dst, const void* src, int szbytes) {
    asm volatile("cp.async.cg.shared.global [%0], [%1], 16, %2;"
                 :: "r"(dst), "l"(src), "r"(szbytes));
}
#define CP_COMMIT() asm volatile("cp.async.commit_group;" ::: "memory")
template<int N>
__device__ __forceinline__ void cp_wait() {
    asm volatile("cp.async.wait_group %0;" :: "n"(N) : "memory");
}

// bf16 hi/lo split helpers
__device__ __forceinline__ void split2(float x, float y, uint32_t& h, uint32_t& l) {
    __nv_bfloat16 h0 = __float2bfloat16_rn(x);
    __nv_bfloat16 h1 = __float2bfloat16_rn(y);
    __nv_bfloat16 l0 = __float2bfloat16_rn(x - __bfloat162float(h0));
    __nv_bfloat16 l1 = __float2bfloat16_rn(y - __bfloat162float(h1));
    h = (uint32_t)__bfloat16_as_ushort(h0) | ((uint32_t)__bfloat16_as_ushort(h1) << 16);
    l = (uint32_t)__bfloat16_as_ushort(l0) | ((uint32_t)__bfloat16_as_ushort(l1) << 16);
}
__device__ __forceinline__ void split4(float4 v, uint2& h, uint2& l) {
    split2(v.x, v.y, h.x, l.x);
    split2(v.z, v.w, h.y, l.y);
}

__device__ __forceinline__ float gelu_exact(float v) {
    return 0.5f * v * (1.0f + erff(v * 0.70710678118654752f));
}

// ---------------------------------------------------------------------------
// Weight conversion: W [K,N] fp32 -> hi/lo [N,K] bf16 (transpose)
// ---------------------------------------------------------------------------
__global__ void conv_wT(const float* __restrict__ W, __nv_bfloat16* __restrict__ hi,
                        __nv_bfloat16* __restrict__ lo, int K, int N) {
    __shared__ float t[32][33];
    int n0 = blockIdx.x * 32, k0 = blockIdx.y * 32;
    int tx = threadIdx.x, ty = threadIdx.y;
    #pragma unroll
    for (int r = 0; r < 4; r++)
        t[ty + r*8][tx] = W[(size_t)(k0 + ty + r*8) * N + n0 + tx];
    __syncthreads();
    #pragma unroll
    for (int r = 0; r < 4; r++) {
        float v = t[tx][ty + r*8];
        __nv_bfloat16 h = __float2bfloat16_rn(v);
        size_t o = (size_t)(n0 + ty + r*8) * K + k0 + tx;
        hi[o] = h;
        lo[o] = __float2bfloat16_rn(v - __bfloat162float(h));
    }
}

// Elementwise fp32 -> fp16
__global__ void conv_half4(const float* __restrict__ src,
                           __half* __restrict__ dst, int n4) {
    int i = blockIdx.x * 256 + threadIdx.x;
    if (i >= n4) return;
    float4 v = reinterpret_cast<const float4*>(src)[i];
    __half2 a = __floats2half2_rn(v.x, v.y);
    __half2 b = __floats2half2_rn(v.z, v.w);
    uint2 o;
    o.x = *reinterpret_cast<uint32_t*>(&a);
    o.y = *reinterpret_cast<uint32_t*>(&b);
    reinterpret_cast<uint2*>(dst)[i] = o;
}

// ---------------------------------------------------------------------------
// Embedding
// ---------------------------------------------------------------------------
__global__ void embed_kernel(const int* __restrict__ ids,
                             const float* __restrict__ emb,
                             const float* __restrict__ pe,
                             float* __restrict__ x) {
    int n = blockIdx.x;
    int tid = threadIdx.x;
    int id = ids[n];
    int s = n & (SS - 1);
    const float sq = 22.62741699796952f;
    float4 e = reinterpret_cast<const float4*>(emb + (size_t)id * DD)[tid];
    float4 p = reinterpret_cast<const float4*>(pe + (size_t)s * DD)[tid];
    float4 o;
    o.x = e.x * sq + p.x; o.y = e.y * sq + p.y;
    o.z = e.z * sq + p.z; o.w = e.w * sq + p.w;
    reinterpret_cast<float4*>(x + (size_t)n * DD)[tid] = o;
}

// ---------------------------------------------------------------------------
// LayerNorm.  MODE 0: bf16 hi/lo split.  MODE 2: single fp16.
// ---------------------------------------------------------------------------
template<int MODE>
__global__ void ln_kernel(const float* __restrict__ in,
                          uint32_t* __restrict__ out_hi,
                          uint32_t* __restrict__ out_lo,
                          const float* __restrict__ g, const float* __restrict__ b) {
    int row = blockIdx.x;
    int tid = threadIdx.x;    // 128
    float4 v = reinterpret_cast<const float4*>(in + (size_t)row * DD)[tid];
    float s = v.x + v.y + v.z + v.w;
    float ss = v.x*v.x + v.y*v.y + v.z*v.z + v.w*v.w;
    #pragma unroll
    for (int o = 16; o > 0; o >>= 1) {
        s  += __shfl_xor_sync(0xffffffffu, s, o);
        ss += __shfl_xor_sync(0xffffffffu, ss, o);
    }
    __shared__ float rs[4], rss[4];
    int warp = tid >> 5;
    if ((tid & 31) == 0) { rs[warp] = s; rss[warp] = ss; }
    __syncthreads();
    float mean = (rs[0]+rs[1]+rs[2]+rs[3]) * (1.0f/DD);
    float var  = (rss[0]+rss[1]+rss[2]+rss[3]) * (1.0f/DD) - mean*mean;
    float rstd = rsqrtf(var + 1e-5f);
    float4 gg = reinterpret_cast<const float4*>(g)[tid];
    float4 bb = reinterpret_cast<const float4*>(b)[tid];
    float4 o;
    o.x = (v.x - mean)*rstd*gg.x + bb.x;
    o.y = (v.y - mean)*rstd*gg.y + bb.y;
    o.z = (v.z - mean)*rstd*gg.z + bb.z;
    o.w = (v.w - mean)*rstd*gg.w + bb.w;
    if (MODE == 0) {
        uint2 h, l;
        split4(o, h, l);
        reinterpret_cast<uint2*>(out_hi)[(size_t)row * (DD/4) + tid] = h;
        reinterpret_cast<uint2*>(out_lo)[(size_t)row * (DD/4) + tid] = l;
    } else {
        __half2 a = __floats2half2_rn(o.x, o.y);
        __half2 c = __floats2half2_rn(o.z, o.w);
        uint2 hh;
        hh.x = *reinterpret_cast<uint32_t*>(&a);
        hh.y = *reinterpret_cast<uint32_t*>(&c);
        reinterpret_cast<uint2*>(out_hi)[(size_t)row * (DD/4) + tid] = hh;
    }
}

#define SUBT 16384                      // 128 rows x 128B

// ---------------------------------------------------------------------------
// Wide layer GEMM (qkv, ff1): bf16 3-pass, CTA 128x256, 256 thr, 8 warps
// (2M x 4N), warp tile 64x64. Stage = Ahi16+Alo16+Bhi32+Blo32 = 96KB, 2-stage.
// ---------------------------------------------------------------------------
#define STGW (6*SUBT)                   // 96KB
#define GW_SMEM (2*STGW)                // 196608

template<int EPI, bool SPLIT>
__global__ __launch_bounds__(256, 1)
void gemm_w(const __nv_bfloat16* __restrict__ Ahi, const __nv_bfloat16* __restrict__ Alo,
            const __nv_bfloat16* __restrict__ Bhi, const __nv_bfloat16* __restrict__ Blo,
            const float* __restrict__ bias,
            float* __restrict__ C, __nv_bfloat16* __restrict__ Chi,
            __nv_bfloat16* __restrict__ Clo, int Nout, int K) {
    extern __shared__ char smem[];
    uint32_t sb = smem_u32(smem);
    const int tid = threadIdx.x;
    const int lane = tid & 31, wid = tid >> 5;
    const int m0 = blockIdx.y * 128, n0 = blockIdx.x * 256;
    const int warp_m = (wid >> 2) * 64;
    const int warp_n = (wid & 3) * 64;

    float acc[4][8][4];
    #pragma unroll
    for (int i = 0; i < 4; i++)
        #pragma unroll
        for (int j = 0; j < 8; j++)
            #pragma unroll
            for (int e = 0; e < 4; e++) acc[i][j][e] = 0.f;

    const int nch = K >> 6;   // 8

    // stage layout: Ahi@0(16K) Alo@16K Bhi@32K(32K) Blo@64K(32K)
    auto load_stage = [&](int buf, int k0) {
        uint32_t base = sb + buf * STGW;
        #pragma unroll
        for (int t = 0; t < 2; t++) {          // Ahi, Alo
            const __nv_bfloat16* P = t ? Alo : Ahi;
            uint32_t dbase = base + t * SUBT;
            #pragma unroll
            for (int it = 0; it < 4; it++) {
                int u = tid + it * 256;
                int row = u >> 3, c = u & 7;
                uint32_t dst = dbase + row * 128 + ((c ^ (row & 7)) * 16);
                cp_async16(dst, P + (size_t)(m0 + row) * K + k0 + c * 8, 16);
            }
        }
        #pragma unroll
        for (int t = 0; t < 2; t++) {          // Bhi, Blo (256 rows each)
            const __nv_bfloat16* P = t ? Blo : Bhi;
            uint32_t dbase = base + 2*SUBT + t * 2*SUBT;
            #pragma unroll
            for (int it = 0; it < 8; it++) {
                int u = tid + it * 256;
                int row = u >> 3, c = u & 7;
                uint32_t dst = dbase + row * 128 + ((c ^ (row & 7)) * 16);
                cp_async16(dst, P + (size_t)(n0 + row) * K + k0 + c * 8, 16);
            }
        }
    };

    int ra[4];
    #pragma unroll
    for (int mb = 0; mb < 4; mb++) ra[mb] = warp_m + mb * 16 + (lane & 15);
    const int ca = lane >> 4;
    int rB[4];
    #pragma unroll
    for (int nb = 0; nb < 4; nb++)
        rB[nb] = warp_n + nb * 16 + ((lane >> 4) & 1) * 8 + (lane & 7);
    const int kcB = (lane >> 3) & 1;

    auto compute = [&](int buf) {
        uint32_t base = sb + buf * STGW;
        #pragma unroll
        for (int ks = 0; ks < 4; ks++) {
            uint32_t ah[4][4], al[4][4], bb[4][4];
            uint32_t offb[4];
            #pragma unroll
            for (int mb = 0; mb < 4; mb++) {
                uint32_t off = ra[mb] * 128 + (((ks*2 + ca) ^ (ra[mb] & 7)) * 16);
                ldm4(ah[mb], base + off);
                ldm4(al[mb], base + SUBT + off);
            }
            #pragma unroll
            for (int nb = 0; nb < 4; nb++) {
                offb[nb] = rB[nb] * 128 + (((ks*2 + kcB) ^ (rB[nb] & 7)) * 16);
                ldm4(bb[nb], base + 2*SUBT + offb[nb]);
            }
            #pragma unroll
            for (int mb = 0; mb < 4; mb++)
                #pragma unroll
                for (int nb = 0; nb < 4; nb++) {
                    mma16816(acc[mb][nb*2],   ah[mb], bb[nb][0], bb[nb][1]);
                    mma16816(acc[mb][nb*2+1], ah[mb], bb[nb][2], bb[nb][3]);
                }
            #pragma unroll
            for (int mb = 0; mb < 4; mb++)
                #pragma unroll
                for (int nb = 0; nb < 4; nb++) {
                    mma16816(acc[mb][nb*2],   al[mb], bb[nb][0], bb[nb][1]);
                    mma16816(acc[mb][nb*2+1], al[mb], bb[nb][2], bb[nb][3]);
                }
            #pragma unroll
            for (int nb = 0; nb < 4; nb++)
                ldm4(bb[nb], base + 4*SUBT + offb[nb]);
            #pragma unroll
            for (int mb = 0; mb < 4; mb++)
                #pragma unroll
                for (int nb = 0; nb < 4; nb++) {
                    mma16816(acc[mb][nb*2],   ah[mb], bb[nb][0], bb[nb][1]);
                    mma16816(acc[mb][nb*2+1], ah[mb], bb[nb][2], bb[nb][3]);
                }
        }
    };

    load_stage(0, 0);
    CP_COMMIT();
    for (int c = 0; c < nch; c++) {
        if (c + 1 < nch) {
            load_stage((c + 1) & 1, (c + 1) << 6);
            CP_COMMIT();
            cp_wait<1>();
        } else {
            cp_wait<0>();
        }
        __syncthreads();
        compute(c & 1);
        __syncthreads();
    }

    const int gid = lane >> 2, qid = lane & 3;
    #pragma unroll
    for (int mb = 0; mb < 4; mb++) {
        #pragma unroll
        for (int nf = 0; nf < 8; nf++) {
            int n = n0 + warp_n + nf * 8 + qid * 2;
            #pragma unroll
            for (int hh = 0; hh < 2; hh++) {
                int m = m0 + warp_m + mb * 16 + gid + hh * 8;
                float vx = acc[mb][nf][hh*2];
                float vy = acc[mb][nf][hh*2 + 1];
                if (EPI & 1) { vx += bias[n]; vy += bias[n + 1]; }
                if (EPI & 2) { vx = gelu_exact(vx); vy = gelu_exact(vy); }
                size_t o = (size_t)m * Nout + n;
                if (SPLIT) {
                    uint32_t h, l;
                    split2(vx, vy, h, l);
                    *reinterpret_cast<uint32_t*>(Chi + o) = h;
                    *reinterpret_cast<uint32_t*>(Clo + o) = l;
                } else {
                    *reinterpret_cast<float2*>(C + o) = make_float2(vx, vy);
                }
            }
        }
    }
}

// ---------------------------------------------------------------------------
// Narrow layer GEMM (wo, ff2): bf16 3-pass, CTA 128x128, 256 thr, 8 warps
// (4M x 2N), warp tile 32x64, 3-stage pipeline. (R6 proven config.)
// ---------------------------------------------------------------------------
#define STGN (4*SUBT)                   // 64KB
#define GN_SMEM (3*STGN)                // 196608

template<int EPI>
__global__ __launch_bounds__(256, 1)
void gemm_n(const __nv_bfloat16* __restrict__ Ahi, const __nv_bfloat16* __restrict__ Alo,
            const __nv_bfloat16* __restrict__ Bhi, const __nv_bfloat16* __restrict__ Blo,
            const float* __restrict__ bias, const float* __restrict__ resid,
            float* __restrict__ C, int Nout, int K) {
    extern __shared__ char smem[];
    uint32_t sb = smem_u32(smem);
    const int tid = threadIdx.x;
    const int lane = tid & 31, wid = tid >> 5;
    const int m0 = blockIdx.y * 128, n0 = blockIdx.x * 128;
    const int warp_m = (wid >> 1) * 32;
    const int warp_n = (wid & 1) * 64;

    float acc[2][8][4];
    #pragma unroll
    for (int i = 0; i < 2; i++)
        #pragma unroll
        for (int j = 0; j < 8; j++)
            #pragma unroll
            for (int e = 0; e < 4; e++) acc[i][j][e] = 0.f;

    const int nch = K >> 6;

    auto load_stage = [&](int buf, int k0) {
        uint32_t base = sb + buf * STGN;
        const __nv_bfloat16* srcs[4] = {Ahi, Alo, Bhi, Blo};
        #pragma unroll
        for (int sub = 0; sub < 4; sub++) {
            const __nv_bfloat16* P = srcs[sub];
            int row0 = (sub < 2) ? m0 : n0;
            uint32_t dbase = base + sub * SUBT;
            #pragma unroll
            for (int it = 0; it < 4; it++) {
                int u = tid + it * 256;
                int row = u >> 3, c = u & 7;
                uint32_t dst = dbase + row * 128 + ((c ^ (row & 7)) * 16);
                cp_async16(dst, P + (size_t)(row0 + row) * K + k0 + c * 8, 16);
            }
        }
    };

    int ra[2];
    ra[0] = warp_m + (lane & 15);
    ra[1] = ra[0] + 16;
    const int ca = lane >> 4;
    int rB[4];
    #pragma unroll
    for (int nb = 0; nb < 4; nb++)
        rB[nb] = warp_n + nb * 16 + ((lane >> 4) & 1) * 8 + (lane & 7);
    const int kcB = (lane >> 3) & 1;

    auto compute = [&](int buf) {
        uint32_t base = sb + buf * STGN;
        #pragma unroll
        for (int ks = 0; ks < 4; ks++) {
            uint32_t ah[2][4], al[2][4], bh[4][4], bl[4][4];
            #pragma unroll
            for (int mb = 0; mb < 2; mb++) {
                uint32_t off = ra[mb] * 128 + (((ks*2 + ca) ^ (ra[mb] & 7)) * 16);
                ldm4(ah[mb], base + off);
                ldm4(al[mb], base + SUBT + off);
            }
            #pragma unroll
            for (int nb = 0; nb < 4; nb++) {
                uint32_t off = rB[nb] * 128 + (((ks*2 + kcB) ^ (rB[nb] & 7)) * 16);
                ldm4(bh[nb], base + 2*SUBT + off);
                ldm4(bl[nb], base + 3*SUBT + off);
            }
            #pragma unroll
            for (int mb = 0; mb < 2; mb++)
                #pragma unroll
                for (int nb = 0; nb < 4; nb++) {
                    mma16816(acc[mb][nb*2],   ah[mb], bh[nb][0], bh[nb][1]);
                    mma16816(acc[mb][nb*2+1], ah[mb], bh[nb][2], bh[nb][3]);
                }
            #pragma unroll
            for (int mb = 0; mb < 2; mb++)
                #pragma unroll
                for (int nb = 0; nb < 4; nb++) {
                    mma16816(acc[mb][nb*2],   al[mb], bh[nb][0], bh[nb][1]);
                    mma16816(acc[mb][nb*2+1], al[mb], bh[nb][2], bh[nb][3]);
                }
            #pragma unroll
            for (int mb = 0; mb < 2; mb++)
                #pragma unroll
                for (int nb = 0; nb < 4; nb++) {
                    mma16816(acc[mb][nb*2],   ah[mb], bl[nb][0], bl[nb][1]);
                    mma16816(acc[mb][nb*2+1], ah[mb], bl[nb][2], bl[nb][3]);
                }
        }
    };

    load_stage(0, 0);
    CP_COMMIT();
    if (nch > 1) { load_stage(1, 64); CP_COMMIT(); }
    for (int c = 0; c < nch; c++) {
        if (c == nch - 1) cp_wait<0>(); else cp_wait<1>();
        __syncthreads();
        compute(c % 3);
        int nx = c + 2;
        if (nx < nch) { load_stage(nx % 3, nx << 6); CP_COMMIT(); }
    }

    const int gid = lane >> 2, qid = lane & 3;
    #pragma unroll
    for (int mb = 0; mb < 2; mb++) {
        #pragma unroll
        for (int nf = 0; nf < 8; nf++) {
            int n = n0 + warp_n + nf * 8 + qid * 2;
            #pragma unroll
            for (int hh = 0; hh < 2; hh++) {
                int m = m0 + warp_m + mb * 16 + gid + hh * 8;
                float vx = acc[mb][nf][hh*2];
                float vy = acc[mb][nf][hh*2 + 1];
                if (EPI & 1) { vx += bias[n]; vy += bias[n + 1]; }
                size_t o = (size_t)m * Nout + n;
                if (EPI & 4) {
                    float2 r = *reinterpret_cast<const float2*>(resid + o);
                    vx += r.x; vy += r.y;
                }
                *reinterpret_cast<float2*>(C + o) = make_float2(vx, vy);
            }
        }
    }
}

// ---------------------------------------------------------------------------
// LM-head GEMM: fp16 1-pass, CTA 128x256, 8 warps (2x4), warp tile 64x64.
// ---------------------------------------------------------------------------
#define STGL (3*SUBT)                   // 48KB
#define GL_SMEM (3*STGL)                // 147456

__global__ __launch_bounds__(256, 1)
void gemm_lm(const __half* __restrict__ A, const __half* __restrict__ B,
             float* __restrict__ C, int Nout, int K) {
    extern __shared__ char smem[];
    uint32_t sb = smem_u32(smem);
    const int tid = threadIdx.x;
    const int lane = tid & 31, wid = tid >> 5;
    const int m0 = blockIdx.y * 128, n0 = blockIdx.x * 256;
    const int warp_m = (wid >> 2) * 64;
    const int warp_n = (wid & 3) * 64;

    float acc[4][8][4];
    #pragma unroll
    for (int i = 0; i < 4; i++)
        #pragma unroll
        for (int j = 0; j < 8; j++)
            #pragma unroll
            for (int e = 0; e < 4; e++) acc[i][j][e] = 0.f;

    const int nch = K >> 6;   // 8

    auto load_stage = [&](int buf, int k0) {
        uint32_t base = sb + buf * STGL;
        #pragma unroll
        for (int it = 0; it < 4; it++) {
            int u = tid + it * 256;
            int row = u >> 3, c = u & 7;
            uint32_t dst = base + row * 128 + ((c ^ (row & 7)) * 16);
            cp_async16(dst, A + (size_t)(m0 + row) * K + k0 + c * 8, 16);
        }
        #pragma unroll
        for (int it = 0; it < 8; it++) {
            int u = tid + it * 256;
            int row = u >> 3, c = u & 7;
            uint32_t dst = base + SUBT + row * 128 + ((c ^ (row & 7)) * 16);
            const __half* g = B + (size_t)(n0 + row) * K + k0 + c * 8;
            int sz = 16;
            if (n0 + row >= Nout) { g = B; sz = 0; }
            cp_async16(dst, g, sz);
        }
    };

    int ra[4];
    #pragma unroll
    for (int mb = 0; mb < 4; mb++) ra[mb] = warp_m + mb * 16 + (lane & 15);
    const int ca = lane >> 4;
    int rB[4];
    #pragma unroll
    for (int nb = 0; nb < 4; nb++)
        rB[nb] = warp_n + nb * 16 + ((lane >> 4) & 1) * 8 + (lane & 7);
    const int kcB = (lane >> 3) & 1;

    auto compute = [&](int buf) {
        uint32_t base = sb + buf * STGL;
        #pragma unroll
        for (int ks = 0; ks < 4; ks++) {
            uint32_t a[4][4], b[4][4];
            #pragma unroll
            for (int mb = 0; mb < 4; mb++) {
                uint32_t off = ra[mb] * 128 + (((ks*2 + ca) ^ (ra[mb] & 7)) * 16);
                ldm4(a[mb], base + off);
            }
            #pragma unroll
            for (int nb = 0; nb < 4; nb++) {
                uint32_t off = rB[nb] * 128 + (((ks*2 + kcB) ^ (rB[nb] & 7)) * 16);
                ldm4(b[nb], base + SUBT + off);
            }
            #pragma unroll
            for (int mb = 0; mb < 4; mb++)
                #pragma unroll
                for (int nb = 0; nb < 4; nb++) {
                    mma16816h(acc[mb][nb*2],   a[mb], b[nb][0], b[nb][1]);
                    mma16816h(acc[mb][nb*2+1], a[mb], b[nb][2], b[nb][3]);
                }
        }
    };

    load_stage(0, 0);
    CP_COMMIT();
    load_stage(1, 64);
    CP_COMMIT();
    for (int c = 0; c < nch; c++) {
        if (c == nch - 1) cp_wait<0>(); else cp_wait<1>();
        __syncthreads();
        compute(c % 3);
        int nx = c + 2;
        if (nx < nch) { load_stage(nx % 3, nx << 6); CP_COMMIT(); }
    }

    const int gid = lane >> 2, qid = lane & 3;
    #pragma unroll
    for (int mb = 0; mb < 4; mb++) {
        #pragma unroll
        for (int nf = 0; nf < 8; nf++) {
            int n = n0 + warp_n + nf * 8 + qid * 2;
            #pragma unroll
            for (int hh = 0; hh < 2; hh++) {
                int m = m0 + warp_m + mb * 16 + gid + hh * 8;
                float vx = acc[mb][nf][hh*2];
                float vy = acc[mb][nf][hh*2 + 1];
                size_t o = (size_t)m * Nout + n;
                if (n < Nout)     C[o]     = vx;
                if (n + 1 < Nout) C[o + 1] = vy;
            }
        }
    }
}

// ---------------------------------------------------------------------------
// Causal flash attention (fp32): 4 partial sums break the serial FMA chain;
// heavy tiles scheduled first (reversed blockIdx.x).
// ---------------------------------------------------------------------------
__global__ __launch_bounds__(128)
void attn_kernel(const float* __restrict__ qkv,
                 __nv_bfloat16* __restrict__ ctx_hi,
                 __nv_bfloat16* __restrict__ ctx_lo) {
    __shared__ float4 ks[64][16];
    __shared__ float4 vs[64][16];
    int bh = blockIdx.y;
    int b = bh >> 3, h = bh & 7;
    int tile = gridDim.x - 1 - blockIdx.x;       // heavy tiles first
    int r = tile * 128 + threadIdx.x;

    const float* qp = qkv + ((size_t)(b * SS + r) * QKVD + h * DH);
    float4 qf[16];
    #pragma unroll
    for (int c = 0; c < 16; c++) qf[c] = reinterpret_cast<const float4*>(qp)[c];

    float4 acc[16];
    #pragma unroll
    for (int c = 0; c < 16; c++) acc[c] = make_float4(0.f, 0.f, 0.f, 0.f);
    float m = -1e30f, l = 0.f;

    int ntiles = (tile * 128) / 64 + 2;
    for (int t = 0; t < ntiles; t++) {
        int kbase = t * 64;
        #pragma unroll
        for (int i = 0; i < 8; i++) {
            int idx = threadIdx.x + i * 128;
            int j = idx >> 4, c = idx & 15;
            size_t off = (size_t)(b * SS + kbase + j) * QKVD + h * DH;
            ks[j][c] = reinterpret_cast<const float4*>(qkv + off + DD)[c];
            vs[j][c] = reinterpret_cast<const float4*>(qkv + off + 2*DD)[c];
        }
        __syncthreads();
        int jmax = r - kbase + 1;
        if (jmax > 64) jmax = 64;
        for (int j = 0; j < jmax; j++) {
            // 4 independent partial sums -> dep chain 16 instead of 64
            float s0 = 0.f, s1 = 0.f, s2 = 0.f, s3 = 0.f;
            #pragma unroll
            for (int c = 0; c < 16; c++) {
                float4 kk = ks[j][c];
                s0 += qf[c].x * kk.x;
                s1 += qf[c].y * kk.y;
                s2 += qf[c].z * kk.z;
                s3 += qf[c].w * kk.w;
            }
            float s = ((s0 + s1) + (s2 + s3)) * 0.125f;
            if (s > m) {
                float sc = __expf(m - s);
                l *= sc;
                #pragma unroll
                for (int c = 0; c < 16; c++) {
                    acc[c].x *= sc; acc[c].y *= sc; acc[c].z *= sc; acc[c].w *= sc;
                }
                m = s;
            }
            float p = __expf(s - m);
            l += p;
            #pragma unroll
            for (int c = 0; c < 16; c++) {
                float4 vv = vs[j][c];
                acc[c].x += p*vv.x; acc[c].y += p*vv.y;
                acc[c].z += p*vv.z; acc[c].w += p*vv.w;
            }
        }
        __syncthreads();
    }

    float inv = 1.0f / l;
    size_t off = (size_t)(b * SS + r) * DD + h * DH;
    #pragma unroll
    for (int c = 0; c < 16; c++) {
        float4 o;
        o.x = acc[c].x*inv; o.y = acc[c].y*inv; o.z = acc[c].z*inv; o.w = acc[c].w*inv;
        uint2 hh, ll;
        split4(o, hh, ll);
        reinterpret_cast<uint2*>(ctx_hi + off)[c] = hh;
        reinterpret_cast<uint2*>(ctx_lo + off)[c] = ll;
    }
}

// ---------------------------------------------------------------------------
// Host launch
// ---------------------------------------------------------------------------
extern "C" void kernel_launch(void* const* d_in, const int* in_sizes, int n_in,
                              void* d_out, int out_size) {
    const int*   ids   = (const int*)  d_in[0];
    const float* emb   = (const float*)d_in[1];
    const float* pe    = (const float*)d_in[2];
    const float* wq    = (const float*)d_in[3];
    const float* wk    = (const float*)d_in[4];
    const float* wv    = (const float*)d_in[5];
    const float* wo    = (const float*)d_in[6];
    const float* wo_b  = (const float*)d_in[7];
    const float* w1    = (const float*)d_in[8];
    const float* b1    = (const float*)d_in[9];
    const float* w2    = (const float*)d_in[10];
    const float* b2    = (const float*)d_in[11];
    const float* ln1_g = (const float*)d_in[12];
    const float* ln1_b = (const float*)d_in[13];
    const float* ln2_g = (const float*)d_in[14];
    const float* ln2_b = (const float*)d_in[15];
    const float* lnf_g = (const float*)d_in[16];
    const float* lnf_b = (const float*)d_in[17];
    float* out = (float*)d_out;

    float *x, *qkv;
    __nv_bfloat16 *h_hi, *h_lo, *ctx_hi, *ctx_lo, *ff_hi, *ff_lo;
    __nv_bfloat16 *wqkvT_hi, *wqkvT_lo, *woT_hi, *woT_lo;
    __nv_bfloat16 *w1T_hi, *w1T_lo, *w2T_hi, *w2T_lo;
    __half *hf, *embH;
    cudaGetSymbolAddress((void**)&x, g_x);
    cudaGetSymbolAddress((void**)&qkv, g_qkv);
    cudaGetSymbolAddress((void**)&h_hi, g_h_hi);
    cudaGetSymbolAddress((void**)&h_lo, g_h_lo);
    cudaGetSymbolAddress((void**)&ctx_hi, g_ctx_hi);
    cudaGetSymbolAddress((void**)&ctx_lo, g_ctx_lo);
    cudaGetSymbolAddress((void**)&ff_hi, g_ff_hi);
    cudaGetSymbolAddress((void**)&ff_lo, g_ff_lo);
    cudaGetSymbolAddress((void**)&wqkvT_hi, g_wqkvT_hi);
    cudaGetSymbolAddress((void**)&wqkvT_lo, g_wqkvT_lo);
    cudaGetSymbolAddress((void**)&woT_hi, g_woT_hi);
    cudaGetSymbolAddress((void**)&woT_lo, g_woT_lo);
    cudaGetSymbolAddress((void**)&w1T_hi, g_w1T_hi);
    cudaGetSymbolAddress((void**)&w1T_lo, g_w1T_lo);
    cudaGetSymbolAddress((void**)&w2T_hi, g_w2T_hi);
    cudaGetSymbolAddress((void**)&w2T_lo, g_w2T_lo);
    cudaGetSymbolAddress((void**)&hf, g_hf);
    cudaGetSymbolAddress((void**)&embH, g_embH);

    cudaFuncSetAttribute(gemm_w<0, false>, cudaFuncAttributeMaxDynamicSharedMemorySize, GW_SMEM);
    cudaFuncSetAttribute(gemm_w<3, true >, cudaFuncAttributeMaxDynamicSharedMemorySize, GW_SMEM);
    cudaFuncSetAttribute(gemm_n<5>, cudaFuncAttributeMaxDynamicSharedMemorySize, GN_SMEM);
    cudaFuncSetAttribute(gemm_lm, cudaFuncAttributeMaxDynamicSharedMemorySize, GL_SMEM);

    // weight conversions
    dim3 cb(32, 8);
    conv_wT<<<dim3(DD/32, DD/32), cb>>>(wq, wqkvT_hi,            wqkvT_lo,            DD, DD);
    conv_wT<<<dim3(DD/32, DD/32), cb>>>(wk, wqkvT_hi + DD*DD,    wqkvT_lo + DD*DD,    DD, DD);
    conv_wT<<<dim3(DD/32, DD/32), cb>>>(wv, wqkvT_hi + 2*DD*DD,  wqkvT_lo + 2*DD*DD,  DD, DD);
    conv_wT<<<dim3(DD/32, DD/32), cb>>>(wo, woT_hi, woT_lo, DD, DD);
    conv_wT<<<dim3(FFD/32, DD/32), cb>>>(w1, w1T_hi, w1T_lo, DD, FFD);
    conv_wT<<<dim3(DD/32, FFD/32), cb>>>(w2, w2T_hi, w2T_lo, FFD, DD);
    {
        int n4 = VV * DD / 4;
        conv_half4<<<(n4 + 255) / 256, 256>>>(emb, embH, n4);
    }

    embed_kernel<<<NN, 128>>>(ids, emb, pe, x);

    dim3 gQKV(QKVD/256, NN/128);     // (6, 32)
    dim3 gProj(DD/128, NN/128);      // (4, 32)
    dim3 gFF1(FFD/256, NN/128);      // (8, 32)
    dim3 gAttn(SS/128, BB*HH);       // (8, 32)

    for (int layer = 0; layer < NLAYERS; layer++) {
        ln_kernel<0><<<NN, 128>>>(x, (uint32_t*)h_hi, (uint32_t*)h_lo, ln1_g, ln1_b);
        gemm_w<0, false><<<gQKV, 256, GW_SMEM>>>(
            h_hi, h_lo, wqkvT_hi, wqkvT_lo, nullptr,
            qkv, nullptr, nullptr, QKVD, DD);
        attn_kernel<<<gAttn, 128>>>(qkv, ctx_hi, ctx_lo);
        gemm_n<5><<<gProj, 256, GN_SMEM>>>(
            ctx_hi, ctx_lo, woT_hi, woT_lo, wo_b, x, x, DD, DD);
        ln_kernel<0><<<NN, 128>>>(x, (uint32_t*)h_hi, (uint32_t*)h_lo, ln2_g, ln2_b);
        gemm_w<3, true><<<gFF1, 256, GW_SMEM>>>(
            h_hi, h_lo, w1T_hi, w1T_lo, b1,
            nullptr, ff_hi, ff_lo, FFD, DD);
        gemm_n<5><<<gProj, 256, GN_SMEM>>>(
            ff_hi, ff_lo, w2T_hi, w2T_lo, b2, x, x, DD, FFD);
    }

    ln_kernel<2><<<NN, 128>>>(x, (uint32_t*)hf, nullptr, lnf_g, lnf_b);

    dim3 gLM((VV + 255) / 256, NN / 128);   // (197, 32)
    gemm_lm<<<gLM, 256, GL_SMEM>>>(hf, embH, out, VV, DD);
}

// round 9
// speedup vs baseline: 4.8025x; 1.7934x over previous
#include <cuda_runtime.h>
#include <cuda_bf16.h>
#include <cuda_fp16.h>
#include <math.h>
#include <stdint.h>

// Problem constants
#define BB 4
#define SS 1024
#define NN (BB*SS)      // 4096 tokens
#define DD 512
#define HH 8
#define DH 64
#define FFD 2048
#define VV 50257
#define NLAYERS 6
#define QKVD 1536       // fused qkv width

// ---------------------------------------------------------------------------
// Scratch (allocation-free: __device__ globals)
// ---------------------------------------------------------------------------
__device__ float g_x[NN*DD];
__device__ __nv_bfloat16 g_h_hi[NN*DD],  g_h_lo[NN*DD];
__device__ __half g_qkvh[NN*QKVD];
__device__ __nv_bfloat16 g_ctx_hi[NN*DD], g_ctx_lo[NN*DD];
__device__ __nv_bfloat16 g_ff_hi[NN*FFD], g_ff_lo[NN*FFD];
// transposed bf16 weights [N,K]
__device__ __nv_bfloat16 g_wqkvT_hi[3*DD*DD], g_wqkvT_lo[3*DD*DD];
__device__ __nv_bfloat16 g_woT_hi[DD*DD],     g_woT_lo[DD*DD];
__device__ __nv_bfloat16 g_w1T_hi[FFD*DD],    g_w1T_lo[FFD*DD];
__device__ __nv_bfloat16 g_w2T_hi[DD*FFD],    g_w2T_lo[DD*FFD];
// LM head (fp16 1-pass)
__device__ __half g_hf[NN*DD];
__device__ __half g_embH[VV*DD];

// ---------------------------------------------------------------------------
// Helpers
// ---------------------------------------------------------------------------
__device__ __forceinline__ uint32_t smem_u32(const void* p) {
    uint32_t a;
    asm("{ .reg .u64 t; cvta.to.shared.u64 t, %1; cvt.u32.u64 %0, t; }"
        : "=r"(a) : "l"(p));
    return a;
}

__device__ __forceinline__ void ldm4(uint32_t* r, uint32_t addr) {
    asm volatile("ldmatrix.sync.aligned.m8n8.x4.shared.b16 {%0,%1,%2,%3}, [%4];"
                 : "=r"(r[0]), "=r"(r[1]), "=r"(r[2]), "=r"(r[3]) : "r"(addr));
}
__device__ __forceinline__ void ldm4t(uint32_t* r, uint32_t addr) {
    asm volatile("ldmatrix.sync.aligned.m8n8.x4.trans.shared.b16 {%0,%1,%2,%3}, [%4];"
                 : "=r"(r[0]), "=r"(r[1]), "=r"(r[2]), "=r"(r[3]) : "r"(addr));
}

__device__ __forceinline__ void mma16816(float* c, const uint32_t* a,
                                         uint32_t b0, uint32_t b1) {
    asm volatile(
        "mma.sync.aligned.m16n8k16.row.col.f32.bf16.bf16.f32 "
        "{%0,%1,%2,%3}, {%4,%5,%6,%7}, {%8,%9}, {%0,%1,%2,%3};"
        : "+f"(c[0]), "+f"(c[1]), "+f"(c[2]), "+f"(c[3])
        : "r"(a[0]), "r"(a[1]), "r"(a[2]), "r"(a[3]), "r"(b0), "r"(b1));
}
__device__ __forceinline__ void mma16816h(float* c, const uint32_t* a,
                                          uint32_t b0, uint32_t b1) {
    asm volatile(
        "mma.sync.aligned.m16n8k16.row.col.f32.f16.f16.f32 "
        "{%0,%1,%2,%3}, {%4,%5,%6,%7}, {%8,%9}, {%0,%1,%2,%3};"
        : "+f"(c[0]), "+f"(c[1]), "+f"(c[2]), "+f"(c[3])
        : "r"(a[0]), "r"(a[1]), "r"(a[2]), "r"(a[3]), "r"(b0), "r"(b1));
}

__device__ __forceinline__ void cp_async16(uint32_t dst, const void* src, int szbytes) {
    asm volatile("cp.async.cg.shared.global [%0], [%1], 16, %2;"
                 :: "r"(dst), "l"(src), "r"(szbytes));
}
#define CP_COMMIT() asm volatile("cp.async.commit_group;" ::: "memory")
template<int N>
__device__ __forceinline__ void cp_wait() {
    asm volatile("cp.async.wait_group %0;" :: "n"(N) : "memory");
}

// bf16 hi/lo split helpers
__device__ __forceinline__ void split2(float x, float y, uint32_t& h, uint32_t& l) {
    __nv_bfloat16 h0 = __float2bfloat16_rn(x);
    __nv_bfloat16 h1 = __float2bfloat16_rn(y);
    __nv_bfloat16 l0 = __float2bfloat16_rn(x - __bfloat162float(h0));
    __nv_bfloat16 l1 = __float2bfloat16_rn(y - __bfloat162float(h1));
    h = (uint32_t)__bfloat16_as_ushort(h0) | ((uint32_t)__bfloat16_as_ushort(h1) << 16);
    l = (uint32_t)__bfloat16_as_ushort(l0) | ((uint32_t)__bfloat16_as_ushort(l1) << 16);
}
__device__ __forceinline__ void split4(float4 v, uint2& h, uint2& l) {
    split2(v.x, v.y, h.x, l.x);
    split2(v.z, v.w, h.y, l.y);
}
__device__ __forceinline__ uint32_t packh2(float x, float y) {
    __half2 t = __floats2half2_rn(x, y);
    return *reinterpret_cast<uint32_t*>(&t);
}

__device__ __forceinline__ float gelu_exact(float v) {
    return 0.5f * v * (1.0f + erff(v * 0.70710678118654752f));
}

// ---------------------------------------------------------------------------
// Weight conversion: W [K,N] fp32 -> hi/lo [N,K] bf16 (transpose)
// ---------------------------------------------------------------------------
__global__ void conv_wT(const float* __restrict__ W, __nv_bfloat16* __restrict__ hi,
                        __nv_bfloat16* __restrict__ lo, int K, int N) {
    __shared__ float t[32][33];
    int n0 = blockIdx.x * 32, k0 = blockIdx.y * 32;
    int tx = threadIdx.x, ty = threadIdx.y;
    #pragma unroll
    for (int r = 0; r < 4; r++)
        t[ty + r*8][tx] = W[(size_t)(k0 + ty + r*8) * N + n0 + tx];
    __syncthreads();
    #pragma unroll
    for (int r = 0; r < 4; r++) {
        float v = t[tx][ty + r*8];
        __nv_bfloat16 h = __float2bfloat16_rn(v);
        size_t o = (size_t)(n0 + ty + r*8) * K + k0 + tx;
        hi[o] = h;
        lo[o] = __float2bfloat16_rn(v - __bfloat162float(h));
    }
}

// Elementwise fp32 -> fp16
__global__ void conv_half4(const float* __restrict__ src,
                           __half* __restrict__ dst, int n4) {
    int i = blockIdx.x * 256 + threadIdx.x;
    if (i >= n4) return;
    float4 v = reinterpret_cast<const float4*>(src)[i];
    uint2 o;
    o.x = packh2(v.x, v.y);
    o.y = packh2(v.z, v.w);
    reinterpret_cast<uint2*>(dst)[i] = o;
}

// ---------------------------------------------------------------------------
// Embedding
// ---------------------------------------------------------------------------
__global__ void embed_kernel(const int* __restrict__ ids,
                             const float* __restrict__ emb,
                             const float* __restrict__ pe,
                             float* __restrict__ x) {
    int n = blockIdx.x;
    int tid = threadIdx.x;
    int id = ids[n];
    int s = n & (SS - 1);
    const float sq = 22.62741699796952f;
    float4 e = reinterpret_cast<const float4*>(emb + (size_t)id * DD)[tid];
    float4 p = reinterpret_cast<const float4*>(pe + (size_t)s * DD)[tid];
    float4 o;
    o.x = e.x * sq + p.x; o.y = e.y * sq + p.y;
    o.z = e.z * sq + p.z; o.w = e.w * sq + p.w;
    reinterpret_cast<float4*>(x + (size_t)n * DD)[tid] = o;
}

// ---------------------------------------------------------------------------
// LayerNorm.  MODE 0: bf16 hi/lo split.  MODE 2: single fp16.
// ---------------------------------------------------------------------------
template<int MODE>
__global__ void ln_kernel(const float* __restrict__ in,
                          uint32_t* __restrict__ out_hi,
                          uint32_t* __restrict__ out_lo,
                          const float* __restrict__ g, const float* __restrict__ b) {
    int row = blockIdx.x;
    int tid = threadIdx.x;    // 128
    float4 v = reinterpret_cast<const float4*>(in + (size_t)row * DD)[tid];
    float s = v.x + v.y + v.z + v.w;
    float ss = v.x*v.x + v.y*v.y + v.z*v.z + v.w*v.w;
    #pragma unroll
    for (int o = 16; o > 0; o >>= 1) {
        s  += __shfl_xor_sync(0xffffffffu, s, o);
        ss += __shfl_xor_sync(0xffffffffu, ss, o);
    }
    __shared__ float rs[4], rss[4];
    int warp = tid >> 5;
    if ((tid & 31) == 0) { rs[warp] = s; rss[warp] = ss; }
    __syncthreads();
    float mean = (rs[0]+rs[1]+rs[2]+rs[3]) * (1.0f/DD);
    float var  = (rss[0]+rss[1]+rss[2]+rss[3]) * (1.0f/DD) - mean*mean;
    float rstd = rsqrtf(var + 1e-5f);
    float4 gg = reinterpret_cast<const float4*>(g)[tid];
    float4 bb = reinterpret_cast<const float4*>(b)[tid];
    float4 o;
    o.x = (v.x - mean)*rstd*gg.x + bb.x;
    o.y = (v.y - mean)*rstd*gg.y + bb.y;
    o.z = (v.z - mean)*rstd*gg.z + bb.z;
    o.w = (v.w - mean)*rstd*gg.w + bb.w;
    if (MODE == 0) {
        uint2 h, l;
        split4(o, h, l);
        reinterpret_cast<uint2*>(out_hi)[(size_t)row * (DD/4) + tid] = h;
        reinterpret_cast<uint2*>(out_lo)[(size_t)row * (DD/4) + tid] = l;
    } else {
        uint2 hh;
        hh.x = packh2(o.x, o.y);
        hh.y = packh2(o.z, o.w);
        reinterpret_cast<uint2*>(out_hi)[(size_t)row * (DD/4) + tid] = hh;
    }
}

#define SUBT 16384                      // 128 rows x 128B

// ---------------------------------------------------------------------------
// Wide layer GEMM (qkv, ff1): bf16 3-pass, CTA 128x256, 256 thr, 8 warps
// (2M x 4N), warp tile 64x64. OUT: 0=f32, 1=bf16 split, 2=f16 single.
// ---------------------------------------------------------------------------
#define STGW (6*SUBT)                   // 96KB
#define GW_SMEM (2*STGW)                // 196608

template<int EPI, int OUT>
__global__ __launch_bounds__(256, 1)
void gemm_w(const __nv_bfloat16* __restrict__ Ahi, const __nv_bfloat16* __restrict__ Alo,
            const __nv_bfloat16* __restrict__ Bhi, const __nv_bfloat16* __restrict__ Blo,
            const float* __restrict__ bias,
            float* __restrict__ C, __nv_bfloat16* __restrict__ Chi,
            __nv_bfloat16* __restrict__ Clo, __half* __restrict__ Ch,
            int Nout, int K) {
    extern __shared__ char smem[];
    uint32_t sb = smem_u32(smem);
    const int tid = threadIdx.x;
    const int lane = tid & 31, wid = tid >> 5;
    const int m0 = blockIdx.y * 128, n0 = blockIdx.x * 256;
    const int warp_m = (wid >> 2) * 64;
    const int warp_n = (wid & 3) * 64;

    float acc[4][8][4];
    #pragma unroll
    for (int i = 0; i < 4; i++)
        #pragma unroll
        for (int j = 0; j < 8; j++)
            #pragma unroll
            for (int e = 0; e < 4; e++) acc[i][j][e] = 0.f;

    const int nch = K >> 6;   // 8

    auto load_stage = [&](int buf, int k0) {
        uint32_t base = sb + buf * STGW;
        #pragma unroll
        for (int t = 0; t < 2; t++) {
            const __nv_bfloat16* P = t ? Alo : Ahi;
            uint32_t dbase = base + t * SUBT;
            #pragma unroll
            for (int it = 0; it < 4; it++) {
                int u = tid + it * 256;
                int row = u >> 3, c = u & 7;
                uint32_t dst = dbase + row * 128 + ((c ^ (row & 7)) * 16);
                cp_async16(dst, P + (size_t)(m0 + row) * K + k0 + c * 8, 16);
            }
        }
        #pragma unroll
        for (int t = 0; t < 2; t++) {
            const __nv_bfloat16* P = t ? Blo : Bhi;
            uint32_t dbase = base + 2*SUBT + t * 2*SUBT;
            #pragma unroll
            for (int it = 0; it < 8; it++) {
                int u = tid + it * 256;
                int row = u >> 3, c = u & 7;
                uint32_t dst = dbase + row * 128 + ((c ^ (row & 7)) * 16);
                cp_async16(dst, P + (size_t)(n0 + row) * K + k0 + c * 8, 16);
            }
        }
    };

    int ra[4];
    #pragma unroll
    for (int mb = 0; mb < 4; mb++) ra[mb] = warp_m + mb * 16 + (lane & 15);
    const int ca = lane >> 4;
    int rB[4];
    #pragma unroll
    for (int nb = 0; nb < 4; nb++)
        rB[nb] = warp_n + nb * 16 + ((lane >> 4) & 1) * 8 + (lane & 7);
    const int kcB = (lane >> 3) & 1;

    auto compute = [&](int buf) {
        uint32_t base = sb + buf * STGW;
        #pragma unroll
        for (int ks = 0; ks < 4; ks++) {
            uint32_t ah[4][4], al[4][4], bb[4][4];
            uint32_t offb[4];
            #pragma unroll
            for (int mb = 0; mb < 4; mb++) {
                uint32_t off = ra[mb] * 128 + (((ks*2 + ca) ^ (ra[mb] & 7)) * 16);
                ldm4(ah[mb], base + off);
                ldm4(al[mb], base + SUBT + off);
            }
            #pragma unroll
            for (int nb = 0; nb < 4; nb++) {
                offb[nb] = rB[nb] * 128 + (((ks*2 + kcB) ^ (rB[nb] & 7)) * 16);
                ldm4(bb[nb], base + 2*SUBT + offb[nb]);
            }
            #pragma unroll
            for (int mb = 0; mb < 4; mb++)
                #pragma unroll
                for (int nb = 0; nb < 4; nb++) {
                    mma16816(acc[mb][nb*2],   ah[mb], bb[nb][0], bb[nb][1]);
                    mma16816(acc[mb][nb*2+1], ah[mb], bb[nb][2], bb[nb][3]);
                }
            #pragma unroll
            for (int mb = 0; mb < 4; mb++)
                #pragma unroll
                for (int nb = 0; nb < 4; nb++) {
                    mma16816(acc[mb][nb*2],   al[mb], bb[nb][0], bb[nb][1]);
                    mma16816(acc[mb][nb*2+1], al[mb], bb[nb][2], bb[nb][3]);
                }
            #pragma unroll
            for (int nb = 0; nb < 4; nb++)
                ldm4(bb[nb], base + 4*SUBT + offb[nb]);
            #pragma unroll
            for (int mb = 0; mb < 4; mb++)
                #pragma unroll
                for (int nb = 0; nb < 4; nb++) {
                    mma16816(acc[mb][nb*2],   ah[mb], bb[nb][0], bb[nb][1]);
                    mma16816(acc[mb][nb*2+1], ah[mb], bb[nb][2], bb[nb][3]);
                }
        }
    };

    load_stage(0, 0);
    CP_COMMIT();
    for (int c = 0; c < nch; c++) {
        if (c + 1 < nch) {
            load_stage((c + 1) & 1, (c + 1) << 6);
            CP_COMMIT();
            cp_wait<1>();
        } else {
            cp_wait<0>();
        }
        __syncthreads();
        compute(c & 1);
        __syncthreads();
    }

    const int gid = lane >> 2, qid = lane & 3;
    #pragma unroll
    for (int mb = 0; mb < 4; mb++) {
        #pragma unroll
        for (int nf = 0; nf < 8; nf++) {
            int n = n0 + warp_n + nf * 8 + qid * 2;
            #pragma unroll
            for (int hh = 0; hh < 2; hh++) {
                int m = m0 + warp_m + mb * 16 + gid + hh * 8;
                float vx = acc[mb][nf][hh*2];
                float vy = acc[mb][nf][hh*2 + 1];
                if (EPI & 1) { vx += bias[n]; vy += bias[n + 1]; }
                if (EPI & 2) { vx = gelu_exact(vx); vy = gelu_exact(vy); }
                size_t o = (size_t)m * Nout + n;
                if (OUT == 1) {
                    uint32_t h, l;
                    split2(vx, vy, h, l);
                    *reinterpret_cast<uint32_t*>(Chi + o) = h;
                    *reinterpret_cast<uint32_t*>(Clo + o) = l;
                } else if (OUT == 2) {
                    *reinterpret_cast<uint32_t*>(Ch + o) = packh2(vx, vy);
                } else {
                    *reinterpret_cast<float2*>(C + o) = make_float2(vx, vy);
                }
            }
        }
    }
}

// ---------------------------------------------------------------------------
// Narrow layer GEMM (wo, ff2): bf16 3-pass, CTA 128x128, 256 thr, 8 warps
// (4M x 2N), warp tile 32x64, 3-stage pipeline.
// ---------------------------------------------------------------------------
#define STGN (4*SUBT)                   // 64KB
#define GN_SMEM (3*STGN)                // 196608

template<int EPI>
__global__ __launch_bounds__(256, 1)
void gemm_n(const __nv_bfloat16* __restrict__ Ahi, const __nv_bfloat16* __restrict__ Alo,
            const __nv_bfloat16* __restrict__ Bhi, const __nv_bfloat16* __restrict__ Blo,
            const float* __restrict__ bias, const float* __restrict__ resid,
            float* __restrict__ C, int Nout, int K) {
    extern __shared__ char smem[];
    uint32_t sb = smem_u32(smem);
    const int tid = threadIdx.x;
    const int lane = tid & 31, wid = tid >> 5;
    const int m0 = blockIdx.y * 128, n0 = blockIdx.x * 128;
    const int warp_m = (wid >> 1) * 32;
    const int warp_n = (wid & 1) * 64;

    float acc[2][8][4];
    #pragma unroll
    for (int i = 0; i < 2; i++)
        #pragma unroll
        for (int j = 0; j < 8; j++)
            #pragma unroll
            for (int e = 0; e < 4; e++) acc[i][j][e] = 0.f;

    const int nch = K >> 6;

    auto load_stage = [&](int buf, int k0) {
        uint32_t base = sb + buf * STGN;
        const __nv_bfloat16* srcs[4] = {Ahi, Alo, Bhi, Blo};
        #pragma unroll
        for (int sub = 0; sub < 4; sub++) {
            const __nv_bfloat16* P = srcs[sub];
            int row0 = (sub < 2) ? m0 : n0;
            uint32_t dbase = base + sub * SUBT;
            #pragma unroll
            for (int it = 0; it < 4; it++) {
                int u = tid + it * 256;
                int row = u >> 3, c = u & 7;
                uint32_t dst = dbase + row * 128 + ((c ^ (row & 7)) * 16);
                cp_async16(dst, P + (size_t)(row0 + row) * K + k0 + c * 8, 16);
            }
        }
    };

    int ra[2];
    ra[0] = warp_m + (lane & 15);
    ra[1] = ra[0] + 16;
    const int ca = lane >> 4;
    int rB[4];
    #pragma unroll
    for (int nb = 0; nb < 4; nb++)
        rB[nb] = warp_n + nb * 16 + ((lane >> 4) & 1) * 8 + (lane & 7);
    const int kcB = (lane >> 3) & 1;

    auto compute = [&](int buf) {
        uint32_t base = sb + buf * STGN;
        #pragma unroll
        for (int ks = 0; ks < 4; ks++) {
            uint32_t ah[2][4], al[2][4], bh[4][4], bl[4][4];
            #pragma unroll
            for (int mb = 0; mb < 2; mb++) {
                uint32_t off = ra[mb] * 128 + (((ks*2 + ca) ^ (ra[mb] & 7)) * 16);
                ldm4(ah[mb], base + off);
                ldm4(al[mb], base + SUBT + off);
            }
            #pragma unroll
            for (int nb = 0; nb < 4; nb++) {
                uint32_t off = rB[nb] * 128 + (((ks*2 + kcB) ^ (rB[nb] & 7)) * 16);
                ldm4(bh[nb], base + 2*SUBT + off);
                ldm4(bl[nb], base + 3*SUBT + off);
            }
            #pragma unroll
            for (int mb = 0; mb < 2; mb++)
                #pragma unroll
                for (int nb = 0; nb < 4; nb++) {
                    mma16816(acc[mb][nb*2],   ah[mb], bh[nb][0], bh[nb][1]);
                    mma16816(acc[mb][nb*2+1], ah[mb], bh[nb][2], bh[nb][3]);
                }
            #pragma unroll
            for (int mb = 0; mb < 2; mb++)
                #pragma unroll
                for (int nb = 0; nb < 4; nb++) {
                    mma16816(acc[mb][nb*2],   al[mb], bh[nb][0], bh[nb][1]);
                    mma16816(acc[mb][nb*2+1], al[mb], bh[nb][2], bh[nb][3]);
                }
            #pragma unroll
            for (int mb = 0; mb < 2; mb++)
                #pragma unroll
                for (int nb = 0; nb < 4; nb++) {
                    mma16816(acc[mb][nb*2],   ah[mb], bl[nb][0], bl[nb][1]);
                    mma16816(acc[mb][nb*2+1], ah[mb], bl[nb][2], bl[nb][3]);
                }
        }
    };

    load_stage(0, 0);
    CP_COMMIT();
    if (nch > 1) { load_stage(1, 64); CP_COMMIT(); }
    for (int c = 0; c < nch; c++) {
        if (c == nch - 1) cp_wait<0>(); else cp_wait<1>();
        __syncthreads();
        compute(c % 3);
        int nx = c + 2;
        if (nx < nch) { load_stage(nx % 3, nx << 6); CP_COMMIT(); }
    }

    const int gid = lane >> 2, qid = lane & 3;
    #pragma unroll
    for (int mb = 0; mb < 2; mb++) {
        #pragma unroll
        for (int nf = 0; nf < 8; nf++) {
            int n = n0 + warp_n + nf * 8 + qid * 2;
            #pragma unroll
            for (int hh = 0; hh < 2; hh++) {
                int m = m0 + warp_m + mb * 16 + gid + hh * 8;
                float vx = acc[mb][nf][hh*2];
                float vy = acc[mb][nf][hh*2 + 1];
                if (EPI & 1) { vx += bias[n]; vy += bias[n + 1]; }
                size_t o = (size_t)m * Nout + n;
                if (EPI & 4) {
                    float2 r = *reinterpret_cast<const float2*>(resid + o);
                    vx += r.x; vy += r.y;
                }
                *reinterpret_cast<float2*>(C + o) = make_float2(vx, vy);
            }
        }
    }
}

// ---------------------------------------------------------------------------
// LM-head GEMM: fp16 1-pass, CTA 128x256, 8 warps (2x4), warp tile 64x64.
// ---------------------------------------------------------------------------
#define STGL (3*SUBT)                   // 48KB
#define GL_SMEM (3*STGL)                // 147456

__global__ __launch_bounds__(256, 1)
void gemm_lm(const __half* __restrict__ A, const __half* __restrict__ B,
             float* __restrict__ C, int Nout, int K) {
    extern __shared__ char smem[];
    uint32_t sb = smem_u32(smem);
    const int tid = threadIdx.x;
    const int lane = tid & 31, wid = tid >> 5;
    const int m0 = blockIdx.y * 128, n0 = blockIdx.x * 256;
    const int warp_m = (wid >> 2) * 64;
    const int warp_n = (wid & 3) * 64;

    float acc[4][8][4];
    #pragma unroll
    for (int i = 0; i < 4; i++)
        #pragma unroll
        for (int j = 0; j < 8; j++)
            #pragma unroll
            for (int e = 0; e < 4; e++) acc[i][j][e] = 0.f;

    const int nch = K >> 6;   // 8

    auto load_stage = [&](int buf, int k0) {
        uint32_t base = sb + buf * STGL;
        #pragma unroll
        for (int it = 0; it < 4; it++) {
            int u = tid + it * 256;
            int row = u >> 3, c = u & 7;
            uint32_t dst = base + row * 128 + ((c ^ (row & 7)) * 16);
            cp_async16(dst, A + (size_t)(m0 + row) * K + k0 + c * 8, 16);
        }
        #pragma unroll
        for (int it = 0; it < 8; it++) {
            int u = tid + it * 256;
            int row = u >> 3, c = u & 7;
            uint32_t dst = base + SUBT + row * 128 + ((c ^ (row & 7)) * 16);
            const __half* g = B + (size_t)(n0 + row) * K + k0 + c * 8;
            int sz = 16;
            if (n0 + row >= Nout) { g = B; sz = 0; }
            cp_async16(dst, g, sz);
        }
    };

    int ra[4];
    #pragma unroll
    for (int mb = 0; mb < 4; mb++) ra[mb] = warp_m + mb * 16 + (lane & 15);
    const int ca = lane >> 4;
    int rB[4];
    #pragma unroll
    for (int nb = 0; nb < 4; nb++)
        rB[nb] = warp_n + nb * 16 + ((lane >> 4) & 1) * 8 + (lane & 7);
    const int kcB = (lane >> 3) & 1;

    auto compute = [&](int buf) {
        uint32_t base = sb + buf * STGL;
        #pragma unroll
        for (int ks = 0; ks < 4; ks++) {
            uint32_t a[4][4], b[4][4];
            #pragma unroll
            for (int mb = 0; mb < 4; mb++) {
                uint32_t off = ra[mb] * 128 + (((ks*2 + ca) ^ (ra[mb] & 7)) * 16);
                ldm4(a[mb], base + off);
            }
            #pragma unroll
            for (int nb = 0; nb < 4; nb++) {
                uint32_t off = rB[nb] * 128 + (((ks*2 + kcB) ^ (rB[nb] & 7)) * 16);
                ldm4(b[nb], base + SUBT + off);
            }
            #pragma unroll
            for (int mb = 0; mb < 4; mb++)
                #pragma unroll
                for (int nb = 0; nb < 4; nb++) {
                    mma16816h(acc[mb][nb*2],   a[mb], b[nb][0], b[nb][1]);
                    mma16816h(acc[mb][nb*2+1], a[mb], b[nb][2], b[nb][3]);
                }
        }
    };

    load_stage(0, 0);
    CP_COMMIT();
    load_stage(1, 64);
    CP_COMMIT();
    for (int c = 0; c < nch; c++) {
        if (c == nch - 1) cp_wait<0>(); else cp_wait<1>();
        __syncthreads();
        compute(c % 3);
        int nx = c + 2;
        if (nx < nch) { load_stage(nx % 3, nx << 6); CP_COMMIT(); }
    }

    const int gid = lane >> 2, qid = lane & 3;
    #pragma unroll
    for (int mb = 0; mb < 4; mb++) {
        #pragma unroll
        for (int nf = 0; nf < 8; nf++) {
            int n = n0 + warp_n + nf * 8 + qid * 2;
            #pragma unroll
            for (int hh = 0; hh < 2; hh++) {
                int m = m0 + warp_m + mb * 16 + gid + hh * 8;
                float vx = acc[mb][nf][hh*2];
                float vy = acc[mb][nf][hh*2 + 1];
                size_t o = (size_t)m * Nout + n;
                if (n < Nout)     C[o]     = vx;
                if (n + 1 < Nout) C[o + 1] = vy;
            }
        }
    }
}

// ---------------------------------------------------------------------------
// Tensor-core causal flash attention (fp16 mma, fp32 softmax).
// CTA: 128 thr (4 warps), 64 queries (16/warp). grid (S/64, B*H).
// K/V tiles of 64 keys double-buffered via cp.async.
// ---------------------------------------------------------------------------
__global__ __launch_bounds__(128)
void attn_mma(const __half* __restrict__ qkv,
              __nv_bfloat16* __restrict__ ctx_hi,
              __nv_bfloat16* __restrict__ ctx_lo) {
    __shared__ __align__(16) char sQ[8192];
    __shared__ __align__(16) char sK[2][8192];
    __shared__ __align__(16) char sV[2][8192];
    int bh = blockIdx.y;
    int b = bh >> 3, h = bh & 7;
    int qb = gridDim.x - 1 - blockIdx.x;      // heavy blocks first
    int tid = threadIdx.x, lane = tid & 31, wid = tid >> 5;
    int warp_q = wid * 16;
    const int gid = lane >> 2, qid = lane & 3;
    uint32_t sQb = smem_u32(sQ);
    uint32_t sKb[2] = {smem_u32(sK[0]), smem_u32(sK[1])};
    uint32_t sVb[2] = {smem_u32(sV[0]), smem_u32(sV[1])};

    size_t tokbase = (size_t)b * SS;

    // load Q tile (64 rows x 64 fp16 = 128B/row, SW swizzle)
    #pragma unroll
    for (int it = 0; it < 4; it++) {
        int u = tid + it * 128;
        int row = u >> 3, c = u & 7;
        uint32_t dst = sQb + row * 128 + ((c ^ (row & 7)) * 16);
        const __half* g = qkv + (tokbase + qb*64 + row) * QKVD + h*DH + c*8;
        cp_async16(dst, g, 16);
    }
    auto load_kv = [&](int buf, int t) {
        #pragma unroll
        for (int it = 0; it < 4; it++) {
            int u = tid + it * 128;
            int row = u >> 3, c = u & 7;
            uint32_t sw = row * 128 + ((c ^ (row & 7)) * 16);
            const __half* gk = qkv + (tokbase + t*64 + row) * QKVD + DD + h*DH + c*8;
            const __half* gv = qkv + (tokbase + t*64 + row) * QKVD + 2*DD + h*DH + c*8;
            cp_async16(sKb[buf] + sw, gk, 16);
            cp_async16(sVb[buf] + sw, gv, 16);
        }
    };
    load_kv(0, 0);
    CP_COMMIT();
    cp_wait<0>();
    __syncthreads();

    // Q fragments (A operand, m16 rows = warp_q.., k=64)
    uint32_t qa[4][4];
    {
        int r = warp_q + (lane & 15);
        int chalf = lane >> 4;
        #pragma unroll
        for (int ks = 0; ks < 4; ks++) {
            int c = ks*2 + chalf;
            ldm4(qa[ks], sQb + r * 128 + ((c ^ (r & 7)) * 16));
        }
    }

    float m0v = -1e30f, m1v = -1e30f, l0 = 0.f, l1 = 0.f;
    float oacc[8][4];
    #pragma unroll
    for (int i = 0; i < 8; i++)
        #pragma unroll
        for (int e = 0; e < 4; e++) oacc[i][e] = 0.f;

    const int rloc0 = warp_q + gid;          // local query rows rloc0, rloc0+8

    for (int t = 0; t <= qb; t++) {
        int buf = t & 1;
        if (t < qb) { load_kv(buf ^ 1, t + 1); CP_COMMIT(); }

        // ---- S = Q K^T (fp32 accum)
        float sacc[8][4];
        #pragma unroll
        for (int i = 0; i < 8; i++)
            #pragma unroll
            for (int e = 0; e < 4; e++) sacc[i][e] = 0.f;
        {
            int rb = ((lane >> 4) & 1) * 8 + (lane & 7);
            int kc = (lane >> 3) & 1;
            #pragma unroll
            for (int ks = 0; ks < 4; ks++) {
                uint32_t kb[4][4];
                #pragma unroll
                for (int nb = 0; nb < 4; nb++) {
                    int r = nb*16 + rb;
                    int c = ks*2 + kc;
                    ldm4(kb[nb], sKb[buf] + r * 128 + ((c ^ (r & 7)) * 16));
                }
                #pragma unroll
                for (int nb = 0; nb < 4; nb++) {
                    mma16816h(sacc[nb*2],   qa[ks], kb[nb][0], kb[nb][1]);
                    mma16816h(sacc[nb*2+1], qa[ks], kb[nb][2], kb[nb][3]);
                }
            }
        }
        // scale + causal mask (only diagonal tile)
        #pragma unroll
        for (int i = 0; i < 8; i++)
            #pragma unroll
            for (int e = 0; e < 4; e++) sacc[i][e] *= 0.125f;
        if (t == qb) {
            #pragma unroll
            for (int i = 0; i < 8; i++) {
                int col = i*8 + qid*2;
                #pragma unroll
                for (int e = 0; e < 4; e++) {
                    int cc = col + (e & 1);
                    int rr = rloc0 + ((e >> 1) * 8);
                    if (cc > rr) sacc[i][e] = -1e30f;
                }
            }
        }
        // ---- online softmax
        float rmax0 = -1e30f, rmax1 = -1e30f;
        #pragma unroll
        for (int i = 0; i < 8; i++) {
            rmax0 = fmaxf(rmax0, fmaxf(sacc[i][0], sacc[i][1]));
            rmax1 = fmaxf(rmax1, fmaxf(sacc[i][2], sacc[i][3]));
        }
        #pragma unroll
        for (int o = 1; o <= 2; o <<= 1) {
            rmax0 = fmaxf(rmax0, __shfl_xor_sync(0xffffffffu, rmax0, o));
            rmax1 = fmaxf(rmax1, __shfl_xor_sync(0xffffffffu, rmax1, o));
        }
        float mn0 = fmaxf(m0v, rmax0), mn1 = fmaxf(m1v, rmax1);
        float cor0 = __expf(m0v - mn0), cor1 = __expf(m1v - mn1);
        m0v = mn0; m1v = mn1;
        float rs0 = 0.f, rs1 = 0.f;
        float p[8][4];
        #pragma unroll
        for (int i = 0; i < 8; i++) {
            p[i][0] = __expf(sacc[i][0] - mn0);
            p[i][1] = __expf(sacc[i][1] - mn0);
            p[i][2] = __expf(sacc[i][2] - mn1);
            p[i][3] = __expf(sacc[i][3] - mn1);
            rs0 += p[i][0] + p[i][1];
            rs1 += p[i][2] + p[i][3];
        }
        #pragma unroll
        for (int o = 1; o <= 2; o <<= 1) {
            rs0 += __shfl_xor_sync(0xffffffffu, rs0, o);
            rs1 += __shfl_xor_sync(0xffffffffu, rs1, o);
        }
        l0 = l0 * cor0 + rs0;
        l1 = l1 * cor1 + rs1;
        #pragma unroll
        for (int i = 0; i < 8; i++) {
            oacc[i][0] *= cor0; oacc[i][1] *= cor0;
            oacc[i][2] *= cor1; oacc[i][3] *= cor1;
        }
        // ---- P V  (P C-frags -> A frags; V^T via ldmatrix.trans)
        uint32_t pa[4][4];
        #pragma unroll
        for (int kk = 0; kk < 4; kk++) {
            pa[kk][0] = packh2(p[2*kk][0],   p[2*kk][1]);
            pa[kk][1] = packh2(p[2*kk][2],   p[2*kk][3]);
            pa[kk][2] = packh2(p[2*kk+1][0], p[2*kk+1][1]);
            pa[kk][3] = packh2(p[2*kk+1][2], p[2*kk+1][3]);
        }
        {
            int rv = ((lane >> 3) & 1) * 8 + (lane & 7);
            int cv = lane >> 4;
            #pragma unroll
            for (int kk = 0; kk < 4; kk++) {
                uint32_t vb[4][4];
                #pragma unroll
                for (int nd = 0; nd < 4; nd++) {
                    int r = kk*16 + rv;
                    int c = nd*2 + cv;
                    ldm4t(vb[nd], sVb[buf] + r * 128 + ((c ^ (r & 7)) * 16));
                }
                #pragma unroll
                for (int nd = 0; nd < 4; nd++) {
                    mma16816h(oacc[nd*2],   pa[kk], vb[nd][0], vb[nd][1]);
                    mma16816h(oacc[nd*2+1], pa[kk], vb[nd][2], vb[nd][3]);
                }
            }
        }
        if (t < qb) cp_wait<0>();
        __syncthreads();
    }

    // ---- normalize + store bf16 hi/lo
    float inv0 = 1.0f / l0, inv1 = 1.0f / l1;
    size_t tok0 = tokbase + qb*64 + rloc0;
    #pragma unroll
    for (int nd = 0; nd < 8; nd++) {
        int col = h*DH + nd*8 + qid*2;
        {
            float ox = oacc[nd][0] * inv0, oy = oacc[nd][1] * inv0;
            uint32_t hh, ll;
            split2(ox, oy, hh, ll);
            size_t o = tok0 * DD + col;
            *reinterpret_cast<uint32_t*>(ctx_hi + o) = hh;
            *reinterpret_cast<uint32_t*>(ctx_lo + o) = ll;
        }
        {
            float ox = oacc[nd][2] * inv1, oy = oacc[nd][3] * inv1;
            uint32_t hh, ll;
            split2(ox, oy, hh, ll);
            size_t o = (tok0 + 8) * DD + col;
            *reinterpret_cast<uint32_t*>(ctx_hi + o) = hh;
            *reinterpret_cast<uint32_t*>(ctx_lo + o) = ll;
        }
    }
}

// ---------------------------------------------------------------------------
// Host launch
// ---------------------------------------------------------------------------
extern "C" void kernel_launch(void* const* d_in, const int* in_sizes, int n_in,
                              void* d_out, int out_size) {
    const int*   ids   = (const int*)  d_in[0];
    const float* emb   = (const float*)d_in[1];
    const float* pe    = (const float*)d_in[2];
    const float* wq    = (const float*)d_in[3];
    const float* wk    = (const float*)d_in[4];
    const float* wv    = (const float*)d_in[5];
    const float* wo    = (const float*)d_in[6];
    const float* wo_b  = (const float*)d_in[7];
    const float* w1    = (const float*)d_in[8];
    const float* b1    = (const float*)d_in[9];
    const float* w2    = (const float*)d_in[10];
    const float* b2    = (const float*)d_in[11];
    const float* ln1_g = (const float*)d_in[12];
    const float* ln1_b = (const float*)d_in[13];
    const float* ln2_g = (const float*)d_in[14];
    const float* ln2_b = (const float*)d_in[15];
    const float* lnf_g = (const float*)d_in[16];
    const float* lnf_b = (const float*)d_in[17];
    float* out = (float*)d_out;

    float *x;
    __half *qkvh;
    __nv_bfloat16 *h_hi, *h_lo, *ctx_hi, *ctx_lo, *ff_hi, *ff_lo;
    __nv_bfloat16 *wqkvT_hi, *wqkvT_lo, *woT_hi, *woT_lo;
    __nv_bfloat16 *w1T_hi, *w1T_lo, *w2T_hi, *w2T_lo;
    __half *hf, *embH;
    cudaGetSymbolAddress((void**)&x, g_x);
    cudaGetSymbolAddress((void**)&qkvh, g_qkvh);
    cudaGetSymbolAddress((void**)&h_hi, g_h_hi);
    cudaGetSymbolAddress((void**)&h_lo, g_h_lo);
    cudaGetSymbolAddress((void**)&ctx_hi, g_ctx_hi);
    cudaGetSymbolAddress((void**)&ctx_lo, g_ctx_lo);
    cudaGetSymbolAddress((void**)&ff_hi, g_ff_hi);
    cudaGetSymbolAddress((void**)&ff_lo, g_ff_lo);
    cudaGetSymbolAddress((void**)&wqkvT_hi, g_wqkvT_hi);
    cudaGetSymbolAddress((void**)&wqkvT_lo, g_wqkvT_lo);
    cudaGetSymbolAddress((void**)&woT_hi, g_woT_hi);
    cudaGetSymbolAddress((void**)&woT_lo, g_woT_lo);
    cudaGetSymbolAddress((void**)&w1T_hi, g_w1T_hi);
    cudaGetSymbolAddress((void**)&w1T_lo, g_w1T_lo);
    cudaGetSymbolAddress((void**)&w2T_hi, g_w2T_hi);
    cudaGetSymbolAddress((void**)&w2T_lo, g_w2T_lo);
    cudaGetSymbolAddress((void**)&hf, g_hf);
    cudaGetSymbolAddress((void**)&embH, g_embH);

    cudaFuncSetAttribute(gemm_w<0, 2>, cudaFuncAttributeMaxDynamicSharedMemorySize, GW_SMEM);
    cudaFuncSetAttribute(gemm_w<3, 1>, cudaFuncAttributeMaxDynamicSharedMemorySize, GW_SMEM);
    cudaFuncSetAttribute(gemm_n<5>, cudaFuncAttributeMaxDynamicSharedMemorySize, GN_SMEM);
    cudaFuncSetAttribute(gemm_lm, cudaFuncAttributeMaxDynamicSharedMemorySize, GL_SMEM);

    // weight conversions
    dim3 cb(32, 8);
    conv_wT<<<dim3(DD/32, DD/32), cb>>>(wq, wqkvT_hi,            wqkvT_lo,            DD, DD);
    conv_wT<<<dim3(DD/32, DD/32), cb>>>(wk, wqkvT_hi + DD*DD,    wqkvT_lo + DD*DD,    DD, DD);
    conv_wT<<<dim3(DD/32, DD/32), cb>>>(wv, wqkvT_hi + 2*DD*DD,  wqkvT_lo + 2*DD*DD,  DD, DD);
    conv_wT<<<dim3(DD/32, DD/32), cb>>>(wo, woT_hi, woT_lo, DD, DD);
    conv_wT<<<dim3(FFD/32, DD/32), cb>>>(w1, w1T_hi, w1T_lo, DD, FFD);
    conv_wT<<<dim3(DD/32, FFD/32), cb>>>(w2, w2T_hi, w2T_lo, FFD, DD);
    {
        int n4 = VV * DD / 4;
        conv_half4<<<(n4 + 255) / 256, 256>>>(emb, embH, n4);
    }

    embed_kernel<<<NN, 128>>>(ids, emb, pe, x);

    dim3 gQKV(QKVD/256, NN/128);     // (6, 32)
    dim3 gProj(DD/128, NN/128);      // (4, 32)
    dim3 gFF1(FFD/256, NN/128);      // (8, 32)
    dim3 gAttn(SS/64, BB*HH);        // (16, 32)

    for (int layer = 0; layer < NLAYERS; layer++) {
        ln_kernel<0><<<NN, 128>>>(x, (uint32_t*)h_hi, (uint32_t*)h_lo, ln1_g, ln1_b);
        gemm_w<0, 2><<<gQKV, 256, GW_SMEM>>>(
            h_hi, h_lo, wqkvT_hi, wqkvT_lo, nullptr,
            nullptr, nullptr, nullptr, qkvh, QKVD, DD);
        attn_mma<<<gAttn, 128>>>(qkvh, ctx_hi, ctx_lo);
        gemm_n<5><<<gProj, 256, GN_SMEM>>>(
            ctx_hi, ctx_lo, woT_hi, woT_lo, wo_b, x, x, DD, DD);
        ln_kernel<0><<<NN, 128>>>(x, (uint32_t*)h_hi, (uint32_t*)h_lo, ln2_g, ln2_b);
        gemm_w<3, 1><<<gFF1, 256, GW_SMEM>>>(
            h_hi, h_lo, w1T_hi, w1T_lo, b1,
            nullptr, ff_hi, ff_lo, nullptr, FFD, DD);
        gemm_n<5><<<gProj, 256, GN_SMEM>>>(
            ff_hi, ff_lo, w2T_hi, w2T_lo, b2, x, x, DD, FFD);
    }

    ln_kernel<2><<<NN, 128>>>(x, (uint32_t*)hf, nullptr, lnf_g, lnf_b);

    dim3 gLM((VV + 255) / 256, NN / 128);   // (197, 32)
    gemm_lm<<<gLM, 256, GL_SMEM>>>(hf, embH, out, VV, DD);
}

// round 11
// speedup vs baseline: 5.6662x; 1.1799x over previous
#include <cuda_runtime.h>
#include <cuda_bf16.h>
#include <cuda_fp16.h>
#include <math.h>
#include <stdint.h>

// Problem constants
#define BB 4
#define SS 1024
#define NN (BB*SS)      // 4096 tokens
#define DD 512
#define HH 8
#define DH 64
#define FFD 2048
#define VV 50257
#define NLAYERS 6
#define QKVD 1536       // fused qkv width

// ---------------------------------------------------------------------------
// Scratch (allocation-free: __device__ globals)
// ---------------------------------------------------------------------------
__device__ float g_x[NN*DD];
__device__ __half g_h_hi[NN*DD],  g_h_lo[NN*DD];
__device__ __half g_qkvh[NN*QKVD];
__device__ __half g_ctx_hi[NN*DD], g_ctx_lo[NN*DD];
__device__ __half g_ff_hi[NN*FFD], g_ff_lo[NN*FFD];
// transposed fp16 weights [N,K]
__device__ __half g_wqkvT[3*DD*DD];
__device__ __half g_woT[DD*DD];
__device__ __half g_w1T[FFD*DD];
__device__ __half g_w2T[DD*FFD];
// LM head
__device__ __half g_hf[NN*DD];
__device__ __half g_embH[VV*DD];

// ---------------------------------------------------------------------------
// Helpers
// ---------------------------------------------------------------------------
__device__ __forceinline__ uint32_t smem_u32(const void* p) {
    uint32_t a;
    asm("{ .reg .u64 t; cvta.to.shared.u64 t, %1; cvt.u32.u64 %0, t; }"
        : "=r"(a) : "l"(p));
    return a;
}

__device__ __forceinline__ void ldm4(uint32_t* r, uint32_t addr) {
    asm volatile("ldmatrix.sync.aligned.m8n8.x4.shared.b16 {%0,%1,%2,%3}, [%4];"
                 : "=r"(r[0]), "=r"(r[1]), "=r"(r[2]), "=r"(r[3]) : "r"(addr));
}
__device__ __forceinline__ void ldm4t(uint32_t* r, uint32_t addr) {
    asm volatile("ldmatrix.sync.aligned.m8n8.x4.trans.shared.b16 {%0,%1,%2,%3}, [%4];"
                 : "=r"(r[0]), "=r"(r[1]), "=r"(r[2]), "=r"(r[3]) : "r"(addr));
}

__device__ __forceinline__ void mma16816h(float* c, const uint32_t* a,
                                          uint32_t b0, uint32_t b1) {
    asm volatile(
        "mma.sync.aligned.m16n8k16.row.col.f32.f16.f16.f32 "
        "{%0,%1,%2,%3}, {%4,%5,%6,%7}, {%8,%9}, {%0,%1,%2,%3};"
        : "+f"(c[0]), "+f"(c[1]), "+f"(c[2]), "+f"(c[3])
        : "r"(a[0]), "r"(a[1]), "r"(a[2]), "r"(a[3]), "r"(b0), "r"(b1));
}

__device__ __forceinline__ void cp_async16(uint32_t dst, const void* src, int szbytes) {
    asm volatile("cp.async.cg.shared.global [%0], [%1], 16, %2;"
                 :: "r"(dst), "l"(src), "r"(szbytes));
}
#define CP_COMMIT() asm volatile("cp.async.commit_group;" ::: "memory")
template<int N>
__device__ __forceinline__ void cp_wait() {
    asm volatile("cp.async.wait_group %0;" :: "n"(N) : "memory");
}

// fp16 hi/lo split (2 floats -> packed f16x2 hi and lo)
__device__ __forceinline__ void split2h(float x, float y, uint32_t& h, uint32_t& l) {
    __half h0 = __float2half_rn(x);
    __half h1 = __float2half_rn(y);
    __half l0 = __float2half_rn(x - __half2float(h0));
    __half l1 = __float2half_rn(y - __half2float(h1));
    h = (uint32_t)__half_as_ushort(h0) | ((uint32_t)__half_as_ushort(h1) << 16);
    l = (uint32_t)__half_as_ushort(l0) | ((uint32_t)__half_as_ushort(l1) << 16);
}
__device__ __forceinline__ uint32_t packh2(float x, float y) {
    __half2 t = __floats2half2_rn(x, y);
    return *reinterpret_cast<uint32_t*>(&t);
}

__device__ __forceinline__ float gelu_exact(float v) {
    return 0.5f * v * (1.0f + erff(v * 0.70710678118654752f));
}

// ---------------------------------------------------------------------------
// Weight conversion: W [K,N] fp32 -> fp16 [N,K] (transpose)
// ---------------------------------------------------------------------------
__global__ void conv_wTh(const float* __restrict__ W, __half* __restrict__ o16,
                         int K, int N) {
    __shared__ float t[32][33];
    int n0 = blockIdx.x * 32, k0 = blockIdx.y * 32;
    int tx = threadIdx.x, ty = threadIdx.y;
    #pragma unroll
    for (int r = 0; r < 4; r++)
        t[ty + r*8][tx] = W[(size_t)(k0 + ty + r*8) * N + n0 + tx];
    __syncthreads();
    #pragma unroll
    for (int r = 0; r < 4; r++)
        o16[(size_t)(n0 + ty + r*8) * K + k0 + tx] = __float2half_rn(t[tx][ty + r*8]);
}

// Elementwise fp32 -> fp16
__global__ void conv_half4(const float* __restrict__ src,
                           __half* __restrict__ dst, int n4) {
    int i = blockIdx.x * 256 + threadIdx.x;
    if (i >= n4) return;
    float4 v = reinterpret_cast<const float4*>(src)[i];
    uint2 o;
    o.x = packh2(v.x, v.y);
    o.y = packh2(v.z, v.w);
    reinterpret_cast<uint2*>(dst)[i] = o;
}

// ---------------------------------------------------------------------------
// Embedding
// ---------------------------------------------------------------------------
__global__ void embed_kernel(const int* __restrict__ ids,
                             const float* __restrict__ emb,
                             const float* __restrict__ pe,
                             float* __restrict__ x) {
    int n = blockIdx.x;
    int tid = threadIdx.x;
    int id = ids[n];
    int s = n & (SS - 1);
    const float sq = 22.62741699796952f;
    float4 e = reinterpret_cast<const float4*>(emb + (size_t)id * DD)[tid];
    float4 p = reinterpret_cast<const float4*>(pe + (size_t)s * DD)[tid];
    float4 o;
    o.x = e.x * sq + p.x; o.y = e.y * sq + p.y;
    o.z = e.z * sq + p.z; o.w = e.w * sq + p.w;
    reinterpret_cast<float4*>(x + (size_t)n * DD)[tid] = o;
}

// ---------------------------------------------------------------------------
// LayerNorm.  MODE 0: fp16 hi/lo split.  MODE 2: single fp16.
// ---------------------------------------------------------------------------
template<int MODE>
__global__ void ln_kernel(const float* __restrict__ in,
                          uint32_t* __restrict__ out_hi,
                          uint32_t* __restrict__ out_lo,
                          const float* __restrict__ g, const float* __restrict__ b) {
    int row = blockIdx.x;
    int tid = threadIdx.x;    // 128
    float4 v = reinterpret_cast<const float4*>(in + (size_t)row * DD)[tid];
    float s = v.x + v.y + v.z + v.w;
    float ss = v.x*v.x + v.y*v.y + v.z*v.z + v.w*v.w;
    #pragma unroll
    for (int o = 16; o > 0; o >>= 1) {
        s  += __shfl_xor_sync(0xffffffffu, s, o);
        ss += __shfl_xor_sync(0xffffffffu, ss, o);
    }
    __shared__ float rs[4], rss[4];
    int warp = tid >> 5;
    if ((tid & 31) == 0) { rs[warp] = s; rss[warp] = ss; }
    __syncthreads();
    float mean = (rs[0]+rs[1]+rs[2]+rs[3]) * (1.0f/DD);
    float var  = (rss[0]+rss[1]+rss[2]+rss[3]) * (1.0f/DD) - mean*mean;
    float rstd = rsqrtf(var + 1e-5f);
    float4 gg = reinterpret_cast<const float4*>(g)[tid];
    float4 bb = reinterpret_cast<const float4*>(b)[tid];
    float4 o;
    o.x = (v.x - mean)*rstd*gg.x + bb.x;
    o.y = (v.y - mean)*rstd*gg.y + bb.y;
    o.z = (v.z - mean)*rstd*gg.z + bb.z;
    o.w = (v.w - mean)*rstd*gg.w + bb.w;
    if (MODE == 0) {
        uint2 h, l;
        split2h(o.x, o.y, h.x, l.x);
        split2h(o.z, o.w, h.y, l.y);
        reinterpret_cast<uint2*>(out_hi)[(size_t)row * (DD/4) + tid] = h;
        reinterpret_cast<uint2*>(out_lo)[(size_t)row * (DD/4) + tid] = l;
    } else {
        uint2 hh;
        hh.x = packh2(o.x, o.y);
        hh.y = packh2(o.z, o.w);
        reinterpret_cast<uint2*>(out_hi)[(size_t)row * (DD/4) + tid] = hh;
    }
}

#define SUBT 16384                      // 128 rows x 128B

// ---------------------------------------------------------------------------
// Wide layer GEMM (qkv, ff1): fp16 2-pass (Ah+Al)*B, CTA 128x256, 8 warps
// (2M x 4N), warp tile 64x64. Stage = Ahi16+Alo16+B32 = 64KB, 3 stages.
// OUT: 2 = fp16 single (Ch), 3 = fp16 hi/lo split (Chi/Clo).
// ---------------------------------------------------------------------------
#define STGW (4*SUBT)                   // 64KB
#define GW_SMEM (3*STGW)                // 196608

template<int EPI, int OUT>
__global__ __launch_bounds__(256, 1)
void gemm_w(const __half* __restrict__ Ahi, const __half* __restrict__ Alo,
            const __half* __restrict__ B,
            const float* __restrict__ bias,
            __half* __restrict__ Chi, __half* __restrict__ Clo,
            __half* __restrict__ Ch, int Nout, int K) {
    extern __shared__ char smem[];
    uint32_t sb = smem_u32(smem);
    const int tid = threadIdx.x;
    const int lane = tid & 31, wid = tid >> 5;
    const int m0 = blockIdx.y * 128, n0 = blockIdx.x * 256;
    const int warp_m = (wid >> 2) * 64;
    const int warp_n = (wid & 3) * 64;

    float acc[4][8][4];
    #pragma unroll
    for (int i = 0; i < 4; i++)
        #pragma unroll
        for (int j = 0; j < 8; j++)
            #pragma unroll
            for (int e = 0; e < 4; e++) acc[i][j][e] = 0.f;

    const int nch = K >> 6;   // 8

    auto load_stage = [&](int buf, int k0) {
        uint32_t base = sb + buf * STGW;
        #pragma unroll
        for (int t = 0; t < 2; t++) {
            const __half* P = t ? Alo : Ahi;
            uint32_t dbase = base + t * SUBT;
            #pragma unroll
            for (int it = 0; it < 4; it++) {
                int u = tid + it * 256;
                int row = u >> 3, c = u & 7;
                uint32_t dst = dbase + row * 128 + ((c ^ (row & 7)) * 16);
                cp_async16(dst, P + (size_t)(m0 + row) * K + k0 + c * 8, 16);
            }
        }
        // B: 256 rows
        #pragma unroll
        for (int it = 0; it < 8; it++) {
            int u = tid + it * 256;
            int row = u >> 3, c = u & 7;
            uint32_t dst = base + 2*SUBT + row * 128 + ((c ^ (row & 7)) * 16);
            cp_async16(dst, B + (size_t)(n0 + row) * K + k0 + c * 8, 16);
        }
    };

    int ra[4];
    #pragma unroll
    for (int mb = 0; mb < 4; mb++) ra[mb] = warp_m + mb * 16 + (lane & 15);
    const int ca = lane >> 4;
    int rB[4];
    #pragma unroll
    for (int nb = 0; nb < 4; nb++)
        rB[nb] = warp_n + nb * 16 + ((lane >> 4) & 1) * 8 + (lane & 7);
    const int kcB = (lane >> 3) & 1;

    auto compute = [&](int buf) {
        uint32_t base = sb + buf * STGW;
        #pragma unroll
        for (int ks = 0; ks < 4; ks++) {
            uint32_t ah[4][4], al[4][4], bb[4][4];
            #pragma unroll
            for (int mb = 0; mb < 4; mb++) {
                uint32_t off = ra[mb] * 128 + (((ks*2 + ca) ^ (ra[mb] & 7)) * 16);
                ldm4(ah[mb], base + off);
                ldm4(al[mb], base + SUBT + off);
            }
            #pragma unroll
            for (int nb = 0; nb < 4; nb++) {
                uint32_t off = rB[nb] * 128 + (((ks*2 + kcB) ^ (rB[nb] & 7)) * 16);
                ldm4(bb[nb], base + 2*SUBT + off);
            }
            #pragma unroll
            for (int mb = 0; mb < 4; mb++)
                #pragma unroll
                for (int nb = 0; nb < 4; nb++) {
                    mma16816h(acc[mb][nb*2],   ah[mb], bb[nb][0], bb[nb][1]);
                    mma16816h(acc[mb][nb*2+1], ah[mb], bb[nb][2], bb[nb][3]);
                }
            #pragma unroll
            for (int mb = 0; mb < 4; mb++)
                #pragma unroll
                for (int nb = 0; nb < 4; nb++) {
                    mma16816h(acc[mb][nb*2],   al[mb], bb[nb][0], bb[nb][1]);
                    mma16816h(acc[mb][nb*2+1], al[mb], bb[nb][2], bb[nb][3]);
                }
        }
    };

    load_stage(0, 0);
    CP_COMMIT();
    load_stage(1, 64);
    CP_COMMIT();
    for (int c = 0; c < nch; c++) {
        if (c == nch - 1) cp_wait<0>(); else cp_wait<1>();
        __syncthreads();
        compute(c % 3);
        int nx = c + 2;
        if (nx < nch) { load_stage(nx % 3, nx << 6); CP_COMMIT(); }
    }

    const int gid = lane >> 2, qid = lane & 3;
    #pragma unroll
    for (int mb = 0; mb < 4; mb++) {
        #pragma unroll
        for (int nf = 0; nf < 8; nf++) {
            int n = n0 + warp_n + nf * 8 + qid * 2;
            #pragma unroll
            for (int hh = 0; hh < 2; hh++) {
                int m = m0 + warp_m + mb * 16 + gid + hh * 8;
                float vx = acc[mb][nf][hh*2];
                float vy = acc[mb][nf][hh*2 + 1];
                if (EPI & 1) { vx += bias[n]; vy += bias[n + 1]; }
                if (EPI & 2) { vx = gelu_exact(vx); vy = gelu_exact(vy); }
                size_t o = (size_t)m * Nout + n;
                if (OUT == 3) {
                    uint32_t h, l;
                    split2h(vx, vy, h, l);
                    *reinterpret_cast<uint32_t*>(Chi + o) = h;
                    *reinterpret_cast<uint32_t*>(Clo + o) = l;
                } else {
                    *reinterpret_cast<uint32_t*>(Ch + o) = packh2(vx, vy);
                }
            }
        }
    }
}

// ---------------------------------------------------------------------------
// Narrow layer GEMM (wo, ff2): fp16 2-pass, CTA 128x128, 8 warps (4M x 2N),
// warp tile 32x64, 3-stage. Stage = Ahi16+Alo16+B16 = 48KB.
// Output: fp32 x with bias+residual.
// ---------------------------------------------------------------------------
#define STGN (3*SUBT)                   // 48KB
#define GN_SMEM (3*STGN)                // 147456

__global__ __launch_bounds__(256, 1)
void gemm_n(const __half* __restrict__ Ahi, const __half* __restrict__ Alo,
            const __half* __restrict__ B,
            const float* __restrict__ bias, const float* __restrict__ resid,
            float* __restrict__ C, int Nout, int K) {
    extern __shared__ char smem[];
    uint32_t sb = smem_u32(smem);
    const int tid = threadIdx.x;
    const int lane = tid & 31, wid = tid >> 5;
    const int m0 = blockIdx.y * 128, n0 = blockIdx.x * 128;
    const int warp_m = (wid >> 1) * 32;
    const int warp_n = (wid & 1) * 64;

    float acc[2][8][4];
    #pragma unroll
    for (int i = 0; i < 2; i++)
        #pragma unroll
        for (int j = 0; j < 8; j++)
            #pragma unroll
            for (int e = 0; e < 4; e++) acc[i][j][e] = 0.f;

    const int nch = K >> 6;

    auto load_stage = [&](int buf, int k0) {
        uint32_t base = sb + buf * STGN;
        const __half* srcs[3] = {Ahi, Alo, B};
        #pragma unroll
        for (int sub = 0; sub < 3; sub++) {
            const __half* P = srcs[sub];
            int row0 = (sub < 2) ? m0 : n0;
            uint32_t dbase = base + sub * SUBT;
            #pragma unroll
            for (int it = 0; it < 4; it++) {
                int u = tid + it * 256;
                int row = u >> 3, c = u & 7;
                uint32_t dst = dbase + row * 128 + ((c ^ (row & 7)) * 16);
                cp_async16(dst, P + (size_t)(row0 + row) * K + k0 + c * 8, 16);
            }
        }
    };

    int ra[2];
    ra[0] = warp_m + (lane & 15);
    ra[1] = ra[0] + 16;
    const int ca = lane >> 4;
    int rB[4];
    #pragma unroll
    for (int nb = 0; nb < 4; nb++)
        rB[nb] = warp_n + nb * 16 + ((lane >> 4) & 1) * 8 + (lane & 7);
    const int kcB = (lane >> 3) & 1;

    auto compute = [&](int buf) {
        uint32_t base = sb + buf * STGN;
        #pragma unroll
        for (int ks = 0; ks < 4; ks++) {
            uint32_t ah[2][4], al[2][4], bb[4][4];
            #pragma unroll
            for (int mb = 0; mb < 2; mb++) {
                uint32_t off = ra[mb] * 128 + (((ks*2 + ca) ^ (ra[mb] & 7)) * 16);
                ldm4(ah[mb], base + off);
                ldm4(al[mb], base + SUBT + off);
            }
            #pragma unroll
            for (int nb = 0; nb < 4; nb++) {
                uint32_t off = rB[nb] * 128 + (((ks*2 + kcB) ^ (rB[nb] & 7)) * 16);
                ldm4(bb[nb], base + 2*SUBT + off);
            }
            #pragma unroll
            for (int mb = 0; mb < 2; mb++)
                #pragma unroll
                for (int nb = 0; nb < 4; nb++) {
                    mma16816h(acc[mb][nb*2],   ah[mb], bb[nb][0], bb[nb][1]);
                    mma16816h(acc[mb][nb*2+1], ah[mb], bb[nb][2], bb[nb][3]);
                }
            #pragma unroll
            for (int mb = 0; mb < 2; mb++)
                #pragma unroll
                for (int nb = 0; nb < 4; nb++) {
                    mma16816h(acc[mb][nb*2],   al[mb], bb[nb][0], bb[nb][1]);
                    mma16816h(acc[mb][nb*2+1], al[mb], bb[nb][2], bb[nb][3]);
                }
        }
    };

    load_stage(0, 0);
    CP_COMMIT();
    if (nch > 1) { load_stage(1, 64); CP_COMMIT(); }
    for (int c = 0; c < nch; c++) {
        if (c == nch - 1) cp_wait<0>(); else cp_wait<1>();
        __syncthreads();
        compute(c % 3);
        int nx = c + 2;
        if (nx < nch) { load_stage(nx % 3, nx << 6); CP_COMMIT(); }
    }

    const int gid = lane >> 2, qid = lane & 3;
    #pragma unroll
    for (int mb = 0; mb < 2; mb++) {
        #pragma unroll
        for (int nf = 0; nf < 8; nf++) {
            int n = n0 + warp_n + nf * 8 + qid * 2;
            #pragma unroll
            for (int hh = 0; hh < 2; hh++) {
                int m = m0 + warp_m + mb * 16 + gid + hh * 8;
                float vx = acc[mb][nf][hh*2];
                float vy = acc[mb][nf][hh*2 + 1];
                vx += bias[n]; vy += bias[n + 1];
                size_t o = (size_t)m * Nout + n;
                float2 r = *reinterpret_cast<const float2*>(resid + o);
                vx += r.x; vy += r.y;
                *reinterpret_cast<float2*>(C + o) = make_float2(vx, vy);
            }
        }
    }
}

// ---------------------------------------------------------------------------
// LM-head GEMM: fp16 1-pass, CTA 128x256, 8 warps (2x4), warp tile 64x64.
// ---------------------------------------------------------------------------
#define STGL (3*SUBT)                   // 48KB
#define GL_SMEM (3*STGL)                // 147456

__global__ __launch_bounds__(256, 1)
void gemm_lm(const __half* __restrict__ A, const __half* __restrict__ B,
             float* __restrict__ C, int Nout, int K) {
    extern __shared__ char smem[];
    uint32_t sb = smem_u32(smem);
    const int tid = threadIdx.x;
    const int lane = tid & 31, wid = tid >> 5;
    const int m0 = blockIdx.y * 128, n0 = blockIdx.x * 256;
    const int warp_m = (wid >> 2) * 64;
    const int warp_n = (wid & 3) * 64;

    float acc[4][8][4];
    #pragma unroll
    for (int i = 0; i < 4; i++)
        #pragma unroll
        for (int j = 0; j < 8; j++)
            #pragma unroll
            for (int e = 0; e < 4; e++) acc[i][j][e] = 0.f;

    const int nch = K >> 6;   // 8

    auto load_stage = [&](int buf, int k0) {
        uint32_t base = sb + buf * STGL;
        #pragma unroll
        for (int it = 0; it < 4; it++) {
            int u = tid + it * 256;
            int row = u >> 3, c = u & 7;
            uint32_t dst = base + row * 128 + ((c ^ (row & 7)) * 16);
            cp_async16(dst, A + (size_t)(m0 + row) * K + k0 + c * 8, 16);
        }
        #pragma unroll
        for (int it = 0; it < 8; it++) {
            int u = tid + it * 256;
            int row = u >> 3, c = u & 7;
            uint32_t dst = base + SUBT + row * 128 + ((c ^ (row & 7)) * 16);
            const __half* g = B + (size_t)(n0 + row) * K + k0 + c * 8;
            int sz = 16;
            if (n0 + row >= Nout) { g = B; sz = 0; }
            cp_async16(dst, g, sz);
        }
    };

    int ra[4];
    #pragma unroll
    for (int mb = 0; mb < 4; mb++) ra[mb] = warp_m + mb * 16 + (lane & 15);
    const int ca = lane >> 4;
    int rB[4];
    #pragma unroll
    for (int nb = 0; nb < 4; nb++)
        rB[nb] = warp_n + nb * 16 + ((lane >> 4) & 1) * 8 + (lane & 7);
    const int kcB = (lane >> 3) & 1;

    auto compute = [&](int buf) {
        uint32_t base = sb + buf * STGL;
        #pragma unroll
        for (int ks = 0; ks < 4; ks++) {
            uint32_t a[4][4], b[4][4];
            #pragma unroll
            for (int mb = 0; mb < 4; mb++) {
                uint32_t off = ra[mb] * 128 + (((ks*2 + ca) ^ (ra[mb] & 7)) * 16);
                ldm4(a[mb], base + off);
            }
            #pragma unroll
            for (int nb = 0; nb < 4; nb++) {
                uint32_t off = rB[nb] * 128 + (((ks*2 + kcB) ^ (rB[nb] & 7)) * 16);
                ldm4(b[nb], base + SUBT + off);
            }
            #pragma unroll
            for (int mb = 0; mb < 4; mb++)
                #pragma unroll
                for (int nb = 0; nb < 4; nb++) {
                    mma16816h(acc[mb][nb*2],   a[mb], b[nb][0], b[nb][1]);
                    mma16816h(acc[mb][nb*2+1], a[mb], b[nb][2], b[nb][3]);
                }
        }
    };

    load_stage(0, 0);
    CP_COMMIT();
    load_stage(1, 64);
    CP_COMMIT();
    for (int c = 0; c < nch; c++) {
        if (c == nch - 1) cp_wait<0>(); else cp_wait<1>();
        __syncthreads();
        compute(c % 3);
        int nx = c + 2;
        if (nx < nch) { load_stage(nx % 3, nx << 6); CP_COMMIT(); }
    }

    const int gid = lane >> 2, qid = lane & 3;
    #pragma unroll
    for (int mb = 0; mb < 4; mb++) {
        #pragma unroll
        for (int nf = 0; nf < 8; nf++) {
            int n = n0 + warp_n + nf * 8 + qid * 2;
            #pragma unroll
            for (int hh = 0; hh < 2; hh++) {
                int m = m0 + warp_m + mb * 16 + gid + hh * 8;
                float vx = acc[mb][nf][hh*2];
                float vy = acc[mb][nf][hh*2 + 1];
                size_t o = (size_t)m * Nout + n;
                if (n < Nout)     C[o]     = vx;
                if (n + 1 < Nout) C[o + 1] = vy;
            }
        }
    }
}

// ---------------------------------------------------------------------------
// Tensor-core causal flash attention (fp16 mma, fp32 softmax).
// CTA: 128 thr (4 warps), 64 queries (16/warp). grid (S/64, B*H).
// ---------------------------------------------------------------------------
__global__ __launch_bounds__(128)
void attn_mma(const __half* __restrict__ qkv,
              __half* __restrict__ ctx_hi,
              __half* __restrict__ ctx_lo) {
    __shared__ __align__(16) char sQ[8192];
    __shared__ __align__(16) char sK[2][8192];
    __shared__ __align__(16) char sV[2][8192];
    int bh = blockIdx.y;
    int b = bh >> 3, h = bh & 7;
    int qb = gridDim.x - 1 - blockIdx.x;      // heavy blocks first
    int tid = threadIdx.x, lane = tid & 31, wid = tid >> 5;
    int warp_q = wid * 16;
    const int gid = lane >> 2, qid = lane & 3;
    uint32_t sQb = smem_u32(sQ);
    uint32_t sKb[2] = {smem_u32(sK[0]), smem_u32(sK[1])};
    uint32_t sVb[2] = {smem_u32(sV[0]), smem_u32(sV[1])};

    size_t tokbase = (size_t)b * SS;

    #pragma unroll
    for (int it = 0; it < 4; it++) {
        int u = tid + it * 128;
        int row = u >> 3, c = u & 7;
        uint32_t dst = sQb + row * 128 + ((c ^ (row & 7)) * 16);
        const __half* g = qkv + (tokbase + qb*64 + row) * QKVD + h*DH + c*8;
        cp_async16(dst, g, 16);
    }
    auto load_kv = [&](int buf, int t) {
        #pragma unroll
        for (int it = 0; it < 4; it++) {
            int u = tid + it * 128;
            int row = u >> 3, c = u & 7;
            uint32_t sw = row * 128 + ((c ^ (row & 7)) * 16);
            const __half* gk = qkv + (tokbase + t*64 + row) * QKVD + DD + h*DH + c*8;
            const __half* gv = qkv + (tokbase + t*64 + row) * QKVD + 2*DD + h*DH + c*8;
            cp_async16(sKb[buf] + sw, gk, 16);
            cp_async16(sVb[buf] + sw, gv, 16);
        }
    };
    load_kv(0, 0);
    CP_COMMIT();
    cp_wait<0>();
    __syncthreads();

    uint32_t qa[4][4];
    {
        int r = warp_q + (lane & 15);
        int chalf = lane >> 4;
        #pragma unroll
        for (int ks = 0; ks < 4; ks++) {
            int c = ks*2 + chalf;
            ldm4(qa[ks], sQb + r * 128 + ((c ^ (r & 7)) * 16));
        }
    }

    float m0v = -1e30f, m1v = -1e30f, l0 = 0.f, l1 = 0.f;
    float oacc[8][4];
    #pragma unroll
    for (int i = 0; i < 8; i++)
        #pragma unroll
        for (int e = 0; e < 4; e++) oacc[i][e] = 0.f;

    const int rloc0 = warp_q + gid;

    for (int t = 0; t <= qb; t++) {
        int buf = t & 1;
        if (t < qb) { load_kv(buf ^ 1, t + 1); CP_COMMIT(); }

        float sacc[8][4];
        #pragma unroll
        for (int i = 0; i < 8; i++)
            #pragma unroll
            for (int e = 0; e < 4; e++) sacc[i][e] = 0.f;
        {
            int rb = ((lane >> 4) & 1) * 8 + (lane & 7);
            int kc = (lane >> 3) & 1;
            #pragma unroll
            for (int ks = 0; ks < 4; ks++) {
                uint32_t kb[4][4];
                #pragma unroll
                for (int nb = 0; nb < 4; nb++) {
                    int r = nb*16 + rb;
                    int c = ks*2 + kc;
                    ldm4(kb[nb], sKb[buf] + r * 128 + ((c ^ (r & 7)) * 16));
                }
                #pragma unroll
                for (int nb = 0; nb < 4; nb++) {
                    mma16816h(sacc[nb*2],   qa[ks], kb[nb][0], kb[nb][1]);
                    mma16816h(sacc[nb*2+1], qa[ks], kb[nb][2], kb[nb][3]);
                }
            }
        }
        #pragma unroll
        for (int i = 0; i < 8; i++)
            #pragma unroll
            for (int e = 0; e < 4; e++) sacc[i][e] *= 0.125f;
        if (t == qb) {
            #pragma unroll
            for (int i = 0; i < 8; i++) {
                int col = i*8 + qid*2;
                #pragma unroll
                for (int e = 0; e < 4; e++) {
                    int cc = col + (e & 1);
                    int rr = rloc0 + ((e >> 1) * 8);
                    if (cc > rr) sacc[i][e] = -1e30f;
                }
            }
        }
        float rmax0 = -1e30f, rmax1 = -1e30f;
        #pragma unroll
        for (int i = 0; i < 8; i++) {
            rmax0 = fmaxf(rmax0, fmaxf(sacc[i][0], sacc[i][1]));
            rmax1 = fmaxf(rmax1, fmaxf(sacc[i][2], sacc[i][3]));
        }
        #pragma unroll
        for (int o = 1; o <= 2; o <<= 1) {
            rmax0 = fmaxf(rmax0, __shfl_xor_sync(0xffffffffu, rmax0, o));
            rmax1 = fmaxf(rmax1, __shfl_xor_sync(0xffffffffu, rmax1, o));
        }
        float mn0 = fmaxf(m0v, rmax0), mn1 = fmaxf(m1v, rmax1);
        float cor0 = __expf(m0v - mn0), cor1 = __expf(m1v - mn1);
        m0v = mn0; m1v = mn1;
        float rs0 = 0.f, rs1 = 0.f;
        float p[8][4];
        #pragma unroll
        for (int i = 0; i < 8; i++) {
            p[i][0] = __expf(sacc[i][0] - mn0);
            p[i][1] = __expf(sacc[i][1] - mn0);
            p[i][2] = __expf(sacc[i][2] - mn1);
            p[i][3] = __expf(sacc[i][3] - mn1);
            rs0 += p[i][0] + p[i][1];
            rs1 += p[i][2] + p[i][3];
        }
        #pragma unroll
        for (int o = 1; o <= 2; o <<= 1) {
            rs0 += __shfl_xor_sync(0xffffffffu, rs0, o);
            rs1 += __shfl_xor_sync(0xffffffffu, rs1, o);
        }
        l0 = l0 * cor0 + rs0;
        l1 = l1 * cor1 + rs1;
        #pragma unroll
        for (int i = 0; i < 8; i++) {
            oacc[i][0] *= cor0; oacc[i][1] *= cor0;
            oacc[i][2] *= cor1; oacc[i][3] *= cor1;
        }
        uint32_t pa[4][4];
        #pragma unroll
        for (int kk = 0; kk < 4; kk++) {
            pa[kk][0] = packh2(p[2*kk][0],   p[2*kk][1]);
            pa[kk][1] = packh2(p[2*kk][2],   p[2*kk][3]);
            pa[kk][2] = packh2(p[2*kk+1][0], p[2*kk+1][1]);
            pa[kk][3] = packh2(p[2*kk+1][2], p[2*kk+1][3]);
        }
        {
            int rv = ((lane >> 3) & 1) * 8 + (lane & 7);
            int cv = lane >> 4;
            #pragma unroll
            for (int kk = 0; kk < 4; kk++) {
                uint32_t vb[4][4];
                #pragma unroll
                for (int nd = 0; nd < 4; nd++) {
                    int r = kk*16 + rv;
                    int c = nd*2 + cv;
                    ldm4t(vb[nd], sVb[buf] + r * 128 + ((c ^ (r & 7)) * 16));
                }
                #pragma unroll
                for (int nd = 0; nd < 4; nd++) {
                    mma16816h(oacc[nd*2],   pa[kk], vb[nd][0], vb[nd][1]);
                    mma16816h(oacc[nd*2+1], pa[kk], vb[nd][2], vb[nd][3]);
                }
            }
        }
        if (t < qb) cp_wait<0>();
        __syncthreads();
    }

    float inv0 = 1.0f / l0, inv1 = 1.0f / l1;
    size_t tok0 = tokbase + qb*64 + rloc0;
    #pragma unroll
    for (int nd = 0; nd < 8; nd++) {
        int col = h*DH + nd*8 + qid*2;
        {
            float ox = oacc[nd][0] * inv0, oy = oacc[nd][1] * inv0;
            uint32_t hh, ll;
            split2h(ox, oy, hh, ll);
            size_t o = tok0 * DD + col;
            *reinterpret_cast<uint32_t*>(ctx_hi + o) = hh;
            *reinterpret_cast<uint32_t*>(ctx_lo + o) = ll;
        }
        {
            float ox = oacc[nd][2] * inv1, oy = oacc[nd][3] * inv1;
            uint32_t hh, ll;
            split2h(ox, oy, hh, ll);
            size_t o = (tok0 + 8) * DD + col;
            *reinterpret_cast<uint32_t*>(ctx_hi + o) = hh;
            *reinterpret_cast<uint32_t*>(ctx_lo + o) = ll;
        }
    }
}

// ---------------------------------------------------------------------------
// Host launch
// ---------------------------------------------------------------------------
extern "C" void kernel_launch(void* const* d_in, const int* in_sizes, int n_in,
                              void* d_out, int out_size) {
    const int*   ids   = (const int*)  d_in[0];
    const float* emb   = (const float*)d_in[1];
    const float* pe    = (const float*)d_in[2];
    const float* wq    = (const float*)d_in[3];
    const float* wk    = (const float*)d_in[4];
    const float* wv    = (const float*)d_in[5];
    const float* wo    = (const float*)d_in[6];
    const float* wo_b  = (const float*)d_in[7];
    const float* w1    = (const float*)d_in[8];
    const float* b1    = (const float*)d_in[9];
    const float* w2    = (const float*)d_in[10];
    const float* b2    = (const float*)d_in[11];
    const float* ln1_g = (const float*)d_in[12];
    const float* ln1_b = (const float*)d_in[13];
    const float* ln2_g = (const float*)d_in[14];
    const float* ln2_b = (const float*)d_in[15];
    const float* lnf_g = (const float*)d_in[16];
    const float* lnf_b = (const float*)d_in[17];
    float* out = (float*)d_out;

    float *x;
    __half *qkvh, *h_hi, *h_lo, *ctx_hi, *ctx_lo, *ff_hi, *ff_lo;
    __half *wqkvT, *woT, *w1T, *w2T, *hf, *embH;
    cudaGetSymbolAddress((void**)&x, g_x);
    cudaGetSymbolAddress((void**)&qkvh, g_qkvh);
    cudaGetSymbolAddress((void**)&h_hi, g_h_hi);
    cudaGetSymbolAddress((void**)&h_lo, g_h_lo);
    cudaGetSymbolAddress((void**)&ctx_hi, g_ctx_hi);
    cudaGetSymbolAddress((void**)&ctx_lo, g_ctx_lo);
    cudaGetSymbolAddress((void**)&ff_hi, g_ff_hi);
    cudaGetSymbolAddress((void**)&ff_lo, g_ff_lo);
    cudaGetSymbolAddress((void**)&wqkvT, g_wqkvT);
    cudaGetSymbolAddress((void**)&woT, g_woT);
    cudaGetSymbolAddress((void**)&w1T, g_w1T);
    cudaGetSymbolAddress((void**)&w2T, g_w2T);
    cudaGetSymbolAddress((void**)&hf, g_hf);
    cudaGetSymbolAddress((void**)&embH, g_embH);

    cudaFuncSetAttribute(gemm_w<0, 2>, cudaFuncAttributeMaxDynamicSharedMemorySize, GW_SMEM);
    cudaFuncSetAttribute(gemm_w<3, 3>, cudaFuncAttributeMaxDynamicSharedMemorySize, GW_SMEM);
    cudaFuncSetAttribute(gemm_n, cudaFuncAttributeMaxDynamicSharedMemorySize, GN_SMEM);
    cudaFuncSetAttribute(gemm_lm, cudaFuncAttributeMaxDynamicSharedMemorySize, GL_SMEM);

    // weight conversions (fp16 single, transposed)
    dim3 cb(32, 8);
    conv_wTh<<<dim3(DD/32, DD/32), cb>>>(wq, wqkvT,           DD, DD);
    conv_wTh<<<dim3(DD/32, DD/32), cb>>>(wk, wqkvT + DD*DD,   DD, DD);
    conv_wTh<<<dim3(DD/32, DD/32), cb>>>(wv, wqkvT + 2*DD*DD, DD, DD);
    conv_wTh<<<dim3(DD/32, DD/32), cb>>>(wo, woT, DD, DD);
    conv_wTh<<<dim3(FFD/32, DD/32), cb>>>(w1, w1T, DD, FFD);
    conv_wTh<<<dim3(DD/32, FFD/32), cb>>>(w2, w2T, FFD, DD);
    {
        int n4 = VV * DD / 4;
        conv_half4<<<(n4 + 255) / 256, 256>>>(emb, embH, n4);
    }

    embed_kernel<<<NN, 128>>>(ids, emb, pe, x);

    dim3 gQKV(QKVD/256, NN/128);     // (6, 32)
    dim3 gProj(DD/128, NN/128);      // (4, 32)
    dim3 gFF1(FFD/256, NN/128);      // (8, 32)
    dim3 gAttn(SS/64, BB*HH);        // (16, 32)

    for (int layer = 0; layer < NLAYERS; layer++) {
        ln_kernel<0><<<NN, 128>>>(x, (uint32_t*)h_hi, (uint32_t*)h_lo, ln1_g, ln1_b);
        gemm_w<0, 2><<<gQKV, 256, GW_SMEM>>>(
            h_hi, h_lo, wqkvT, nullptr, nullptr, nullptr, qkvh, QKVD, DD);
        attn_mma<<<gAttn, 128>>>(qkvh, ctx_hi, ctx_lo);
        gemm_n<<<gProj, 256, GN_SMEM>>>(
            ctx_hi, ctx_lo, woT, wo_b, x, x, DD, DD);
        ln_kernel<0><<<NN, 128>>>(x, (uint32_t*)h_hi, (uint32_t*)h_lo, ln2_g, ln2_b);
        gemm_w<3, 3><<<gFF1, 256, GW_SMEM>>>(
            h_hi, h_lo, w1T, b1, ff_hi, ff_lo, nullptr, FFD, DD);
        gemm_n<<<gProj, 256, GN_SMEM>>>(
            ff_hi, ff_lo, w2T, b2, x, x, DD, FFD);
    }

    ln_kernel<2><<<NN, 128>>>(x, (uint32_t*)hf, nullptr, lnf_g, lnf_b);

    dim3 gLM((VV + 255) / 256, NN / 128);   // (197, 32)
    gemm_lm<<<gLM, 256, GL_SMEM>>>(hf, embH, out, VV, DD);
}

// round 12
// speedup vs baseline: 6.9680x; 1.2297x over previous
#include <cuda_runtime.h>
#include <cuda_bf16.h>
#include <cuda_fp16.h>
#include <math.h>
#include <stdint.h>

// Problem constants
#define BB 4
#define SS 1024
#define NN (BB*SS)      // 4096 tokens
#define DD 512
#define HH 8
#define DH 64
#define FFD 2048
#define VV 50257
#define NLAYERS 6
#define QKVD 1536       // fused qkv width

// ---------------------------------------------------------------------------
// Scratch (allocation-free: __device__ globals) — all activations single fp16
// ---------------------------------------------------------------------------
__device__ float g_x[NN*DD];
__device__ __half g_h[NN*DD];
__device__ __half g_qkvh[NN*QKVD];
__device__ __half g_ctx[NN*DD];
__device__ __half g_ff[NN*FFD];
// transposed fp16 weights [N,K]
__device__ __half g_wqkvT[3*DD*DD];
__device__ __half g_woT[DD*DD];
__device__ __half g_w1T[FFD*DD];
__device__ __half g_w2T[DD*FFD];
// LM head
__device__ __half g_hf[NN*DD];
__device__ __half g_embH[VV*DD];

// ---------------------------------------------------------------------------
// Helpers
// ---------------------------------------------------------------------------
__device__ __forceinline__ uint32_t smem_u32(const void* p) {
    uint32_t a;
    asm("{ .reg .u64 t; cvta.to.shared.u64 t, %1; cvt.u32.u64 %0, t; }"
        : "=r"(a) : "l"(p));
    return a;
}

__device__ __forceinline__ void ldm4(uint32_t* r, uint32_t addr) {
    asm volatile("ldmatrix.sync.aligned.m8n8.x4.shared.b16 {%0,%1,%2,%3}, [%4];"
                 : "=r"(r[0]), "=r"(r[1]), "=r"(r[2]), "=r"(r[3]) : "r"(addr));
}
__device__ __forceinline__ void ldm4t(uint32_t* r, uint32_t addr) {
    asm volatile("ldmatrix.sync.aligned.m8n8.x4.trans.shared.b16 {%0,%1,%2,%3}, [%4];"
                 : "=r"(r[0]), "=r"(r[1]), "=r"(r[2]), "=r"(r[3]) : "r"(addr));
}

__device__ __forceinline__ void mma16816h(float* c, const uint32_t* a,
                                          uint32_t b0, uint32_t b1) {
    asm volatile(
        "mma.sync.aligned.m16n8k16.row.col.f32.f16.f16.f32 "
        "{%0,%1,%2,%3}, {%4,%5,%6,%7}, {%8,%9}, {%0,%1,%2,%3};"
        : "+f"(c[0]), "+f"(c[1]), "+f"(c[2]), "+f"(c[3])
        : "r"(a[0]), "r"(a[1]), "r"(a[2]), "r"(a[3]), "r"(b0), "r"(b1));
}

__device__ __forceinline__ void cp_async16(uint32_t dst, const void* src, int szbytes) {
    asm volatile("cp.async.cg.shared.global [%0], [%1], 16, %2;"
                 :: "r"(dst), "l"(src), "r"(szbytes));
}
#define CP_COMMIT() asm volatile("cp.async.commit_group;" ::: "memory")
template<int N>
__device__ __forceinline__ void cp_wait() {
    asm volatile("cp.async.wait_group %0;" :: "n"(N) : "memory");
}

__device__ __forceinline__ uint32_t packh2(float x, float y) {
    __half2 t = __floats2half2_rn(x, y);
    return *reinterpret_cast<uint32_t*>(&t);
}

__device__ __forceinline__ float gelu_exact(float v) {
    return 0.5f * v * (1.0f + erff(v * 0.70710678118654752f));
}

// ---------------------------------------------------------------------------
// Weight conversion: W [K,N] fp32 -> fp16 [N,K] (transpose)
// ---------------------------------------------------------------------------
__global__ void conv_wTh(const float* __restrict__ W, __half* __restrict__ o16,
                         int K, int N) {
    __shared__ float t[32][33];
    int n0 = blockIdx.x * 32, k0 = blockIdx.y * 32;
    int tx = threadIdx.x, ty = threadIdx.y;
    #pragma unroll
    for (int r = 0; r < 4; r++)
        t[ty + r*8][tx] = W[(size_t)(k0 + ty + r*8) * N + n0 + tx];
    __syncthreads();
    #pragma unroll
    for (int r = 0; r < 4; r++)
        o16[(size_t)(n0 + ty + r*8) * K + k0 + tx] = __float2half_rn(t[tx][ty + r*8]);
}

// Elementwise fp32 -> fp16
__global__ void conv_half4(const float* __restrict__ src,
                           __half* __restrict__ dst, int n4) {
    int i = blockIdx.x * 256 + threadIdx.x;
    if (i >= n4) return;
    float4 v = reinterpret_cast<const float4*>(src)[i];
    uint2 o;
    o.x = packh2(v.x, v.y);
    o.y = packh2(v.z, v.w);
    reinterpret_cast<uint2*>(dst)[i] = o;
}

// ---------------------------------------------------------------------------
// Embedding
// ---------------------------------------------------------------------------
__global__ void embed_kernel(const int* __restrict__ ids,
                             const float* __restrict__ emb,
                             const float* __restrict__ pe,
                             float* __restrict__ x) {
    int n = blockIdx.x;
    int tid = threadIdx.x;
    int id = ids[n];
    int s = n & (SS - 1);
    const float sq = 22.62741699796952f;
    float4 e = reinterpret_cast<const float4*>(emb + (size_t)id * DD)[tid];
    float4 p = reinterpret_cast<const float4*>(pe + (size_t)s * DD)[tid];
    float4 o;
    o.x = e.x * sq + p.x; o.y = e.y * sq + p.y;
    o.z = e.z * sq + p.z; o.w = e.w * sq + p.w;
    reinterpret_cast<float4*>(x + (size_t)n * DD)[tid] = o;
}

// ---------------------------------------------------------------------------
// LayerNorm -> single fp16
// ---------------------------------------------------------------------------
__global__ void ln_kernel(const float* __restrict__ in,
                          uint32_t* __restrict__ out16,
                          const float* __restrict__ g, const float* __restrict__ b) {
    int row = blockIdx.x;
    int tid = threadIdx.x;    // 128
    float4 v = reinterpret_cast<const float4*>(in + (size_t)row * DD)[tid];
    float s = v.x + v.y + v.z + v.w;
    float ss = v.x*v.x + v.y*v.y + v.z*v.z + v.w*v.w;
    #pragma unroll
    for (int o = 16; o > 0; o >>= 1) {
        s  += __shfl_xor_sync(0xffffffffu, s, o);
        ss += __shfl_xor_sync(0xffffffffu, ss, o);
    }
    __shared__ float rs[4], rss[4];
    int warp = tid >> 5;
    if ((tid & 31) == 0) { rs[warp] = s; rss[warp] = ss; }
    __syncthreads();
    float mean = (rs[0]+rs[1]+rs[2]+rs[3]) * (1.0f/DD);
    float var  = (rss[0]+rss[1]+rss[2]+rss[3]) * (1.0f/DD) - mean*mean;
    float rstd = rsqrtf(var + 1e-5f);
    float4 gg = reinterpret_cast<const float4*>(g)[tid];
    float4 bb = reinterpret_cast<const float4*>(b)[tid];
    float4 o;
    o.x = (v.x - mean)*rstd*gg.x + bb.x;
    o.y = (v.y - mean)*rstd*gg.y + bb.y;
    o.z = (v.z - mean)*rstd*gg.z + bb.z;
    o.w = (v.w - mean)*rstd*gg.w + bb.w;
    uint2 hh;
    hh.x = packh2(o.x, o.y);
    hh.y = packh2(o.z, o.w);
    reinterpret_cast<uint2*>(out16)[(size_t)row * (DD/4) + tid] = hh;
}

#define SUBT 16384                      // 128 rows x 128B

// ---------------------------------------------------------------------------
// Wide GEMM (qkv, ff1, LM head): fp16 1-pass, CTA 128x256, 8 warps (2M x 4N),
// warp tile 64x64, 3-stage. Stage = A16 + B32 = 48KB.
// EPI: 1=bias, 2=gelu. OUT: 0=f32 guarded (LM), 2=fp16.
// ---------------------------------------------------------------------------
#define STGW (3*SUBT)                   // 48KB
#define GW_SMEM (3*STGW)                // 147456

template<int EPI, int OUT, bool GUARD>
__global__ __launch_bounds__(256, 1)
void gemm_w(const __half* __restrict__ A, const __half* __restrict__ B,
            const float* __restrict__ bias,
            float* __restrict__ C, __half* __restrict__ Ch,
            int Nout, int K) {
    extern __shared__ char smem[];
    uint32_t sb = smem_u32(smem);
    const int tid = threadIdx.x;
    const int lane = tid & 31, wid = tid >> 5;
    const int m0 = blockIdx.y * 128, n0 = blockIdx.x * 256;
    const int warp_m = (wid >> 2) * 64;
    const int warp_n = (wid & 3) * 64;

    float acc[4][8][4];
    #pragma unroll
    for (int i = 0; i < 4; i++)
        #pragma unroll
        for (int j = 0; j < 8; j++)
            #pragma unroll
            for (int e = 0; e < 4; e++) acc[i][j][e] = 0.f;

    const int nch = K >> 6;   // 8

    auto load_stage = [&](int buf, int k0) {
        uint32_t base = sb + buf * STGW;
        #pragma unroll
        for (int it = 0; it < 4; it++) {
            int u = tid + it * 256;
            int row = u >> 3, c = u & 7;
            uint32_t dst = base + row * 128 + ((c ^ (row & 7)) * 16);
            cp_async16(dst, A + (size_t)(m0 + row) * K + k0 + c * 8, 16);
        }
        #pragma unroll
        for (int it = 0; it < 8; it++) {
            int u = tid + it * 256;
            int row = u >> 3, c = u & 7;
            uint32_t dst = base + SUBT + row * 128 + ((c ^ (row & 7)) * 16);
            const __half* g = B + (size_t)(n0 + row) * K + k0 + c * 8;
            int sz = 16;
            if (GUARD && (n0 + row >= Nout)) { g = B; sz = 0; }
            cp_async16(dst, g, sz);
        }
    };

    int ra[4];
    #pragma unroll
    for (int mb = 0; mb < 4; mb++) ra[mb] = warp_m + mb * 16 + (lane & 15);
    const int ca = lane >> 4;
    int rB[4];
    #pragma unroll
    for (int nb = 0; nb < 4; nb++)
        rB[nb] = warp_n + nb * 16 + ((lane >> 4) & 1) * 8 + (lane & 7);
    const int kcB = (lane >> 3) & 1;

    auto compute = [&](int buf) {
        uint32_t base = sb + buf * STGW;
        #pragma unroll
        for (int ks = 0; ks < 4; ks++) {
            uint32_t a[4][4], b[4][4];
            #pragma unroll
            for (int mb = 0; mb < 4; mb++) {
                uint32_t off = ra[mb] * 128 + (((ks*2 + ca) ^ (ra[mb] & 7)) * 16);
                ldm4(a[mb], base + off);
            }
            #pragma unroll
            for (int nb = 0; nb < 4; nb++) {
                uint32_t off = rB[nb] * 128 + (((ks*2 + kcB) ^ (rB[nb] & 7)) * 16);
                ldm4(b[nb], base + SUBT + off);
            }
            #pragma unroll
            for (int mb = 0; mb < 4; mb++)
                #pragma unroll
                for (int nb = 0; nb < 4; nb++) {
                    mma16816h(acc[mb][nb*2],   a[mb], b[nb][0], b[nb][1]);
                    mma16816h(acc[mb][nb*2+1], a[mb], b[nb][2], b[nb][3]);
                }
        }
    };

    load_stage(0, 0);
    CP_COMMIT();
    load_stage(1, 64);
    CP_COMMIT();
    for (int c = 0; c < nch; c++) {
        if (c == nch - 1) cp_wait<0>(); else cp_wait<1>();
        __syncthreads();
        compute(c % 3);
        int nx = c + 2;
        if (nx < nch) { load_stage(nx % 3, nx << 6); CP_COMMIT(); }
    }

    const int gid = lane >> 2, qid = lane & 3;
    #pragma unroll
    for (int mb = 0; mb < 4; mb++) {
        #pragma unroll
        for (int nf = 0; nf < 8; nf++) {
            int n = n0 + warp_n + nf * 8 + qid * 2;
            #pragma unroll
            for (int hh = 0; hh < 2; hh++) {
                int m = m0 + warp_m + mb * 16 + gid + hh * 8;
                float vx = acc[mb][nf][hh*2];
                float vy = acc[mb][nf][hh*2 + 1];
                if (EPI & 1) { vx += bias[n]; vy += bias[n + 1]; }
                if (EPI & 2) { vx = gelu_exact(vx); vy = gelu_exact(vy); }
                size_t o = (size_t)m * Nout + n;
                if (OUT == 2) {
                    *reinterpret_cast<uint32_t*>(Ch + o) = packh2(vx, vy);
                } else {
                    // scalar f32 stores (Nout may be odd -> no vector stores)
                    if (!GUARD || n < Nout)     C[o]     = vx;
                    if (!GUARD || n + 1 < Nout) C[o + 1] = vy;
                }
            }
        }
    }
}

// ---------------------------------------------------------------------------
// Narrow layer GEMM (wo, ff2): fp16 1-pass, CTA 128x128, 8 warps (4M x 2N),
// warp tile 32x64, 3-stage. Stage = A16 + B16 = 32KB.
// Output: fp32 x with bias+residual.
// ---------------------------------------------------------------------------
#define STGN (2*SUBT)                   // 32KB
#define GN_SMEM (3*STGN)                // 98304

__global__ __launch_bounds__(256, 1)
void gemm_n(const __half* __restrict__ A, const __half* __restrict__ B,
            const float* __restrict__ bias, const float* __restrict__ resid,
            float* __restrict__ C, int Nout, int K) {
    extern __shared__ char smem[];
    uint32_t sb = smem_u32(smem);
    const int tid = threadIdx.x;
    const int lane = tid & 31, wid = tid >> 5;
    const int m0 = blockIdx.y * 128, n0 = blockIdx.x * 128;
    const int warp_m = (wid >> 1) * 32;
    const int warp_n = (wid & 1) * 64;

    float acc[2][8][4];
    #pragma unroll
    for (int i = 0; i < 2; i++)
        #pragma unroll
        for (int j = 0; j < 8; j++)
            #pragma unroll
            for (int e = 0; e < 4; e++) acc[i][j][e] = 0.f;

    const int nch = K >> 6;

    auto load_stage = [&](int buf, int k0) {
        uint32_t base = sb + buf * STGN;
        #pragma unroll
        for (int sub = 0; sub < 2; sub++) {
            const __half* P = sub ? B : A;
            int row0 = sub ? n0 : m0;
            uint32_t dbase = base + sub * SUBT;
            #pragma unroll
            for (int it = 0; it < 4; it++) {
                int u = tid + it * 256;
                int row = u >> 3, c = u & 7;
                uint32_t dst = dbase + row * 128 + ((c ^ (row & 7)) * 16);
                cp_async16(dst, P + (size_t)(row0 + row) * K + k0 + c * 8, 16);
            }
        }
    };

    int ra[2];
    ra[0] = warp_m + (lane & 15);
    ra[1] = ra[0] + 16;
    const int ca = lane >> 4;
    int rB[4];
    #pragma unroll
    for (int nb = 0; nb < 4; nb++)
        rB[nb] = warp_n + nb * 16 + ((lane >> 4) & 1) * 8 + (lane & 7);
    const int kcB = (lane >> 3) & 1;

    auto compute = [&](int buf) {
        uint32_t base = sb + buf * STGN;
        #pragma unroll
        for (int ks = 0; ks < 4; ks++) {
            uint32_t a[2][4], b[4][4];
            #pragma unroll
            for (int mb = 0; mb < 2; mb++) {
                uint32_t off = ra[mb] * 128 + (((ks*2 + ca) ^ (ra[mb] & 7)) * 16);
                ldm4(a[mb], base + off);
            }
            #pragma unroll
            for (int nb = 0; nb < 4; nb++) {
                uint32_t off = rB[nb] * 128 + (((ks*2 + kcB) ^ (rB[nb] & 7)) * 16);
                ldm4(b[nb], base + SUBT + off);
            }
            #pragma unroll
            for (int mb = 0; mb < 2; mb++)
                #pragma unroll
                for (int nb = 0; nb < 4; nb++) {
                    mma16816h(acc[mb][nb*2],   a[mb], b[nb][0], b[nb][1]);
                    mma16816h(acc[mb][nb*2+1], a[mb], b[nb][2], b[nb][3]);
                }
        }
    };

    load_stage(0, 0);
    CP_COMMIT();
    if (nch > 1) { load_stage(1, 64); CP_COMMIT(); }
    for (int c = 0; c < nch; c++) {
        if (c == nch - 1) cp_wait<0>(); else cp_wait<1>();
        __syncthreads();
        compute(c % 3);
        int nx = c + 2;
        if (nx < nch) { load_stage(nx % 3, nx << 6); CP_COMMIT(); }
    }

    const int gid = lane >> 2, qid = lane & 3;
    #pragma unroll
    for (int mb = 0; mb < 2; mb++) {
        #pragma unroll
        for (int nf = 0; nf < 8; nf++) {
            int n = n0 + warp_n + nf * 8 + qid * 2;
            #pragma unroll
            for (int hh = 0; hh < 2; hh++) {
                int m = m0 + warp_m + mb * 16 + gid + hh * 8;
                float vx = acc[mb][nf][hh*2];
                float vy = acc[mb][nf][hh*2 + 1];
                vx += bias[n]; vy += bias[n + 1];
                size_t o = (size_t)m * Nout + n;
                float2 r = *reinterpret_cast<const float2*>(resid + o);
                vx += r.x; vy += r.y;
                *reinterpret_cast<float2*>(C + o) = make_float2(vx, vy);
            }
        }
    }
}

// ---------------------------------------------------------------------------
// Tensor-core causal flash attention (fp16 mma, fp32 softmax).
// CTA: 128 thr (4 warps), 64 queries (16/warp). grid (S/64, B*H).
// ---------------------------------------------------------------------------
__global__ __launch_bounds__(128)
void attn_mma(const __half* __restrict__ qkv,
              __half* __restrict__ ctx) {
    __shared__ __align__(16) char sQ[8192];
    __shared__ __align__(16) char sK[2][8192];
    __shared__ __align__(16) char sV[2][8192];
    int bh = blockIdx.y;
    int b = bh >> 3, h = bh & 7;
    int qb = gridDim.x - 1 - blockIdx.x;      // heavy blocks first
    int tid = threadIdx.x, lane = tid & 31, wid = tid >> 5;
    int warp_q = wid * 16;
    const int gid = lane >> 2, qid = lane & 3;
    uint32_t sQb = smem_u32(sQ);
    uint32_t sKb[2] = {smem_u32(sK[0]), smem_u32(sK[1])};
    uint32_t sVb[2] = {smem_u32(sV[0]), smem_u32(sV[1])};

    size_t tokbase = (size_t)b * SS;

    #pragma unroll
    for (int it = 0; it < 4; it++) {
        int u = tid + it * 128;
        int row = u >> 3, c = u & 7;
        uint32_t dst = sQb + row * 128 + ((c ^ (row & 7)) * 16);
        const __half* g = qkv + (tokbase + qb*64 + row) * QKVD + h*DH + c*8;
        cp_async16(dst, g, 16);
    }
    auto load_kv = [&](int buf, int t) {
        #pragma unroll
        for (int it = 0; it < 4; it++) {
            int u = tid + it * 128;
            int row = u >> 3, c = u & 7;
            uint32_t sw = row * 128 + ((c ^ (row & 7)) * 16);
            const __half* gk = qkv + (tokbase + t*64 + row) * QKVD + DD + h*DH + c*8;
            const __half* gv = qkv + (tokbase + t*64 + row) * QKVD + 2*DD + h*DH + c*8;
            cp_async16(sKb[buf] + sw, gk, 16);
            cp_async16(sVb[buf] + sw, gv, 16);
        }
    };
    load_kv(0, 0);
    CP_COMMIT();
    cp_wait<0>();
    __syncthreads();

    uint32_t qa[4][4];
    {
        int r = warp_q + (lane & 15);
        int chalf = lane >> 4;
        #pragma unroll
        for (int ks = 0; ks < 4; ks++) {
            int c = ks*2 + chalf;
            ldm4(qa[ks], sQb + r * 128 + ((c ^ (r & 7)) * 16));
        }
    }

    float m0v = -1e30f, m1v = -1e30f, l0 = 0.f, l1 = 0.f;
    float oacc[8][4];
    #pragma unroll
    for (int i = 0; i < 8; i++)
        #pragma unroll
        for (int e = 0; e < 4; e++) oacc[i][e] = 0.f;

    const int rloc0 = warp_q + gid;

    for (int t = 0; t <= qb; t++) {
        int buf = t & 1;
        if (t < qb) { load_kv(buf ^ 1, t + 1); CP_COMMIT(); }

        float sacc[8][4];
        #pragma unroll
        for (int i = 0; i < 8; i++)
            #pragma unroll
            for (int e = 0; e < 4; e++) sacc[i][e] = 0.f;
        {
            int rb = ((lane >> 4) & 1) * 8 + (lane & 7);
            int kc = (lane >> 3) & 1;
            #pragma unroll
            for (int ks = 0; ks < 4; ks++) {
                uint32_t kb[4][4];
                #pragma unroll
                for (int nb = 0; nb < 4; nb++) {
                    int r = nb*16 + rb;
                    int c = ks*2 + kc;
                    ldm4(kb[nb], sKb[buf] + r * 128 + ((c ^ (r & 7)) * 16));
                }
                #pragma unroll
                for (int nb = 0; nb < 4; nb++) {
                    mma16816h(sacc[nb*2],   qa[ks], kb[nb][0], kb[nb][1]);
                    mma16816h(sacc[nb*2+1], qa[ks], kb[nb][2], kb[nb][3]);
                }
            }
        }
        #pragma unroll
        for (int i = 0; i < 8; i++)
            #pragma unroll
            for (int e = 0; e < 4; e++) sacc[i][e] *= 0.125f;
        if (t == qb) {
            #pragma unroll
            for (int i = 0; i < 8; i++) {
                int col = i*8 + qid*2;
                #pragma unroll
                for (int e = 0; e < 4; e++) {
                    int cc = col + (e & 1);
                    int rr = rloc0 + ((e >> 1) * 8);
                    if (cc > rr) sacc[i][e] = -1e30f;
                }
            }
        }
        float rmax0 = -1e30f, rmax1 = -1e30f;
        #pragma unroll
        for (int i = 0; i < 8; i++) {
            rmax0 = fmaxf(rmax0, fmaxf(sacc[i][0], sacc[i][1]));
            rmax1 = fmaxf(rmax1, fmaxf(sacc[i][2], sacc[i][3]));
        }
        #pragma unroll
        for (int o = 1; o <= 2; o <<= 1) {
            rmax0 = fmaxf(rmax0, __shfl_xor_sync(0xffffffffu, rmax0, o));
            rmax1 = fmaxf(rmax1, __shfl_xor_sync(0xffffffffu, rmax1, o));
        }
        float mn0 = fmaxf(m0v, rmax0), mn1 = fmaxf(m1v, rmax1);
        float cor0 = __expf(m0v - mn0), cor1 = __expf(m1v - mn1);
        m0v = mn0; m1v = mn1;
        float rs0 = 0.f, rs1 = 0.f;
        float p[8][4];
        #pragma unroll
        for (int i = 0; i < 8; i++) {
            p[i][0] = __expf(sacc[i][0] - mn0);
            p[i][1] = __expf(sacc[i][1] - mn0);
            p[i][2] = __expf(sacc[i][2] - mn1);
            p[i][3] = __expf(sacc[i][3] - mn1);
            rs0 += p[i][0] + p[i][1];
            rs1 += p[i][2] + p[i][3];
        }
        #pragma unroll
        for (int o = 1; o <= 2; o <<= 1) {
            rs0 += __shfl_xor_sync(0xffffffffu, rs0, o);
            rs1 += __shfl_xor_sync(0xffffffffu, rs1, o);
        }
        l0 = l0 * cor0 + rs0;
        l1 = l1 * cor1 + rs1;
        #pragma unroll
        for (int i = 0; i < 8; i++) {
            oacc[i][0] *= cor0; oacc[i][1] *= cor0;
            oacc[i][2] *= cor1; oacc[i][3] *= cor1;
        }
        uint32_t pa[4][4];
        #pragma unroll
        for (int kk = 0; kk < 4; kk++) {
            pa[kk][0] = packh2(p[2*kk][0],   p[2*kk][1]);
            pa[kk][1] = packh2(p[2*kk][2],   p[2*kk][3]);
            pa[kk][2] = packh2(p[2*kk+1][0], p[2*kk+1][1]);
            pa[kk][3] = packh2(p[2*kk+1][2], p[2*kk+1][3]);
        }
        {
            int rv = ((lane >> 3) & 1) * 8 + (lane & 7);
            int cv = lane >> 4;
            #pragma unroll
            for (int kk = 0; kk < 4; kk++) {
                uint32_t vb[4][4];
                #pragma unroll
                for (int nd = 0; nd < 4; nd++) {
                    int r = kk*16 + rv;
                    int c = nd*2 + cv;
                    ldm4t(vb[nd], sVb[buf] + r * 128 + ((c ^ (r & 7)) * 16));
                }
                #pragma unroll
                for (int nd = 0; nd < 4; nd++) {
                    mma16816h(oacc[nd*2],   pa[kk], vb[nd][0], vb[nd][1]);
                    mma16816h(oacc[nd*2+1], pa[kk], vb[nd][2], vb[nd][3]);
                }
            }
        }
        if (t < qb) cp_wait<0>();
        __syncthreads();
    }

    float inv0 = 1.0f / l0, inv1 = 1.0f / l1;
    size_t tok0 = tokbase + qb*64 + rloc0;
    #pragma unroll
    for (int nd = 0; nd < 8; nd++) {
        int col = h*DH + nd*8 + qid*2;
        *reinterpret_cast<uint32_t*>(ctx + tok0 * DD + col) =
            packh2(oacc[nd][0] * inv0, oacc[nd][1] * inv0);
        *reinterpret_cast<uint32_t*>(ctx + (tok0 + 8) * DD + col) =
            packh2(oacc[nd][2] * inv1, oacc[nd][3] * inv1);
    }
}

// ---------------------------------------------------------------------------
// Host launch
// ---------------------------------------------------------------------------
extern "C" void kernel_launch(void* const* d_in, const int* in_sizes, int n_in,
                              void* d_out, int out_size) {
    const int*   ids   = (const int*)  d_in[0];
    const float* emb   = (const float*)d_in[1];
    const float* pe    = (const float*)d_in[2];
    const float* wq    = (const float*)d_in[3];
    const float* wk    = (const float*)d_in[4];
    const float* wv    = (const float*)d_in[5];
    const float* wo    = (const float*)d_in[6];
    const float* wo_b  = (const float*)d_in[7];
    const float* w1    = (const float*)d_in[8];
    const float* b1    = (const float*)d_in[9];
    const float* w2    = (const float*)d_in[10];
    const float* b2    = (const float*)d_in[11];
    const float* ln1_g = (const float*)d_in[12];
    const float* ln1_b = (const float*)d_in[13];
    const float* ln2_g = (const float*)d_in[14];
    const float* ln2_b = (const float*)d_in[15];
    const float* lnf_g = (const float*)d_in[16];
    const float* lnf_b = (const float*)d_in[17];
    float* out = (float*)d_out;

    float *x;
    __half *qkvh, *h16, *ctx, *ff;
    __half *wqkvT, *woT, *w1T, *w2T, *hf, *embH;
    cudaGetSymbolAddress((void**)&x, g_x);
    cudaGetSymbolAddress((void**)&qkvh, g_qkvh);
    cudaGetSymbolAddress((void**)&h16, g_h);
    cudaGetSymbolAddress((void**)&ctx, g_ctx);
    cudaGetSymbolAddress((void**)&ff, g_ff);
    cudaGetSymbolAddress((void**)&wqkvT, g_wqkvT);
    cudaGetSymbolAddress((void**)&woT, g_woT);
    cudaGetSymbolAddress((void**)&w1T, g_w1T);
    cudaGetSymbolAddress((void**)&w2T, g_w2T);
    cudaGetSymbolAddress((void**)&hf, g_hf);
    cudaGetSymbolAddress((void**)&embH, g_embH);

    cudaFuncSetAttribute((void*)gemm_w<0, 2, false>, cudaFuncAttributeMaxDynamicSharedMemorySize, GW_SMEM);
    cudaFuncSetAttribute((void*)gemm_w<3, 2, false>, cudaFuncAttributeMaxDynamicSharedMemorySize, GW_SMEM);
    cudaFuncSetAttribute((void*)gemm_w<0, 0, true >, cudaFuncAttributeMaxDynamicSharedMemorySize, GW_SMEM);
    cudaFuncSetAttribute((void*)gemm_n, cudaFuncAttributeMaxDynamicSharedMemorySize, GN_SMEM);

    // weight conversions (fp16 single, transposed)
    dim3 cb(32, 8);
    conv_wTh<<<dim3(DD/32, DD/32), cb>>>(wq, wqkvT,           DD, DD);
    conv_wTh<<<dim3(DD/32, DD/32), cb>>>(wk, wqkvT + DD*DD,   DD, DD);
    conv_wTh<<<dim3(DD/32, DD/32), cb>>>(wv, wqkvT + 2*DD*DD, DD, DD);
    conv_wTh<<<dim3(DD/32, DD/32), cb>>>(wo, woT, DD, DD);
    conv_wTh<<<dim3(FFD/32, DD/32), cb>>>(w1, w1T, DD, FFD);
    conv_wTh<<<dim3(DD/32, FFD/32), cb>>>(w2, w2T, FFD, DD);
    {
        int n4 = VV * DD / 4;
        conv_half4<<<(n4 + 255) / 256, 256>>>(emb, embH, n4);
    }

    embed_kernel<<<NN, 128>>>(ids, emb, pe, x);

    dim3 gQKV(QKVD/256, NN/128);     // (6, 32)
    dim3 gProj(DD/128, NN/128);      // (4, 32)
    dim3 gFF1(FFD/256, NN/128);      // (8, 32)
    dim3 gAttn(SS/64, BB*HH);        // (16, 32)

    for (int layer = 0; layer < NLAYERS; layer++) {
        ln_kernel<<<NN, 128>>>(x, (uint32_t*)h16, ln1_g, ln1_b);
        gemm_w<0, 2, false><<<gQKV, 256, GW_SMEM>>>(
            h16, wqkvT, nullptr, nullptr, qkvh, QKVD, DD);
        attn_mma<<<gAttn, 128>>>(qkvh, ctx);
        gemm_n<<<gProj, 256, GN_SMEM>>>(
            ctx, woT, wo_b, x, x, DD, DD);
        ln_kernel<<<NN, 128>>>(x, (uint32_t*)h16, ln2_g, ln2_b);
        gemm_w<3, 2, false><<<gFF1, 256, GW_SMEM>>>(
            h16, w1T, b1, nullptr, ff, FFD, DD);
        gemm_n<<<gProj, 256, GN_SMEM>>>(
            ff, w2T, b2, x, x, DD, FFD);
    }

    ln_kernel<<<NN, 128>>>(x, (uint32_t*)hf, lnf_g, lnf_b);

    dim3 gLM((VV + 255) / 256, NN / 128);   // (197, 32)
    gemm_w<0, 0, true><<<gLM, 256, GW_SMEM>>>(
        hf, embH, nullptr, out, nullptr, VV, DD);
}

// round 13
// speedup vs baseline: 7.1706x; 1.0291x over previous
#include <cuda_runtime.h>
#include <cuda_bf16.h>
#include <cuda_fp16.h>
#include <math.h>
#include <stdint.h>

// Problem constants
#define BB 4
#define SS 1024
#define NN (BB*SS)      // 4096 tokens
#define DD 512
#define HH 8
#define DH 64
#define FFD 2048
#define VV 50257
#define NLAYERS 6
#define QKVD 1536       // fused qkv width

// ---------------------------------------------------------------------------
// Scratch (allocation-free: __device__ globals) — all activations single fp16
// ---------------------------------------------------------------------------
__device__ float g_x[NN*DD];
__device__ __half g_h[NN*DD];
__device__ __half g_qkvh[NN*QKVD];
__device__ __half g_ctx[NN*DD];
__device__ __half g_ff[NN*FFD];
// transposed fp16 weights [N,K]
__device__ __half g_wqkvT[3*DD*DD];
__device__ __half g_woT[DD*DD];
__device__ __half g_w1T[FFD*DD];
__device__ __half g_w2T[DD*FFD];
// LM head
__device__ __half g_hf[NN*DD];
__device__ __half g_embH[VV*DD];

// ---------------------------------------------------------------------------
// Helpers
// ---------------------------------------------------------------------------
__device__ __forceinline__ uint32_t smem_u32(const void* p) {
    uint32_t a;
    asm("{ .reg .u64 t; cvta.to.shared.u64 t, %1; cvt.u32.u64 %0, t; }"
        : "=r"(a) : "l"(p));
    return a;
}

__device__ __forceinline__ void ldm4(uint32_t* r, uint32_t addr) {
    asm volatile("ldmatrix.sync.aligned.m8n8.x4.shared.b16 {%0,%1,%2,%3}, [%4];"
                 : "=r"(r[0]), "=r"(r[1]), "=r"(r[2]), "=r"(r[3]) : "r"(addr));
}
__device__ __forceinline__ void ldm4t(uint32_t* r, uint32_t addr) {
    asm volatile("ldmatrix.sync.aligned.m8n8.x4.trans.shared.b16 {%0,%1,%2,%3}, [%4];"
                 : "=r"(r[0]), "=r"(r[1]), "=r"(r[2]), "=r"(r[3]) : "r"(addr));
}

__device__ __forceinline__ void mma16816h(float* c, const uint32_t* a,
                                          uint32_t b0, uint32_t b1) {
    asm volatile(
        "mma.sync.aligned.m16n8k16.row.col.f32.f16.f16.f32 "
        "{%0,%1,%2,%3}, {%4,%5,%6,%7}, {%8,%9}, {%0,%1,%2,%3};"
        : "+f"(c[0]), "+f"(c[1]), "+f"(c[2]), "+f"(c[3])
        : "r"(a[0]), "r"(a[1]), "r"(a[2]), "r"(a[3]), "r"(b0), "r"(b1));
}

__device__ __forceinline__ void cp_async16(uint32_t dst, const void* src, int szbytes) {
    asm volatile("cp.async.cg.shared.global [%0], [%1], 16, %2;"
                 :: "r"(dst), "l"(src), "r"(szbytes));
}
#define CP_COMMIT() asm volatile("cp.async.commit_group;" ::: "memory")
template<int N>
__device__ __forceinline__ void cp_wait() {
    asm volatile("cp.async.wait_group %0;" :: "n"(N) : "memory");
}

__device__ __forceinline__ uint32_t packh2(float x, float y) {
    __half2 t = __floats2half2_rn(x, y);
    return *reinterpret_cast<uint32_t*>(&t);
}

__device__ __forceinline__ float gelu_exact(float v) {
    return 0.5f * v * (1.0f + erff(v * 0.70710678118654752f));
}

// ---------------------------------------------------------------------------
// Weight conversion: W [K,N] fp32 -> fp16 [N,K] (transpose)
// ---------------------------------------------------------------------------
__global__ void conv_wTh(const float* __restrict__ W, __half* __restrict__ o16,
                         int K, int N) {
    __shared__ float t[32][33];
    int n0 = blockIdx.x * 32, k0 = blockIdx.y * 32;
    int tx = threadIdx.x, ty = threadIdx.y;
    #pragma unroll
    for (int r = 0; r < 4; r++)
        t[ty + r*8][tx] = W[(size_t)(k0 + ty + r*8) * N + n0 + tx];
    __syncthreads();
    #pragma unroll
    for (int r = 0; r < 4; r++)
        o16[(size_t)(n0 + ty + r*8) * K + k0 + tx] = __float2half_rn(t[tx][ty + r*8]);
}

// Elementwise fp32 -> fp16
__global__ void conv_half4(const float* __restrict__ src,
                           __half* __restrict__ dst, int n4) {
    int i = blockIdx.x * 256 + threadIdx.x;
    if (i >= n4) return;
    float4 v = reinterpret_cast<const float4*>(src)[i];
    uint2 o;
    o.x = packh2(v.x, v.y);
    o.y = packh2(v.z, v.w);
    reinterpret_cast<uint2*>(dst)[i] = o;
}

// ---------------------------------------------------------------------------
// Embedding
// ---------------------------------------------------------------------------
__global__ void embed_kernel(const int* __restrict__ ids,
                             const float* __restrict__ emb,
                             const float* __restrict__ pe,
                             float* __restrict__ x) {
    int n = blockIdx.x;
    int tid = threadIdx.x;
    int id = ids[n];
    int s = n & (SS - 1);
    const float sq = 22.62741699796952f;
    float4 e = reinterpret_cast<const float4*>(emb + (size_t)id * DD)[tid];
    float4 p = reinterpret_cast<const float4*>(pe + (size_t)s * DD)[tid];
    float4 o;
    o.x = e.x * sq + p.x; o.y = e.y * sq + p.y;
    o.z = e.z * sq + p.z; o.w = e.w * sq + p.w;
    reinterpret_cast<float4*>(x + (size_t)n * DD)[tid] = o;
}

// ---------------------------------------------------------------------------
// LayerNorm -> single fp16
// ---------------------------------------------------------------------------
__global__ void ln_kernel(const float* __restrict__ in,
                          uint32_t* __restrict__ out16,
                          const float* __restrict__ g, const float* __restrict__ b) {
    int row = blockIdx.x;
    int tid = threadIdx.x;    // 128
    float4 v = reinterpret_cast<const float4*>(in + (size_t)row * DD)[tid];
    float s = v.x + v.y + v.z + v.w;
    float ss = v.x*v.x + v.y*v.y + v.z*v.z + v.w*v.w;
    #pragma unroll
    for (int o = 16; o > 0; o >>= 1) {
        s  += __shfl_xor_sync(0xffffffffu, s, o);
        ss += __shfl_xor_sync(0xffffffffu, ss, o);
    }
    __shared__ float rs[4], rss[4];
    int warp = tid >> 5;
    if ((tid & 31) == 0) { rs[warp] = s; rss[warp] = ss; }
    __syncthreads();
    float mean = (rs[0]+rs[1]+rs[2]+rs[3]) * (1.0f/DD);
    float var  = (rss[0]+rss[1]+rss[2]+rss[3]) * (1.0f/DD) - mean*mean;
    float rstd = rsqrtf(var + 1e-5f);
    float4 gg = reinterpret_cast<const float4*>(g)[tid];
    float4 bb = reinterpret_cast<const float4*>(b)[tid];
    float4 o;
    o.x = (v.x - mean)*rstd*gg.x + bb.x;
    o.y = (v.y - mean)*rstd*gg.y + bb.y;
    o.z = (v.z - mean)*rstd*gg.z + bb.z;
    o.w = (v.w - mean)*rstd*gg.w + bb.w;
    uint2 hh;
    hh.x = packh2(o.x, o.y);
    hh.y = packh2(o.z, o.w);
    reinterpret_cast<uint2*>(out16)[(size_t)row * (DD/4) + tid] = hh;
}

#define SUBT 16384                      // 128 rows x 128B

// ---------------------------------------------------------------------------
// Wide GEMM (qkv, ff1, LM head): fp16 1-pass, CTA 128x256, 8 warps (2M x 4N),
// warp tile 64x64, 3-stage. Stage = A16 + B32 = 48KB.
// EPI: 1=bias, 2=gelu. OUT: 0=f32 guarded streaming (LM), 2=fp16.
// SWAP: blockIdx.x indexes M (LM head: M-fastest for B L2 reuse).
// ---------------------------------------------------------------------------
#define STGW (3*SUBT)                   // 48KB
#define GW_SMEM (3*STGW)                // 147456

template<int EPI, int OUT, bool GUARD, bool SWAP>
__global__ __launch_bounds__(256, 1)
void gemm_w(const __half* __restrict__ A, const __half* __restrict__ B,
            const float* __restrict__ bias,
            float* __restrict__ C, __half* __restrict__ Ch,
            int Nout, int K) {
    extern __shared__ char smem[];
    uint32_t sb = smem_u32(smem);
    const int tid = threadIdx.x;
    const int lane = tid & 31, wid = tid >> 5;
    const int m0 = (SWAP ? blockIdx.x : blockIdx.y) * 128;
    const int n0 = (SWAP ? blockIdx.y : blockIdx.x) * 256;
    const int warp_m = (wid >> 2) * 64;
    const int warp_n = (wid & 3) * 64;

    float acc[4][8][4];
    #pragma unroll
    for (int i = 0; i < 4; i++)
        #pragma unroll
        for (int j = 0; j < 8; j++)
            #pragma unroll
            for (int e = 0; e < 4; e++) acc[i][j][e] = 0.f;

    const int nch = K >> 6;   // 8

    auto load_stage = [&](int buf, int k0) {
        uint32_t base = sb + buf * STGW;
        #pragma unroll
        for (int it = 0; it < 4; it++) {
            int u = tid + it * 256;
            int row = u >> 3, c = u & 7;
            uint32_t dst = base + row * 128 + ((c ^ (row & 7)) * 16);
            cp_async16(dst, A + (size_t)(m0 + row) * K + k0 + c * 8, 16);
        }
        #pragma unroll
        for (int it = 0; it < 8; it++) {
            int u = tid + it * 256;
            int row = u >> 3, c = u & 7;
            uint32_t dst = base + SUBT + row * 128 + ((c ^ (row & 7)) * 16);
            const __half* g = B + (size_t)(n0 + row) * K + k0 + c * 8;
            int sz = 16;
            if (GUARD && (n0 + row >= Nout)) { g = B; sz = 0; }
            cp_async16(dst, g, sz);
        }
    };

    int ra[4];
    #pragma unroll
    for (int mb = 0; mb < 4; mb++) ra[mb] = warp_m + mb * 16 + (lane & 15);
    const int ca = lane >> 4;
    int rB[4];
    #pragma unroll
    for (int nb = 0; nb < 4; nb++)
        rB[nb] = warp_n + nb * 16 + ((lane >> 4) & 1) * 8 + (lane & 7);
    const int kcB = (lane >> 3) & 1;

    auto compute = [&](int buf) {
        uint32_t base = sb + buf * STGW;
        #pragma unroll
        for (int ks = 0; ks < 4; ks++) {
            uint32_t a[4][4], b[4][4];
            #pragma unroll
            for (int mb = 0; mb < 4; mb++) {
                uint32_t off = ra[mb] * 128 + (((ks*2 + ca) ^ (ra[mb] & 7)) * 16);
                ldm4(a[mb], base + off);
            }
            #pragma unroll
            for (int nb = 0; nb < 4; nb++) {
                uint32_t off = rB[nb] * 128 + (((ks*2 + kcB) ^ (rB[nb] & 7)) * 16);
                ldm4(b[nb], base + SUBT + off);
            }
            #pragma unroll
            for (int mb = 0; mb < 4; mb++)
                #pragma unroll
                for (int nb = 0; nb < 4; nb++) {
                    mma16816h(acc[mb][nb*2],   a[mb], b[nb][0], b[nb][1]);
                    mma16816h(acc[mb][nb*2+1], a[mb], b[nb][2], b[nb][3]);
                }
        }
    };

    load_stage(0, 0);
    CP_COMMIT();
    load_stage(1, 64);
    CP_COMMIT();
    for (int c = 0; c < nch; c++) {
        if (c == nch - 1) cp_wait<0>(); else cp_wait<1>();
        __syncthreads();
        compute(c % 3);
        int nx = c + 2;
        if (nx < nch) { load_stage(nx % 3, nx << 6); CP_COMMIT(); }
    }

    const int gid = lane >> 2, qid = lane & 3;
    #pragma unroll
    for (int mb = 0; mb < 4; mb++) {
        #pragma unroll
        for (int nf = 0; nf < 8; nf++) {
            int n = n0 + warp_n + nf * 8 + qid * 2;
            #pragma unroll
            for (int hh = 0; hh < 2; hh++) {
                int m = m0 + warp_m + mb * 16 + gid + hh * 8;
                float vx = acc[mb][nf][hh*2];
                float vy = acc[mb][nf][hh*2 + 1];
                if (EPI & 1) { vx += bias[n]; vy += bias[n + 1]; }
                if (EPI & 2) { vx = gelu_exact(vx); vy = gelu_exact(vy); }
                size_t o = (size_t)m * Nout + n;
                if (OUT == 2) {
                    *reinterpret_cast<uint32_t*>(Ch + o) = packh2(vx, vy);
                } else {
                    // fp32 streaming stores; Nout odd -> o parity = m parity
                    // (n is always even). Even rows: vectorized float2.
                    if (n + 1 < Nout) {
                        if ((o & 1) == 0) {
                            __stcs(reinterpret_cast<float2*>(C + o),
                                   make_float2(vx, vy));
                        } else {
                            __stcs(C + o, vx);
                            __stcs(C + o + 1, vy);
                        }
                    } else if (n < Nout) {
                        __stcs(C + o, vx);
                    }
                }
            }
        }
    }
}

// ---------------------------------------------------------------------------
// Narrow layer GEMM (wo, ff2): fp16 1-pass, CTA 128x128, 8 warps (4M x 2N),
// warp tile 32x64, 3-stage. Stage = A16 + B16 = 32KB.
// Output: fp32 x with bias+residual.
// ---------------------------------------------------------------------------
#define STGN (2*SUBT)                   // 32KB
#define GN_SMEM (3*STGN)                // 98304

__global__ __launch_bounds__(256, 1)
void gemm_n(const __half* __restrict__ A, const __half* __restrict__ B,
            const float* __restrict__ bias, const float* __restrict__ resid,
            float* __restrict__ C, int Nout, int K) {
    extern __shared__ char smem[];
    uint32_t sb = smem_u32(smem);
    const int tid = threadIdx.x;
    const int lane = tid & 31, wid = tid >> 5;
    const int m0 = blockIdx.y * 128, n0 = blockIdx.x * 128;
    const int warp_m = (wid >> 1) * 32;
    const int warp_n = (wid & 1) * 64;

    float acc[2][8][4];
    #pragma unroll
    for (int i = 0; i < 2; i++)
        #pragma unroll
        for (int j = 0; j < 8; j++)
            #pragma unroll
            for (int e = 0; e < 4; e++) acc[i][j][e] = 0.f;

    const int nch = K >> 6;

    auto load_stage = [&](int buf, int k0) {
        uint32_t base = sb + buf * STGN;
        #pragma unroll
        for (int sub = 0; sub < 2; sub++) {
            const __half* P = sub ? B : A;
            int row0 = sub ? n0 : m0;
            uint32_t dbase = base + sub * SUBT;
            #pragma unroll
            for (int it = 0; it < 4; it++) {
                int u = tid + it * 256;
                int row = u >> 3, c = u & 7;
                uint32_t dst = dbase + row * 128 + ((c ^ (row & 7)) * 16);
                cp_async16(dst, P + (size_t)(row0 + row) * K + k0 + c * 8, 16);
            }
        }
    };

    int ra[2];
    ra[0] = warp_m + (lane & 15);
    ra[1] = ra[0] + 16;
    const int ca = lane >> 4;
    int rB[4];
    #pragma unroll
    for (int nb = 0; nb < 4; nb++)
        rB[nb] = warp_n + nb * 16 + ((lane >> 4) & 1) * 8 + (lane & 7);
    const int kcB = (lane >> 3) & 1;

    auto compute = [&](int buf) {
        uint32_t base = sb + buf * STGN;
        #pragma unroll
        for (int ks = 0; ks < 4; ks++) {
            uint32_t a[2][4], b[4][4];
            #pragma unroll
            for (int mb = 0; mb < 2; mb++) {
                uint32_t off = ra[mb] * 128 + (((ks*2 + ca) ^ (ra[mb] & 7)) * 16);
                ldm4(a[mb], base + off);
            }
            #pragma unroll
            for (int nb = 0; nb < 4; nb++) {
                uint32_t off = rB[nb] * 128 + (((ks*2 + kcB) ^ (rB[nb] & 7)) * 16);
                ldm4(b[nb], base + SUBT + off);
            }
            #pragma unroll
            for (int mb = 0; mb < 2; mb++)
                #pragma unroll
                for (int nb = 0; nb < 4; nb++) {
                    mma16816h(acc[mb][nb*2],   a[mb], b[nb][0], b[nb][1]);
                    mma16816h(acc[mb][nb*2+1], a[mb], b[nb][2], b[nb][3]);
                }
        }
    };

    load_stage(0, 0);
    CP_COMMIT();
    if (nch > 1) { load_stage(1, 64); CP_COMMIT(); }
    for (int c = 0; c < nch; c++) {
        if (c == nch - 1) cp_wait<0>(); else cp_wait<1>();
        __syncthreads();
        compute(c % 3);
        int nx = c + 2;
        if (nx < nch) { load_stage(nx % 3, nx << 6); CP_COMMIT(); }
    }

    const int gid = lane >> 2, qid = lane & 3;
    #pragma unroll
    for (int mb = 0; mb < 2; mb++) {
        #pragma unroll
        for (int nf = 0; nf < 8; nf++) {
            int n = n0 + warp_n + nf * 8 + qid * 2;
            #pragma unroll
            for (int hh = 0; hh < 2; hh++) {
                int m = m0 + warp_m + mb * 16 + gid + hh * 8;
                float vx = acc[mb][nf][hh*2];
                float vy = acc[mb][nf][hh*2 + 1];
                vx += bias[n]; vy += bias[n + 1];
                size_t o = (size_t)m * Nout + n;
                float2 r = *reinterpret_cast<const float2*>(resid + o);
                vx += r.x; vy += r.y;
                *reinterpret_cast<float2*>(C + o) = make_float2(vx, vy);
            }
        }
    }
}

// ---------------------------------------------------------------------------
// Tensor-core causal flash attention (fp16 mma, fp32 softmax).
// CTA: 128 thr (4 warps), 64 queries (16/warp). grid (S/64, B*H).
// ---------------------------------------------------------------------------
__global__ __launch_bounds__(128)
void attn_mma(const __half* __restrict__ qkv,
              __half* __restrict__ ctx) {
    __shared__ __align__(16) char sQ[8192];
    __shared__ __align__(16) char sK[2][8192];
    __shared__ __align__(16) char sV[2][8192];
    int bh = blockIdx.y;
    int b = bh >> 3, h = bh & 7;
    int qb = gridDim.x - 1 - blockIdx.x;      // heavy blocks first
    int tid = threadIdx.x, lane = tid & 31, wid = tid >> 5;
    int warp_q = wid * 16;
    const int gid = lane >> 2, qid = lane & 3;
    uint32_t sQb = smem_u32(sQ);
    uint32_t sKb[2] = {smem_u32(sK[0]), smem_u32(sK[1])};
    uint32_t sVb[2] = {smem_u32(sV[0]), smem_u32(sV[1])};

    size_t tokbase = (size_t)b * SS;

    #pragma unroll
    for (int it = 0; it < 4; it++) {
        int u = tid + it * 128;
        int row = u >> 3, c = u & 7;
        uint32_t dst = sQb + row * 128 + ((c ^ (row & 7)) * 16);
        const __half* g = qkv + (tokbase + qb*64 + row) * QKVD + h*DH + c*8;
        cp_async16(dst, g, 16);
    }
    auto load_kv = [&](int buf, int t) {
        #pragma unroll
        for (int it = 0; it < 4; it++) {
            int u = tid + it * 128;
            int row = u >> 3, c = u & 7;
            uint32_t sw = row * 128 + ((c ^ (row & 7)) * 16);
            const __half* gk = qkv + (tokbase + t*64 + row) * QKVD + DD + h*DH + c*8;
            const __half* gv = qkv + (tokbase + t*64 + row) * QKVD + 2*DD + h*DH + c*8;
            cp_async16(sKb[buf] + sw, gk, 16);
            cp_async16(sVb[buf] + sw, gv, 16);
        }
    };
    load_kv(0, 0);
    CP_COMMIT();
    cp_wait<0>();
    __syncthreads();

    uint32_t qa[4][4];
    {
        int r = warp_q + (lane & 15);
        int chalf = lane >> 4;
        #pragma unroll
        for (int ks = 0; ks < 4; ks++) {
            int c = ks*2 + chalf;
            ldm4(qa[ks], sQb + r * 128 + ((c ^ (r & 7)) * 16));
        }
    }

    float m0v = -1e30f, m1v = -1e30f, l0 = 0.f, l1 = 0.f;
    float oacc[8][4];
    #pragma unroll
    for (int i = 0; i < 8; i++)
        #pragma unroll
        for (int e = 0; e < 4; e++) oacc[i][e] = 0.f;

    const int rloc0 = warp_q + gid;

    for (int t = 0; t <= qb; t++) {
        int buf = t & 1;
        if (t < qb) { load_kv(buf ^ 1, t + 1); CP_COMMIT(); }

        float sacc[8][4];
        #pragma unroll
        for (int i = 0; i < 8; i++)
            #pragma unroll
            for (int e = 0; e < 4; e++) sacc[i][e] = 0.f;
        {
            int rb = ((lane >> 4) & 1) * 8 + (lane & 7);
            int kc = (lane >> 3) & 1;
            #pragma unroll
            for (int ks = 0; ks < 4; ks++) {
                uint32_t kb[4][4];
                #pragma unroll
                for (int nb = 0; nb < 4; nb++) {
                    int r = nb*16 + rb;
                    int c = ks*2 + kc;
                    ldm4(kb[nb], sKb[buf] + r * 128 + ((c ^ (r & 7)) * 16));
                }
                #pragma unroll
                for (int nb = 0; nb < 4; nb++) {
                    mma16816h(sacc[nb*2],   qa[ks], kb[nb][0], kb[nb][1]);
                    mma16816h(sacc[nb*2+1], qa[ks], kb[nb][2], kb[nb][3]);
                }
            }
        }
        #pragma unroll
        for (int i = 0; i < 8; i++)
            #pragma unroll
            for (int e = 0; e < 4; e++) sacc[i][e] *= 0.125f;
        if (t == qb) {
            #pragma unroll
            for (int i = 0; i < 8; i++) {
                int col = i*8 + qid*2;
                #pragma unroll
                for (int e = 0; e < 4; e++) {
                    int cc = col + (e & 1);
                    int rr = rloc0 + ((e >> 1) * 8);
                    if (cc > rr) sacc[i][e] = -1e30f;
                }
            }
        }
        float rmax0 = -1e30f, rmax1 = -1e30f;
        #pragma unroll
        for (int i = 0; i < 8; i++) {
            rmax0 = fmaxf(rmax0, fmaxf(sacc[i][0], sacc[i][1]));
            rmax1 = fmaxf(rmax1, fmaxf(sacc[i][2], sacc[i][3]));
        }
        #pragma unroll
        for (int o = 1; o <= 2; o <<= 1) {
            rmax0 = fmaxf(rmax0, __shfl_xor_sync(0xffffffffu, rmax0, o));
            rmax1 = fmaxf(rmax1, __shfl_xor_sync(0xffffffffu, rmax1, o));
        }
        float mn0 = fmaxf(m0v, rmax0), mn1 = fmaxf(m1v, rmax1);
        float cor0 = __expf(m0v - mn0), cor1 = __expf(m1v - mn1);
        m0v = mn0; m1v = mn1;
        float rs0 = 0.f, rs1 = 0.f;
        float p[8][4];
        #pragma unroll
        for (int i = 0; i < 8; i++) {
            p[i][0] = __expf(sacc[i][0] - mn0);
            p[i][1] = __expf(sacc[i][1] - mn0);
            p[i][2] = __expf(sacc[i][2] - mn1);
            p[i][3] = __expf(sacc[i][3] - mn1);
            rs0 += p[i][0] + p[i][1];
            rs1 += p[i][2] + p[i][3];
        }
        #pragma unroll
        for (int o = 1; o <= 2; o <<= 1) {
            rs0 += __shfl_xor_sync(0xffffffffu, rs0, o);
            rs1 += __shfl_xor_sync(0xffffffffu, rs1, o);
        }
        l0 = l0 * cor0 + rs0;
        l1 = l1 * cor1 + rs1;
        #pragma unroll
        for (int i = 0; i < 8; i++) {
            oacc[i][0] *= cor0; oacc[i][1] *= cor0;
            oacc[i][2] *= cor1; oacc[i][3] *= cor1;
        }
        uint32_t pa[4][4];
        #pragma unroll
        for (int kk = 0; kk < 4; kk++) {
            pa[kk][0] = packh2(p[2*kk][0],   p[2*kk][1]);
            pa[kk][1] = packh2(p[2*kk][2],   p[2*kk][3]);
            pa[kk][2] = packh2(p[2*kk+1][0], p[2*kk+1][1]);
            pa[kk][3] = packh2(p[2*kk+1][2], p[2*kk+1][3]);
        }
        {
            int rv = ((lane >> 3) & 1) * 8 + (lane & 7);
            int cv = lane >> 4;
            #pragma unroll
            for (int kk = 0; kk < 4; kk++) {
                uint32_t vb[4][4];
                #pragma unroll
                for (int nd = 0; nd < 4; nd++) {
                    int r = kk*16 + rv;
                    int c = nd*2 + cv;
                    ldm4t(vb[nd], sVb[buf] + r * 128 + ((c ^ (r & 7)) * 16));
                }
                #pragma unroll
                for (int nd = 0; nd < 4; nd++) {
                    mma16816h(oacc[nd*2],   pa[kk], vb[nd][0], vb[nd][1]);
                    mma16816h(oacc[nd*2+1], pa[kk], vb[nd][2], vb[nd][3]);
                }
            }
        }
        if (t < qb) cp_wait<0>();
        __syncthreads();
    }

    float inv0 = 1.0f / l0, inv1 = 1.0f / l1;
    size_t tok0 = tokbase + qb*64 + rloc0;
    #pragma unroll
    for (int nd = 0; nd < 8; nd++) {
        int col = h*DH + nd*8 + qid*2;
        *reinterpret_cast<uint32_t*>(ctx + tok0 * DD + col) =
            packh2(oacc[nd][0] * inv0, oacc[nd][1] * inv0);
        *reinterpret_cast<uint32_t*>(ctx + (tok0 + 8) * DD + col) =
            packh2(oacc[nd][2] * inv1, oacc[nd][3] * inv1);
    }
}

// ---------------------------------------------------------------------------
// Host launch
// ---------------------------------------------------------------------------
extern "C" void kernel_launch(void* const* d_in, const int* in_sizes, int n_in,
                              void* d_out, int out_size) {
    const int*   ids   = (const int*)  d_in[0];
    const float* emb   = (const float*)d_in[1];
    const float* pe    = (const float*)d_in[2];
    const float* wq    = (const float*)d_in[3];
    const float* wk    = (const float*)d_in[4];
    const float* wv    = (const float*)d_in[5];
    const float* wo    = (const float*)d_in[6];
    const float* wo_b  = (const float*)d_in[7];
    const float* w1    = (const float*)d_in[8];
    const float* b1    = (const float*)d_in[9];
    const float* w2    = (const float*)d_in[10];
    const float* b2    = (const float*)d_in[11];
    const float* ln1_g = (const float*)d_in[12];
    const float* ln1_b = (const float*)d_in[13];
    const float* ln2_g = (const float*)d_in[14];
    const float* ln2_b = (const float*)d_in[15];
    const float* lnf_g = (const float*)d_in[16];
    const float* lnf_b = (const float*)d_in[17];
    float* out = (float*)d_out;

    float *x;
    __half *qkvh, *h16, *ctx, *ff;
    __half *wqkvT, *woT, *w1T, *w2T, *hf, *embH;
    cudaGetSymbolAddress((void**)&x, g_x);
    cudaGetSymbolAddress((void**)&qkvh, g_qkvh);
    cudaGetSymbolAddress((void**)&h16, g_h);
    cudaGetSymbolAddress((void**)&ctx, g_ctx);
    cudaGetSymbolAddress((void**)&ff, g_ff);
    cudaGetSymbolAddress((void**)&wqkvT, g_wqkvT);
    cudaGetSymbolAddress((void**)&woT, g_woT);
    cudaGetSymbolAddress((void**)&w1T, g_w1T);
    cudaGetSymbolAddress((void**)&w2T, g_w2T);
    cudaGetSymbolAddress((void**)&hf, g_hf);
    cudaGetSymbolAddress((void**)&embH, g_embH);

    cudaFuncSetAttribute((void*)gemm_w<0, 2, false, false>, cudaFuncAttributeMaxDynamicSharedMemorySize, GW_SMEM);
    cudaFuncSetAttribute((void*)gemm_w<3, 2, false, false>, cudaFuncAttributeMaxDynamicSharedMemorySize, GW_SMEM);
    cudaFuncSetAttribute((void*)gemm_w<0, 0, true, true  >, cudaFuncAttributeMaxDynamicSharedMemorySize, GW_SMEM);
    cudaFuncSetAttribute((void*)gemm_n, cudaFuncAttributeMaxDynamicSharedMemorySize, GN_SMEM);

    // weight conversions (fp16 single, transposed)
    dim3 cb(32, 8);
    conv_wTh<<<dim3(DD/32, DD/32), cb>>>(wq, wqkvT,           DD, DD);
    conv_wTh<<<dim3(DD/32, DD/32), cb>>>(wk, wqkvT + DD*DD,   DD, DD);
    conv_wTh<<<dim3(DD/32, DD/32), cb>>>(wv, wqkvT + 2*DD*DD, DD, DD);
    conv_wTh<<<dim3(DD/32, DD/32), cb>>>(wo, woT, DD, DD);
    conv_wTh<<<dim3(FFD/32, DD/32), cb>>>(w1, w1T, DD, FFD);
    conv_wTh<<<dim3(DD/32, FFD/32), cb>>>(w2, w2T, FFD, DD);
    {
        int n4 = VV * DD / 4;
        conv_half4<<<(n4 + 255) / 256, 256>>>(emb, embH, n4);
    }

    embed_kernel<<<NN, 128>>>(ids, emb, pe, x);

    dim3 gQKV(QKVD/256, NN/128);     // (6, 32)
    dim3 gProj(DD/128, NN/128);      // (4, 32)
    dim3 gFF1(FFD/256, NN/128);      // (8, 32)
    dim3 gAttn(SS/64, BB*HH);        // (16, 32)

    for (int layer = 0; layer < NLAYERS; layer++) {
        ln_kernel<<<NN, 128>>>(x, (uint32_t*)h16, ln1_g, ln1_b);
        gemm_w<0, 2, false, false><<<gQKV, 256, GW_SMEM>>>(
            h16, wqkvT, nullptr, nullptr, qkvh, QKVD, DD);
        attn_mma<<<gAttn, 128>>>(qkvh, ctx);
        gemm_n<<<gProj, 256, GN_SMEM>>>(
            ctx, woT, wo_b, x, x, DD, DD);
        ln_kernel<<<NN, 128>>>(x, (uint32_t*)h16, ln2_g, ln2_b);
        gemm_w<3, 2, false, false><<<gFF1, 256, GW_SMEM>>>(
            h16, w1T, b1, nullptr, ff, FFD, DD);
        gemm_n<<<gProj, 256, GN_SMEM>>>(
            ff, w2T, b2, x, x, DD, FFD);
    }

    ln_kernel<<<NN, 128>>>(x, (uint32_t*)hf, lnf_g, lnf_b);

    // LM head: M-fastest grid (x=M blocks, y=N blocks) so each wave covers all
    // 32 M-blocks x ~4-5 N-blocks -> every B tile DRAM-read once, L2-served
    // to 32 CTAs; output uses streaming stores to protect L2 residency.
    dim3 gLM(NN / 128, (VV + 255) / 256);   // (32, 197)
    gemm_w<0, 0, true, true><<<gLM, 256, GW_SMEM>>>(
        hf, embH, nullptr, out, nullptr, VV, DD);
}

// round 16
// speedup vs baseline: 7.2751x; 1.0146x over previous
#include <cuda_runtime.h>
#include <cuda_bf16.h>
#include <cuda_fp16.h>
#include <math.h>
#include <stdint.h>

// Problem constants
#define BB 4
#define SS 1024
#define NN (BB*SS)      // 4096 tokens
#define DD 512
#define HH 8
#define DH 64
#define FFD 2048
#define VV 50257
#define NLAYERS 6
#define QKVD 1536       // fused qkv width

// ---------------------------------------------------------------------------
// Scratch (allocation-free: __device__ globals) — all activations single fp16
// ---------------------------------------------------------------------------
__device__ float g_x[NN*DD];
__device__ __half g_h[NN*DD];
__device__ __half g_qkvh[NN*QKVD];
__device__ __half g_ctx[NN*DD];
__device__ __half g_ff[NN*FFD];
// transposed fp16 weights [N,K]
__device__ __half g_wqkvT[3*DD*DD];
__device__ __half g_woT[DD*DD];
__device__ __half g_w1T[FFD*DD];
__device__ __half g_w2T[DD*FFD];
// LM head
__device__ __half g_hf[NN*DD];
__device__ __half g_embH[VV*DD];

// ---------------------------------------------------------------------------
// Helpers
// ---------------------------------------------------------------------------
__device__ __forceinline__ uint32_t smem_u32(const void* p) {
    uint32_t a;
    asm("{ .reg .u64 t; cvta.to.shared.u64 t, %1; cvt.u32.u64 %0, t; }"
        : "=r"(a) : "l"(p));
    return a;
}

__device__ __forceinline__ void ldm4(uint32_t* r, uint32_t addr) {
    asm volatile("ldmatrix.sync.aligned.m8n8.x4.shared.b16 {%0,%1,%2,%3}, [%4];"
                 : "=r"(r[0]), "=r"(r[1]), "=r"(r[2]), "=r"(r[3]) : "r"(addr));
}
__device__ __forceinline__ void ldm4t(uint32_t* r, uint32_t addr) {
    asm volatile("ldmatrix.sync.aligned.m8n8.x4.trans.shared.b16 {%0,%1,%2,%3}, [%4];"
                 : "=r"(r[0]), "=r"(r[1]), "=r"(r[2]), "=r"(r[3]) : "r"(addr));
}

__device__ __forceinline__ void mma16816h(float* c, const uint32_t* a,
                                          uint32_t b0, uint32_t b1) {
    asm volatile(
        "mma.sync.aligned.m16n8k16.row.col.f32.f16.f16.f32 "
        "{%0,%1,%2,%3}, {%4,%5,%6,%7}, {%8,%9}, {%0,%1,%2,%3};"
        : "+f"(c[0]), "+f"(c[1]), "+f"(c[2]), "+f"(c[3])
        : "r"(a[0]), "r"(a[1]), "r"(a[2]), "r"(a[3]), "r"(b0), "r"(b1));
}

__device__ __forceinline__ void cp_async16(uint32_t dst, const void* src, int szbytes) {
    asm volatile("cp.async.cg.shared.global [%0], [%1], 16, %2;"
                 :: "r"(dst), "l"(src), "r"(szbytes));
}
#define CP_COMMIT() asm volatile("cp.async.commit_group;" ::: "memory")
template<int N>
__device__ __forceinline__ void cp_wait() {
    asm volatile("cp.async.wait_group %0;" :: "n"(N) : "memory");
}

__device__ __forceinline__ uint32_t packh2(float x, float y) {
    __half2 t = __floats2half2_rn(x, y);
    return *reinterpret_cast<uint32_t*>(&t);
}

__device__ __forceinline__ float gelu_exact(float v) {
    return 0.5f * v * (1.0f + erff(v * 0.70710678118654752f));
}

// ---------------------------------------------------------------------------
// Weight conversion: W [K,N] fp32 -> fp16 [N,K] (transpose)
// ---------------------------------------------------------------------------
__global__ void conv_wTh(const float* __restrict__ W, __half* __restrict__ o16,
                         int K, int N) {
    __shared__ float t[32][33];
    int n0 = blockIdx.x * 32, k0 = blockIdx.y * 32;
    int tx = threadIdx.x, ty = threadIdx.y;
    #pragma unroll
    for (int r = 0; r < 4; r++)
        t[ty + r*8][tx] = W[(size_t)(k0 + ty + r*8) * N + n0 + tx];
    __syncthreads();
    #pragma unroll
    for (int r = 0; r < 4; r++)
        o16[(size_t)(n0 + ty + r*8) * K + k0 + tx] = __float2half_rn(t[tx][ty + r*8]);
}

// Elementwise fp32 -> fp16
__global__ void conv_half4(const float* __restrict__ src,
                           __half* __restrict__ dst, int n4) {
    int i = blockIdx.x * 256 + threadIdx.x;
    if (i >= n4) return;
    float4 v = reinterpret_cast<const float4*>(src)[i];
    uint2 o;
    o.x = packh2(v.x, v.y);
    o.y = packh2(v.z, v.w);
    reinterpret_cast<uint2*>(dst)[i] = o;
}

// ---------------------------------------------------------------------------
// Embedding
// ---------------------------------------------------------------------------
__global__ void embed_kernel(const int* __restrict__ ids,
                             const float* __restrict__ emb,
                             const float* __restrict__ pe,
                             float* __restrict__ x) {
    int n = blockIdx.x;
    int tid = threadIdx.x;
    int id = ids[n];
    int s = n & (SS - 1);
    const float sq = 22.62741699796952f;
    float4 e = reinterpret_cast<const float4*>(emb + (size_t)id * DD)[tid];
    float4 p = reinterpret_cast<const float4*>(pe + (size_t)s * DD)[tid];
    float4 o;
    o.x = e.x * sq + p.x; o.y = e.y * sq + p.y;
    o.z = e.z * sq + p.z; o.w = e.w * sq + p.w;
    reinterpret_cast<float4*>(x + (size_t)n * DD)[tid] = o;
}

// ---------------------------------------------------------------------------
// LayerNorm -> single fp16
// ---------------------------------------------------------------------------
__global__ void ln_kernel(const float* __restrict__ in,
                          uint32_t* __restrict__ out16,
                          const float* __restrict__ g, const float* __restrict__ b) {
    int row = blockIdx.x;
    int tid = threadIdx.x;    // 128
    float4 v = reinterpret_cast<const float4*>(in + (size_t)row * DD)[tid];
    float s = v.x + v.y + v.z + v.w;
    float ss = v.x*v.x + v.y*v.y + v.z*v.z + v.w*v.w;
    #pragma unroll
    for (int o = 16; o > 0; o >>= 1) {
        s  += __shfl_xor_sync(0xffffffffu, s, o);
        ss += __shfl_xor_sync(0xffffffffu, ss, o);
    }
    __shared__ float rs[4], rss[4];
    int warp = tid >> 5;
    if ((tid & 31) == 0) { rs[warp] = s; rss[warp] = ss; }
    __syncthreads();
    float mean = (rs[0]+rs[1]+rs[2]+rs[3]) * (1.0f/DD);
    float var  = (rss[0]+rss[1]+rss[2]+rss[3]) * (1.0f/DD) - mean*mean;
    float rstd = rsqrtf(var + 1e-5f);
    float4 gg = reinterpret_cast<const float4*>(g)[tid];
    float4 bb = reinterpret_cast<const float4*>(b)[tid];
    float4 o;
    o.x = (v.x - mean)*rstd*gg.x + bb.x;
    o.y = (v.y - mean)*rstd*gg.y + bb.y;
    o.z = (v.z - mean)*rstd*gg.z + bb.z;
    o.w = (v.w - mean)*rstd*gg.w + bb.w;
    uint2 hh;
    hh.x = packh2(o.x, o.y);
    hh.y = packh2(o.z, o.w);
    reinterpret_cast<uint2*>(out16)[(size_t)row * (DD/4) + tid] = hh;
}

#define SUBT 16384                      // 128 rows x 128B

// ---------------------------------------------------------------------------
// Wide GEMM (qkv, ff1, LM head): fp16 1-pass, CTA 128x256, 8 warps (2M x 4N),
// warp tile 64x64. 4-stage ring, 2 chunks per barrier.
// EPI: 1=bias, 2=gelu. OUT: 0=f32 guarded streaming (LM), 2=fp16.
// SWAP: blockIdx.x indexes M (LM head: M-fastest for B L2 reuse).
// ---------------------------------------------------------------------------
#define STGW (3*SUBT)                   // 48KB
#define GW_SMEM (4*STGW)                // 196608

template<int EPI, int OUT, bool GUARD, bool SWAP>
__global__ __launch_bounds__(256, 1)
void gemm_w(const __half* __restrict__ A, const __half* __restrict__ B,
            const float* __restrict__ bias,
            float* __restrict__ C, __half* __restrict__ Ch,
            int Nout, int K) {
    extern __shared__ char smem[];
    uint32_t sb = smem_u32(smem);
    const int tid = threadIdx.x;
    const int lane = tid & 31, wid = tid >> 5;
    const int m0 = (SWAP ? blockIdx.x : blockIdx.y) * 128;
    const int n0 = (SWAP ? blockIdx.y : blockIdx.x) * 256;
    const int warp_m = (wid >> 2) * 64;
    const int warp_n = (wid & 3) * 64;

    float acc[4][8][4];
    #pragma unroll
    for (int i = 0; i < 4; i++)
        #pragma unroll
        for (int j = 0; j < 8; j++)
            #pragma unroll
            for (int e = 0; e < 4; e++) acc[i][j][e] = 0.f;

    const int nch = K >> 6;   // 8 (even)

    auto load_stage = [&](int buf, int k0) {
        uint32_t base = sb + buf * STGW;
        #pragma unroll
        for (int it = 0; it < 4; it++) {
            int u = tid + it * 256;
            int row = u >> 3, c = u & 7;
            uint32_t dst = base + row * 128 + ((c ^ (row & 7)) * 16);
            cp_async16(dst, A + (size_t)(m0 + row) * K + k0 + c * 8, 16);
        }
        #pragma unroll
        for (int it = 0; it < 8; it++) {
            int u = tid + it * 256;
            int row = u >> 3, c = u & 7;
            uint32_t dst = base + SUBT + row * 128 + ((c ^ (row & 7)) * 16);
            const __half* g = B + (size_t)(n0 + row) * K + k0 + c * 8;
            int sz = 16;
            if (GUARD && (n0 + row >= Nout)) { g = B; sz = 0; }
            cp_async16(dst, g, sz);
        }
    };

    int ra[4];
    #pragma unroll
    for (int mb = 0; mb < 4; mb++) ra[mb] = warp_m + mb * 16 + (lane & 15);
    const int ca = lane >> 4;
    int rB[4];
    #pragma unroll
    for (int nb = 0; nb < 4; nb++)
        rB[nb] = warp_n + nb * 16 + ((lane >> 4) & 1) * 8 + (lane & 7);
    const int kcB = (lane >> 3) & 1;

    auto compute = [&](int buf) {
        uint32_t base = sb + buf * STGW;
        #pragma unroll
        for (int ks = 0; ks < 4; ks++) {
            uint32_t a[4][4], b[4][4];
            #pragma unroll
            for (int mb = 0; mb < 4; mb++) {
                uint32_t off = ra[mb] * 128 + (((ks*2 + ca) ^ (ra[mb] & 7)) * 16);
                ldm4(a[mb], base + off);
            }
            #pragma unroll
            for (int nb = 0; nb < 4; nb++) {
                uint32_t off = rB[nb] * 128 + (((ks*2 + kcB) ^ (rB[nb] & 7)) * 16);
                ldm4(b[nb], base + SUBT + off);
            }
            #pragma unroll
            for (int mb = 0; mb < 4; mb++)
                #pragma unroll
                for (int nb = 0; nb < 4; nb++) {
                    mma16816h(acc[mb][nb*2],   a[mb], b[nb][0], b[nb][1]);
                    mma16816h(acc[mb][nb*2+1], a[mb], b[nb][2], b[nb][3]);
                }
        }
    };

    // 4-stage ring, 2 chunks consumed per wait+sync
    load_stage(0, 0);
    CP_COMMIT();
    load_stage(1, 64);
    CP_COMMIT();
    for (int c = 0; c < nch; c += 2) {
        cp_wait<0>();            // only chunks c, c+1 pending
        __syncthreads();         // protects buffers (c+2)&3, (c+3)&3
        if (c + 2 < nch) { load_stage((c + 2) & 3, (c + 2) << 6); CP_COMMIT(); }
        if (c + 3 < nch) { load_stage((c + 3) & 3, (c + 3) << 6); CP_COMMIT(); }
        compute(c & 3);
        compute((c + 1) & 3);
    }

    const int gid = lane >> 2, qid = lane & 3;
    #pragma unroll
    for (int mb = 0; mb < 4; mb++) {
        #pragma unroll
        for (int nf = 0; nf < 8; nf++) {
            int n = n0 + warp_n + nf * 8 + qid * 2;
            #pragma unroll
            for (int hh = 0; hh < 2; hh++) {
                int m = m0 + warp_m + mb * 16 + gid + hh * 8;
                float vx = acc[mb][nf][hh*2];
                float vy = acc[mb][nf][hh*2 + 1];
                if (EPI & 1) { vx += bias[n]; vy += bias[n + 1]; }
                if (EPI & 2) { vx = gelu_exact(vx); vy = gelu_exact(vy); }
                size_t o = (size_t)m * Nout + n;
                if (OUT == 2) {
                    *reinterpret_cast<uint32_t*>(Ch + o) = packh2(vx, vy);
                } else {
                    // fp32 streaming stores; Nout odd -> o parity = m parity
                    if (n + 1 < Nout) {
                        if ((o & 1) == 0) {
                            __stcs(reinterpret_cast<float2*>(C + o),
                                   make_float2(vx, vy));
                        } else {
                            __stcs(C + o, vx);
                            __stcs(C + o + 1, vy);
                        }
                    } else if (n < Nout) {
                        __stcs(C + o, vx);
                    }
                }
            }
        }
    }
}

// ---------------------------------------------------------------------------
// Narrow layer GEMM (wo, ff2): fp16 1-pass, CTA 128x128, 8 warps (4M x 2N),
// warp tile 32x64. 4-stage ring, 2 chunks per barrier.
// Output: fp32 x with bias+residual.
// ---------------------------------------------------------------------------
#define STGN (2*SUBT)                   // 32KB
#define GN_SMEM (4*STGN)                // 131072

__global__ __launch_bounds__(256, 1)
void gemm_n(const __half* __restrict__ A, const __half* __restrict__ B,
            const float* __restrict__ bias, const float* __restrict__ resid,
            float* __restrict__ C, int Nout, int K) {
    extern __shared__ char smem[];
    uint32_t sb = smem_u32(smem);
    const int tid = threadIdx.x;
    const int lane = tid & 31, wid = tid >> 5;
    const int m0 = blockIdx.y * 128, n0 = blockIdx.x * 128;
    const int warp_m = (wid >> 1) * 32;
    const int warp_n = (wid & 1) * 64;

    float acc[2][8][4];
    #pragma unroll
    for (int i = 0; i < 2; i++)
        #pragma unroll
        for (int j = 0; j < 8; j++)
            #pragma unroll
            for (int e = 0; e < 4; e++) acc[i][j][e] = 0.f;

    const int nch = K >> 6;   // 8 or 32 (even)

    auto load_stage = [&](int buf, int k0) {
        uint32_t base = sb + buf * STGN;
        #pragma unroll
        for (int sub = 0; sub < 2; sub++) {
            const __half* P = sub ? B : A;
            int row0 = sub ? n0 : m0;
            uint32_t dbase = base + sub * SUBT;
            #pragma unroll
            for (int it = 0; it < 4; it++) {
                int u = tid + it * 256;
                int row = u >> 3, c = u & 7;
                uint32_t dst = dbase + row * 128 + ((c ^ (row & 7)) * 16);
                cp_async16(dst, P + (size_t)(row0 + row) * K + k0 + c * 8, 16);
            }
        }
    };

    int ra[2];
    ra[0] = warp_m + (lane & 15);
    ra[1] = ra[0] + 16;
    const int ca = lane >> 4;
    int rB[4];
    #pragma unroll
    for (int nb = 0; nb < 4; nb++)
        rB[nb] = warp_n + nb * 16 + ((lane >> 4) & 1) * 8 + (lane & 7);
    const int kcB = (lane >> 3) & 1;

    auto compute = [&](int buf) {
        uint32_t base = sb + buf * STGN;
        #pragma unroll
        for (int ks = 0; ks < 4; ks++) {
            uint32_t a[2][4], b[4][4];
            #pragma unroll
            for (int mb = 0; mb < 2; mb++) {
                uint32_t off = ra[mb] * 128 + (((ks*2 + ca) ^ (ra[mb] & 7)) * 16);
                ldm4(a[mb], base + off);
            }
            #pragma unroll
            for (int nb = 0; nb < 4; nb++) {
                uint32_t off = rB[nb] * 128 + (((ks*2 + kcB) ^ (rB[nb] & 7)) * 16);
                ldm4(b[nb], base + SUBT + off);
            }
            #pragma unroll
            for (int mb = 0; mb < 2; mb++)
                #pragma unroll
                for (int nb = 0; nb < 4; nb++) {
                    mma16816h(acc[mb][nb*2],   a[mb], b[nb][0], b[nb][1]);
                    mma16816h(acc[mb][nb*2+1], a[mb], b[nb][2], b[nb][3]);
                }
        }
    };

    load_stage(0, 0);
    CP_COMMIT();
    load_stage(1, 64);
    CP_COMMIT();
    for (int c = 0; c < nch; c += 2) {
        cp_wait<0>();
        __syncthreads();
        if (c + 2 < nch) { load_stage((c + 2) & 3, (c + 2) << 6); CP_COMMIT(); }
        if (c + 3 < nch) { load_stage((c + 3) & 3, (c + 3) << 6); CP_COMMIT(); }
        compute(c & 3);
        compute((c + 1) & 3);
    }

    const int gid = lane >> 2, qid = lane & 3;
    #pragma unroll
    for (int mb = 0; mb < 2; mb++) {
        #pragma unroll
        for (int nf = 0; nf < 8; nf++) {
            int n = n0 + warp_n + nf * 8 + qid * 2;
            #pragma unroll
            for (int hh = 0; hh < 2; hh++) {
                int m = m0 + warp_m + mb * 16 + gid + hh * 8;
                float vx = acc[mb][nf][hh*2];
                float vy = acc[mb][nf][hh*2 + 1];
                vx += bias[n]; vy += bias[n + 1];
                size_t o = (size_t)m * Nout + n;
                float2 r = *reinterpret_cast<const float2*>(resid + o);
                vx += r.x; vy += r.y;
                *reinterpret_cast<float2*>(C + o) = make_float2(vx, vy);
            }
        }
    }
}

// ---------------------------------------------------------------------------
// Tensor-core causal flash attention (fp16 mma, fp32 softmax).
// CTA: 128 thr (4 warps), 64 queries (16/warp). grid (S/64, B*H).
// ---------------------------------------------------------------------------
__global__ __launch_bounds__(128)
void attn_mma(const __half* __restrict__ qkv,
              __half* __restrict__ ctx) {
    __shared__ __align__(16) char sQ[8192];
    __shared__ __align__(16) char sK[2][8192];
    __shared__ __align__(16) char sV[2][8192];
    int bh = blockIdx.y;
    int b = bh >> 3, h = bh & 7;
    int qb = gridDim.x - 1 - blockIdx.x;      // heavy blocks first
    int tid = threadIdx.x, lane = tid & 31, wid = tid >> 5;
    int warp_q = wid * 16;
    const int gid = lane >> 2, qid = lane & 3;
    uint32_t sQb = smem_u32(sQ);
    uint32_t sKb[2] = {smem_u32(sK[0]), smem_u32(sK[1])};
    uint32_t sVb[2] = {smem_u32(sV[0]), smem_u32(sV[1])};

    size_t tokbase = (size_t)b * SS;

    #pragma unroll
    for (int it = 0; it < 4; it++) {
        int u = tid + it * 128;
        int row = u >> 3, c = u & 7;
        uint32_t dst = sQb + row * 128 + ((c ^ (row & 7)) * 16);
        const __half* g = qkv + (tokbase + qb*64 + row) * QKVD + h*DH + c*8;
        cp_async16(dst, g, 16);
    }
    auto load_kv = [&](int buf, int t) {
        #pragma unroll
        for (int it = 0; it < 4; it++) {
            int u = tid + it * 128;
            int row = u >> 3, c = u & 7;
            uint32_t sw = row * 128 + ((c ^ (row & 7)) * 16);
            const __half* gk = qkv + (tokbase + t*64 + row) * QKVD + DD + h*DH + c*8;
            const __half* gv = qkv + (tokbase + t*64 + row) * QKVD + 2*DD + h*DH + c*8;
            cp_async16(sKb[buf] + sw, gk, 16);
            cp_async16(sVb[buf] + sw, gv, 16);
        }
    };
    load_kv(0, 0);
    CP_COMMIT();
    cp_wait<0>();
    __syncthreads();

    uint32_t qa[4][4];
    {
        int r = warp_q + (lane & 15);
        int chalf = lane >> 4;
        #pragma unroll
        for (int ks = 0; ks < 4; ks++) {
            int c = ks*2 + chalf;
            ldm4(qa[ks], sQb + r * 128 + ((c ^ (r & 7)) * 16));
        }
    }

    float m0v = -1e30f, m1v = -1e30f, l0 = 0.f, l1 = 0.f;
    float oacc[8][4];
    #pragma unroll
    for (int i = 0; i < 8; i++)
        #pragma unroll
        for (int e = 0; e < 4; e++) oacc[i][e] = 0.f;

    const int rloc0 = warp_q + gid;

    for (int t = 0; t <= qb; t++) {
        int buf = t & 1;
        if (t < qb) { load_kv(buf ^ 1, t + 1); CP_COMMIT(); }

        float sacc[8][4];
        #pragma unroll
        for (int i = 0; i < 8; i++)
            #pragma unroll
            for (int e = 0; e < 4; e++) sacc[i][e] = 0.f;
        {
            int rb = ((lane >> 4) & 1) * 8 + (lane & 7);
            int kc = (lane >> 3) & 1;
            #pragma unroll
            for (int ks = 0; ks < 4; ks++) {
                uint32_t kb[4][4];
                #pragma unroll
                for (int nb = 0; nb < 4; nb++) {
                    int r = nb*16 + rb;
                    int c = ks*2 + kc;
                    ldm4(kb[nb], sKb[buf] + r * 128 + ((c ^ (r & 7)) * 16));
                }
                #pragma unroll
                for (int nb = 0; nb < 4; nb++) {
                    mma16816h(sacc[nb*2],   qa[ks], kb[nb][0], kb[nb][1]);
                    mma16816h(sacc[nb*2+1], qa[ks], kb[nb][2], kb[nb][3]);
                }
            }
        }
        #pragma unroll
        for (int i = 0; i < 8; i++)
            #pragma unroll
            for (int e = 0; e < 4; e++) sacc[i][e] *= 0.125f;
        if (t == qb) {
            #pragma unroll
            for (int i = 0; i < 8; i++) {
                int col = i*8 + qid*2;
                #pragma unroll
                for (int e = 0; e < 4; e++) {
                    int cc = col + (e & 1);
                    int rr = rloc0 + ((e >> 1) * 8);
                    if (cc > rr) sacc[i][e] = -1e30f;
                }
            }
        }
        float rmax0 = -1e30f, rmax1 = -1e30f;
        #pragma unroll
        for (int i = 0; i < 8; i++) {
            rmax0 = fmaxf(rmax0, fmaxf(sacc[i][0], sacc[i][1]));
            rmax1 = fmaxf(rmax1, fmaxf(sacc[i][2], sacc[i][3]));
        }
        #pragma unroll
        for (int o = 1; o <= 2; o <<= 1) {
            rmax0 = fmaxf(rmax0, __shfl_xor_sync(0xffffffffu, rmax0, o));
            rmax1 = fmaxf(rmax1, __shfl_xor_sync(0xffffffffu, rmax1, o));
        }
        float mn0 = fmaxf(m0v, rmax0), mn1 = fmaxf(m1v, rmax1);
        float cor0 = __expf(m0v - mn0), cor1 = __expf(m1v - mn1);
        m0v = mn0; m1v = mn1;
        float rs0 = 0.f, rs1 = 0.f;
        float p[8][4];
        #pragma unroll
        for (int i = 0; i < 8; i++) {
            p[i][0] = __expf(sacc[i][0] - mn0);
            p[i][1] = __expf(sacc[i][1] - mn0);
            p[i][2] = __expf(sacc[i][2] - mn1);
            p[i][3] = __expf(sacc[i][3] - mn1);
            rs0 += p[i][0] + p[i][1];
            rs1 += p[i][2] + p[i][3];
        }
        #pragma unroll
        for (int o = 1; o <= 2; o <<= 1) {
            rs0 += __shfl_xor_sync(0xffffffffu, rs0, o);
            rs1 += __shfl_xor_sync(0xffffffffu, rs1, o);
        }
        l0 = l0 * cor0 + rs0;
        l1 = l1 * cor1 + rs1;
        #pragma unroll
        for (int i = 0; i < 8; i++) {
            oacc[i][0] *= cor0; oacc[i][1] *= cor0;
            oacc[i][2] *= cor1; oacc[i][3] *= cor1;
        }
        uint32_t pa[4][4];
        #pragma unroll
        for (int kk = 0; kk < 4; kk++) {
            pa[kk][0] = packh2(p[2*kk][0],   p[2*kk][1]);
            pa[kk][1] = packh2(p[2*kk][2],   p[2*kk][3]);
            pa[kk][2] = packh2(p[2*kk+1][0], p[2*kk+1][1]);
            pa[kk][3] = packh2(p[2*kk+1][2], p[2*kk+1][3]);
        }
        {
            int rv = ((lane >> 3) & 1) * 8 + (lane & 7);
            int cv = lane >> 4;
            #pragma unroll
            for (int kk = 0; kk < 4; kk++) {
                uint32_t vb[4][4];
                #pragma unroll
                for (int nd = 0; nd < 4; nd++) {
                    int r = kk*16 + rv;
                    int c = nd*2 + cv;
                    ldm4t(vb[nd], sVb[buf] + r * 128 + ((c ^ (r & 7)) * 16));
                }
                #pragma unroll
                for (int nd = 0; nd < 4; nd++) {
                    mma16816h(oacc[nd*2],   pa[kk], vb[nd][0], vb[nd][1]);
                    mma16816h(oacc[nd*2+1], pa[kk], vb[nd][2], vb[nd][3]);
                }
            }
        }
        if (t < qb) cp_wait<0>();
        __syncthreads();
    }

    float inv0 = 1.0f / l0, inv1 = 1.0f / l1;
    size_t tok0 = tokbase + qb*64 + rloc0;
    #pragma unroll
    for (int nd = 0; nd < 8; nd++) {
        int col = h*DH + nd*8 + qid*2;
        *reinterpret_cast<uint32_t*>(ctx + tok0 * DD + col) =
            packh2(oacc[nd][0] * inv0, oacc[nd][1] * inv0);
        *reinterpret_cast<uint32_t*>(ctx + (tok0 + 8) * DD + col) =
            packh2(oacc[nd][2] * inv1, oacc[nd][3] * inv1);
    }
}

// ---------------------------------------------------------------------------
// Host launch
// ---------------------------------------------------------------------------
extern "C" void kernel_launch(void* const* d_in, const int* in_sizes, int n_in,
                              void* d_out, int out_size) {
    const int*   ids   = (const int*)  d_in[0];
    const float* emb   = (const float*)d_in[1];
    const float* pe    = (const float*)d_in[2];
    const float* wq    = (const float*)d_in[3];
    const float* wk    = (const float*)d_in[4];
    const float* wv    = (const float*)d_in[5];
    const float* wo    = (const float*)d_in[6];
    const float* wo_b  = (const float*)d_in[7];
    const float* w1    = (const float*)d_in[8];
    const float* b1    = (const float*)d_in[9];
    const float* w2    = (const float*)d_in[10];
    const float* b2    = (const float*)d_in[11];
    const float* ln1_g = (const float*)d_in[12];
    const float* ln1_b = (const float*)d_in[13];
    const float* ln2_g = (const float*)d_in[14];
    const float* ln2_b = (const float*)d_in[15];
    const float* lnf_g = (const float*)d_in[16];
    const float* lnf_b = (const float*)d_in[17];
    float* out = (float*)d_out;

    float *x;
    __half *qkvh, *h16, *ctx, *ff;
    __half *wqkvT, *woT, *w1T, *w2T, *hf, *embH;
    cudaGetSymbolAddress((void**)&x, g_x);
    cudaGetSymbolAddress((void**)&qkvh, g_qkvh);
    cudaGetSymbolAddress((void**)&h16, g_h);
    cudaGetSymbolAddress((void**)&ctx, g_ctx);
    cudaGetSymbolAddress((void**)&ff, g_ff);
    cudaGetSymbolAddress((void**)&wqkvT, g_wqkvT);
    cudaGetSymbolAddress((void**)&woT, g_woT);
    cudaGetSymbolAddress((void**)&w1T, g_w1T);
    cudaGetSymbolAddress((void**)&w2T, g_w2T);
    cudaGetSymbolAddress((void**)&hf, g_hf);
    cudaGetSymbolAddress((void**)&embH, g_embH);

    cudaFuncSetAttribute((void*)gemm_w<0, 2, false, false>, cudaFuncAttributeMaxDynamicSharedMemorySize, GW_SMEM);
    cudaFuncSetAttribute((void*)gemm_w<3, 2, false, false>, cudaFuncAttributeMaxDynamicSharedMemorySize, GW_SMEM);
    cudaFuncSetAttribute((void*)gemm_w<0, 0, true, true  >, cudaFuncAttributeMaxDynamicSharedMemorySize, GW_SMEM);
    cudaFuncSetAttribute((void*)gemm_n, cudaFuncAttributeMaxDynamicSharedMemorySize, GN_SMEM);

    // weight conversions (fp16 single, transposed)
    dim3 cb(32, 8);
    conv_wTh<<<dim3(DD/32, DD/32), cb>>>(wq, wqkvT,           DD, DD);
    conv_wTh<<<dim3(DD/32, DD/32), cb>>>(wk, wqkvT + DD*DD,   DD, DD);
    conv_wTh<<<dim3(DD/32, DD/32), cb>>>(wv, wqkvT + 2*DD*DD, DD, DD);
    conv_wTh<<<dim3(DD/32, DD/32), cb>>>(wo, woT, DD, DD);
    conv_wTh<<<dim3(FFD/32, DD/32), cb>>>(w1, w1T, DD, FFD);
    conv_wTh<<<dim3(DD/32, FFD/32), cb>>>(w2, w2T, FFD, DD);
    {
        int n4 = VV * DD / 4;
        conv_half4<<<(n4 + 255) / 256, 256>>>(emb, embH, n4);
    }

    embed_kernel<<<NN, 128>>>(ids, emb, pe, x);

    dim3 gQKV(QKVD/256, NN/128);     // (6, 32)
    dim3 gProj(DD/128, NN/128);      // (4, 32)
    dim3 gFF1(FFD/256, NN/128);      // (8, 32)
    dim3 gAttn(SS/64, BB*HH);        // (16, 32)

    for (int layer = 0; layer < NLAYERS; layer++) {
        ln_kernel<<<NN, 128>>>(x, (uint32_t*)h16, ln1_g, ln1_b);
        gemm_w<0, 2, false, false><<<gQKV, 256, GW_SMEM>>>(
            h16, wqkvT, nullptr, nullptr, qkvh, QKVD, DD);
        attn_mma<<<gAttn, 128>>>(qkvh, ctx);
        gemm_n<<<gProj, 256, GN_SMEM>>>(
            ctx, woT, wo_b, x, x, DD, DD);
        ln_kernel<<<NN, 128>>>(x, (uint32_t*)h16, ln2_g, ln2_b);
        gemm_w<3, 2, false, false><<<gFF1, 256, GW_SMEM>>>(
            h16, w1T, b1, nullptr, ff, FFD, DD);
        gemm_n<<<gProj, 256, GN_SMEM>>>(
            ff, w2T, b2, x, x, DD, FFD);
    }

    ln_kernel<<<NN, 128>>>(x, (uint32_t*)hf, lnf_g, lnf_b);

    // LM head: M-fastest grid for B L2 reuse; streaming output stores.
    dim3 gLM(NN / 128, (VV + 255) / 256);   // (32, 197)
    gemm_w<0, 0, true, true><<<gLM, 256, GW_SMEM>>>(
        hf, embH, nullptr, out, nullptr, VV, DD);
}

// round 17
// speedup vs baseline: 7.4306x; 1.0214x over previous
#include <cuda_runtime.h>
#include <cuda_bf16.h>
#include <cuda_fp16.h>
#include <math.h>
#include <stdint.h>

// Problem constants
#define BB 4
#define SS 1024
#define NN (BB*SS)      // 4096 tokens
#define DD 512
#define HH 8
#define DH 64
#define FFD 2048
#define VV 50257
#define NLAYERS 6
#define QKVD 1536       // fused qkv width

// ---------------------------------------------------------------------------
// Scratch (allocation-free: __device__ globals) — all activations single fp16
// ---------------------------------------------------------------------------
__device__ float g_x[NN*DD];
__device__ __half g_h[NN*DD];
__device__ __half g_qkvh[NN*QKVD];
__device__ __half g_ctx[NN*DD];
__device__ __half g_ff[NN*FFD];
// transposed fp16 weights [N,K]
__device__ __half g_wqkvT[3*DD*DD];
__device__ __half g_woT[DD*DD];
__device__ __half g_w1T[FFD*DD];
__device__ __half g_w2T[DD*FFD];
// LM head
__device__ __half g_hf[NN*DD];
__device__ __half g_embH[VV*DD];

// ---------------------------------------------------------------------------
// Helpers
// ---------------------------------------------------------------------------
__device__ __forceinline__ uint32_t smem_u32(const void* p) {
    uint32_t a;
    asm("{ .reg .u64 t; cvta.to.shared.u64 t, %1; cvt.u32.u64 %0, t; }"
        : "=r"(a) : "l"(p));
    return a;
}

__device__ __forceinline__ void ldm4(uint32_t* r, uint32_t addr) {
    asm volatile("ldmatrix.sync.aligned.m8n8.x4.shared.b16 {%0,%1,%2,%3}, [%4];"
                 : "=r"(r[0]), "=r"(r[1]), "=r"(r[2]), "=r"(r[3]) : "r"(addr));
}
__device__ __forceinline__ void ldm4t(uint32_t* r, uint32_t addr) {
    asm volatile("ldmatrix.sync.aligned.m8n8.x4.trans.shared.b16 {%0,%1,%2,%3}, [%4];"
                 : "=r"(r[0]), "=r"(r[1]), "=r"(r[2]), "=r"(r[3]) : "r"(addr));
}

__device__ __forceinline__ void mma16816h(float* c, const uint32_t* a,
                                          uint32_t b0, uint32_t b1) {
    asm volatile(
        "mma.sync.aligned.m16n8k16.row.col.f32.f16.f16.f32 "
        "{%0,%1,%2,%3}, {%4,%5,%6,%7}, {%8,%9}, {%0,%1,%2,%3};"
        : "+f"(c[0]), "+f"(c[1]), "+f"(c[2]), "+f"(c[3])
        : "r"(a[0]), "r"(a[1]), "r"(a[2]), "r"(a[3]), "r"(b0), "r"(b1));
}

__device__ __forceinline__ void cp_async16(uint32_t dst, const void* src, int szbytes) {
    asm volatile("cp.async.cg.shared.global [%0], [%1], 16, %2;"
                 :: "r"(dst), "l"(src), "r"(szbytes));
}
#define CP_COMMIT() asm volatile("cp.async.commit_group;" ::: "memory")
template<int N>
__device__ __forceinline__ void cp_wait() {
    asm volatile("cp.async.wait_group %0;" :: "n"(N) : "memory");
}

__device__ __forceinline__ uint32_t packh2(float x, float y) {
    __half2 t = __floats2half2_rn(x, y);
    return *reinterpret_cast<uint32_t*>(&t);
}

__device__ __forceinline__ float gelu_exact(float v) {
    return 0.5f * v * (1.0f + erff(v * 0.70710678118654752f));
}

// ---------------------------------------------------------------------------
// Weight conversion: W [K,N] fp32 -> fp16 [N,K] (transpose)
// ---------------------------------------------------------------------------
__global__ void conv_wTh(const float* __restrict__ W, __half* __restrict__ o16,
                         int K, int N) {
    __shared__ float t[32][33];
    int n0 = blockIdx.x * 32, k0 = blockIdx.y * 32;
    int tx = threadIdx.x, ty = threadIdx.y;
    #pragma unroll
    for (int r = 0; r < 4; r++)
        t[ty + r*8][tx] = W[(size_t)(k0 + ty + r*8) * N + n0 + tx];
    __syncthreads();
    #pragma unroll
    for (int r = 0; r < 4; r++)
        o16[(size_t)(n0 + ty + r*8) * K + k0 + tx] = __float2half_rn(t[tx][ty + r*8]);
}

// Elementwise fp32 -> fp16
__global__ void conv_half4(const float* __restrict__ src,
                           __half* __restrict__ dst, int n4) {
    int i = blockIdx.x * 256 + threadIdx.x;
    if (i >= n4) return;
    float4 v = reinterpret_cast<const float4*>(src)[i];
    uint2 o;
    o.x = packh2(v.x, v.y);
    o.y = packh2(v.z, v.w);
    reinterpret_cast<uint2*>(dst)[i] = o;
}

// ---------------------------------------------------------------------------
// Embedding
// ---------------------------------------------------------------------------
__global__ void embed_kernel(const int* __restrict__ ids,
                             const float* __restrict__ emb,
                             const float* __restrict__ pe,
                             float* __restrict__ x) {
    int n = blockIdx.x;
    int tid = threadIdx.x;
    int id = ids[n];
    int s = n & (SS - 1);
    const float sq = 22.62741699796952f;
    float4 e = reinterpret_cast<const float4*>(emb + (size_t)id * DD)[tid];
    float4 p = reinterpret_cast<const float4*>(pe + (size_t)s * DD)[tid];
    float4 o;
    o.x = e.x * sq + p.x; o.y = e.y * sq + p.y;
    o.z = e.z * sq + p.z; o.w = e.w * sq + p.w;
    reinterpret_cast<float4*>(x + (size_t)n * DD)[tid] = o;
}

// ---------------------------------------------------------------------------
// LayerNorm -> single fp16
// ---------------------------------------------------------------------------
__global__ void ln_kernel(const float* __restrict__ in,
                          uint32_t* __restrict__ out16,
                          const float* __restrict__ g, const float* __restrict__ b) {
    int row = blockIdx.x;
    int tid = threadIdx.x;    // 128
    float4 v = reinterpret_cast<const float4*>(in + (size_t)row * DD)[tid];
    float s = v.x + v.y + v.z + v.w;
    float ss = v.x*v.x + v.y*v.y + v.z*v.z + v.w*v.w;
    #pragma unroll
    for (int o = 16; o > 0; o >>= 1) {
        s  += __shfl_xor_sync(0xffffffffu, s, o);
        ss += __shfl_xor_sync(0xffffffffu, ss, o);
    }
    __shared__ float rs[4], rss[4];
    int warp = tid >> 5;
    if ((tid & 31) == 0) { rs[warp] = s; rss[warp] = ss; }
    __syncthreads();
    float mean = (rs[0]+rs[1]+rs[2]+rs[3]) * (1.0f/DD);
    float var  = (rss[0]+rss[1]+rss[2]+rss[3]) * (1.0f/DD) - mean*mean;
    float rstd = rsqrtf(var + 1e-5f);
    float4 gg = reinterpret_cast<const float4*>(g)[tid];
    float4 bb = reinterpret_cast<const float4*>(b)[tid];
    float4 o;
    o.x = (v.x - mean)*rstd*gg.x + bb.x;
    o.y = (v.y - mean)*rstd*gg.y + bb.y;
    o.z = (v.z - mean)*rstd*gg.z + bb.z;
    o.w = (v.w - mean)*rstd*gg.w + bb.w;
    uint2 hh;
    hh.x = packh2(o.x, o.y);
    hh.y = packh2(o.z, o.w);
    reinterpret_cast<uint2*>(out16)[(size_t)row * (DD/4) + tid] = hh;
}

#define SUBT 16384                      // 128 rows x 128B

// ---------------------------------------------------------------------------
// Wide GEMM (ff1, LM head): fp16 1-pass, CTA 128x256, 8 warps (2M x 4N),
// warp tile 64x64. 4-stage ring, 2 chunks per barrier.
// EPI: 1=bias, 2=gelu. OUT: 0=f32 guarded streaming (LM), 2=fp16.
// SWAP: blockIdx.x indexes M (LM head: M-fastest for B L2 reuse).
// ---------------------------------------------------------------------------
#define STGW (3*SUBT)                   // 48KB
#define GW_SMEM (4*STGW)                // 196608

template<int EPI, int OUT, bool GUARD, bool SWAP>
__global__ __launch_bounds__(256, 1)
void gemm_w(const __half* __restrict__ A, const __half* __restrict__ B,
            const float* __restrict__ bias,
            float* __restrict__ C, __half* __restrict__ Ch,
            int Nout, int K) {
    extern __shared__ char smem[];
    uint32_t sb = smem_u32(smem);
    const int tid = threadIdx.x;
    const int lane = tid & 31, wid = tid >> 5;
    const int m0 = (SWAP ? blockIdx.x : blockIdx.y) * 128;
    const int n0 = (SWAP ? blockIdx.y : blockIdx.x) * 256;
    const int warp_m = (wid >> 2) * 64;
    const int warp_n = (wid & 3) * 64;

    float acc[4][8][4];
    #pragma unroll
    for (int i = 0; i < 4; i++)
        #pragma unroll
        for (int j = 0; j < 8; j++)
            #pragma unroll
            for (int e = 0; e < 4; e++) acc[i][j][e] = 0.f;

    const int nch = K >> 6;   // 8 (even)

    auto load_stage = [&](int buf, int k0) {
        uint32_t base = sb + buf * STGW;
        #pragma unroll
        for (int it = 0; it < 4; it++) {
            int u = tid + it * 256;
            int row = u >> 3, c = u & 7;
            uint32_t dst = base + row * 128 + ((c ^ (row & 7)) * 16);
            cp_async16(dst, A + (size_t)(m0 + row) * K + k0 + c * 8, 16);
        }
        #pragma unroll
        for (int it = 0; it < 8; it++) {
            int u = tid + it * 256;
            int row = u >> 3, c = u & 7;
            uint32_t dst = base + SUBT + row * 128 + ((c ^ (row & 7)) * 16);
            const __half* g = B + (size_t)(n0 + row) * K + k0 + c * 8;
            int sz = 16;
            if (GUARD && (n0 + row >= Nout)) { g = B; sz = 0; }
            cp_async16(dst, g, sz);
        }
    };

    int ra[4];
    #pragma unroll
    for (int mb = 0; mb < 4; mb++) ra[mb] = warp_m + mb * 16 + (lane & 15);
    const int ca = lane >> 4;
    int rB[4];
    #pragma unroll
    for (int nb = 0; nb < 4; nb++)
        rB[nb] = warp_n + nb * 16 + ((lane >> 4) & 1) * 8 + (lane & 7);
    const int kcB = (lane >> 3) & 1;

    auto compute = [&](int buf) {
        uint32_t base = sb + buf * STGW;
        #pragma unroll
        for (int ks = 0; ks < 4; ks++) {
            uint32_t a[4][4], b[4][4];
            #pragma unroll
            for (int mb = 0; mb < 4; mb++) {
                uint32_t off = ra[mb] * 128 + (((ks*2 + ca) ^ (ra[mb] & 7)) * 16);
                ldm4(a[mb], base + off);
            }
            #pragma unroll
            for (int nb = 0; nb < 4; nb++) {
                uint32_t off = rB[nb] * 128 + (((ks*2 + kcB) ^ (rB[nb] & 7)) * 16);
                ldm4(b[nb], base + SUBT + off);
            }
            #pragma unroll
            for (int mb = 0; mb < 4; mb++)
                #pragma unroll
                for (int nb = 0; nb < 4; nb++) {
                    mma16816h(acc[mb][nb*2],   a[mb], b[nb][0], b[nb][1]);
                    mma16816h(acc[mb][nb*2+1], a[mb], b[nb][2], b[nb][3]);
                }
        }
    };

    load_stage(0, 0);
    CP_COMMIT();
    load_stage(1, 64);
    CP_COMMIT();
    for (int c = 0; c < nch; c += 2) {
        cp_wait<0>();
        __syncthreads();
        if (c + 2 < nch) { load_stage((c + 2) & 3, (c + 2) << 6); CP_COMMIT(); }
        if (c + 3 < nch) { load_stage((c + 3) & 3, (c + 3) << 6); CP_COMMIT(); }
        compute(c & 3);
        compute((c + 1) & 3);
    }

    const int gid = lane >> 2, qid = lane & 3;
    #pragma unroll
    for (int mb = 0; mb < 4; mb++) {
        #pragma unroll
        for (int nf = 0; nf < 8; nf++) {
            int n = n0 + warp_n + nf * 8 + qid * 2;
            #pragma unroll
            for (int hh = 0; hh < 2; hh++) {
                int m = m0 + warp_m + mb * 16 + gid + hh * 8;
                float vx = acc[mb][nf][hh*2];
                float vy = acc[mb][nf][hh*2 + 1];
                if (EPI & 1) { vx += bias[n]; vy += bias[n + 1]; }
                if (EPI & 2) { vx = gelu_exact(vx); vy = gelu_exact(vy); }
                size_t o = (size_t)m * Nout + n;
                if (OUT == 2) {
                    *reinterpret_cast<uint32_t*>(Ch + o) = packh2(vx, vy);
                } else {
                    // fp32 streaming stores; Nout odd -> o parity = m parity
                    if (n + 1 < Nout) {
                        if ((o & 1) == 0) {
                            __stcs(reinterpret_cast<float2*>(C + o),
                                   make_float2(vx, vy));
                        } else {
                            __stcs(C + o, vx);
                            __stcs(C + o + 1, vy);
                        }
                    } else if (n < Nout) {
                        __stcs(C + o, vx);
                    }
                }
            }
        }
    }
}

// ---------------------------------------------------------------------------
// Narrow layer GEMM (qkv, wo, ff2): fp16 1-pass, CTA 128x128, 8 warps
// (4M x 2N), warp tile 32x64. 4-stage ring, 2 chunks per barrier.
// OUT 0: fp32 + bias + residual (wo/ff2).  OUT 2: fp16, no bias (qkv).
// ---------------------------------------------------------------------------
#define STGN (2*SUBT)                   // 32KB
#define GN_SMEM (4*STGN)                // 131072

template<int OUT>
__global__ __launch_bounds__(256, 1)
void gemm_n(const __half* __restrict__ A, const __half* __restrict__ B,
            const float* __restrict__ bias, const float* __restrict__ resid,
            float* __restrict__ C, __half* __restrict__ Ch, int Nout, int K) {
    extern __shared__ char smem[];
    uint32_t sb = smem_u32(smem);
    const int tid = threadIdx.x;
    const int lane = tid & 31, wid = tid >> 5;
    const int m0 = blockIdx.y * 128, n0 = blockIdx.x * 128;
    const int warp_m = (wid >> 1) * 32;
    const int warp_n = (wid & 1) * 64;

    float acc[2][8][4];
    #pragma unroll
    for (int i = 0; i < 2; i++)
        #pragma unroll
        for (int j = 0; j < 8; j++)
            #pragma unroll
            for (int e = 0; e < 4; e++) acc[i][j][e] = 0.f;

    const int nch = K >> 6;   // 8 or 32 (even)

    auto load_stage = [&](int buf, int k0) {
        uint32_t base = sb + buf * STGN;
        #pragma unroll
        for (int sub = 0; sub < 2; sub++) {
            const __half* P = sub ? B : A;
            int row0 = sub ? n0 : m0;
            uint32_t dbase = base + sub * SUBT;
            #pragma unroll
            for (int it = 0; it < 4; it++) {
                int u = tid + it * 256;
                int row = u >> 3, c = u & 7;
                uint32_t dst = dbase + row * 128 + ((c ^ (row & 7)) * 16);
                cp_async16(dst, P + (size_t)(row0 + row) * K + k0 + c * 8, 16);
            }
        }
    };

    int ra[2];
    ra[0] = warp_m + (lane & 15);
    ra[1] = ra[0] + 16;
    const int ca = lane >> 4;
    int rB[4];
    #pragma unroll
    for (int nb = 0; nb < 4; nb++)
        rB[nb] = warp_n + nb * 16 + ((lane >> 4) & 1) * 8 + (lane & 7);
    const int kcB = (lane >> 3) & 1;

    auto compute = [&](int buf) {
        uint32_t base = sb + buf * STGN;
        #pragma unroll
        for (int ks = 0; ks < 4; ks++) {
            uint32_t a[2][4], b[4][4];
            #pragma unroll
            for (int mb = 0; mb < 2; mb++) {
                uint32_t off = ra[mb] * 128 + (((ks*2 + ca) ^ (ra[mb] & 7)) * 16);
                ldm4(a[mb], base + off);
            }
            #pragma unroll
            for (int nb = 0; nb < 4; nb++) {
                uint32_t off = rB[nb] * 128 + (((ks*2 + kcB) ^ (rB[nb] & 7)) * 16);
                ldm4(b[nb], base + SUBT + off);
            }
            #pragma unroll
            for (int mb = 0; mb < 2; mb++)
                #pragma unroll
                for (int nb = 0; nb < 4; nb++) {
                    mma16816h(acc[mb][nb*2],   a[mb], b[nb][0], b[nb][1]);
                    mma16816h(acc[mb][nb*2+1], a[mb], b[nb][2], b[nb][3]);
                }
        }
    };

    load_stage(0, 0);
    CP_COMMIT();
    load_stage(1, 64);
    CP_COMMIT();
    for (int c = 0; c < nch; c += 2) {
        cp_wait<0>();
        __syncthreads();
        if (c + 2 < nch) { load_stage((c + 2) & 3, (c + 2) << 6); CP_COMMIT(); }
        if (c + 3 < nch) { load_stage((c + 3) & 3, (c + 3) << 6); CP_COMMIT(); }
        compute(c & 3);
        compute((c + 1) & 3);
    }

    const int gid = lane >> 2, qid = lane & 3;
    #pragma unroll
    for (int mb = 0; mb < 2; mb++) {
        #pragma unroll
        for (int nf = 0; nf < 8; nf++) {
            int n = n0 + warp_n + nf * 8 + qid * 2;
            #pragma unroll
            for (int hh = 0; hh < 2; hh++) {
                int m = m0 + warp_m + mb * 16 + gid + hh * 8;
                float vx = acc[mb][nf][hh*2];
                float vy = acc[mb][nf][hh*2 + 1];
                size_t o = (size_t)m * Nout + n;
                if (OUT == 2) {
                    *reinterpret_cast<uint32_t*>(Ch + o) = packh2(vx, vy);
                } else {
                    vx += bias[n]; vy += bias[n + 1];
                    float2 r = *reinterpret_cast<const float2*>(resid + o);
                    vx += r.x; vy += r.y;
                    *reinterpret_cast<float2*>(C + o) = make_float2(vx, vy);
                }
            }
        }
    }
}

// ---------------------------------------------------------------------------
// Tensor-core causal flash attention (fp16 mma, fp32 softmax).
// CTA: 128 thr (4 warps), 64 queries (16/warp). grid (S/64, B*H).
// ---------------------------------------------------------------------------
__global__ __launch_bounds__(128)
void attn_mma(const __half* __restrict__ qkv,
              __half* __restrict__ ctx) {
    __shared__ __align__(16) char sQ[8192];
    __shared__ __align__(16) char sK[2][8192];
    __shared__ __align__(16) char sV[2][8192];
    int bh = blockIdx.y;
    int b = bh >> 3, h = bh & 7;
    int qb = gridDim.x - 1 - blockIdx.x;      // heavy blocks first
    int tid = threadIdx.x, lane = tid & 31, wid = tid >> 5;
    int warp_q = wid * 16;
    const int gid = lane >> 2, qid = lane & 3;
    uint32_t sQb = smem_u32(sQ);
    uint32_t sKb[2] = {smem_u32(sK[0]), smem_u32(sK[1])};
    uint32_t sVb[2] = {smem_u32(sV[0]), smem_u32(sV[1])};

    size_t tokbase = (size_t)b * SS;

    #pragma unroll
    for (int it = 0; it < 4; it++) {
        int u = tid + it * 128;
        int row = u >> 3, c = u & 7;
        uint32_t dst = sQb + row * 128 + ((c ^ (row & 7)) * 16);
        const __half* g = qkv + (tokbase + qb*64 + row) * QKVD + h*DH + c*8;
        cp_async16(dst, g, 16);
    }
    auto load_kv = [&](int buf, int t) {
        #pragma unroll
        for (int it = 0; it < 4; it++) {
            int u = tid + it * 128;
            int row = u >> 3, c = u & 7;
            uint32_t sw = row * 128 + ((c ^ (row & 7)) * 16);
            const __half* gk = qkv + (tokbase + t*64 + row) * QKVD + DD + h*DH + c*8;
            const __half* gv = qkv + (tokbase + t*64 + row) * QKVD + 2*DD + h*DH + c*8;
            cp_async16(sKb[buf] + sw, gk, 16);
            cp_async16(sVb[buf] + sw, gv, 16);
        }
    };
    load_kv(0, 0);
    CP_COMMIT();
    cp_wait<0>();
    __syncthreads();

    uint32_t qa[4][4];
    {
        int r = warp_q + (lane & 15);
        int chalf = lane >> 4;
        #pragma unroll
        for (int ks = 0; ks < 4; ks++) {
            int c = ks*2 + chalf;
            ldm4(qa[ks], sQb + r * 128 + ((c ^ (r & 7)) * 16));
        }
    }

    float m0v = -1e30f, m1v = -1e30f, l0 = 0.f, l1 = 0.f;
    float oacc[8][4];
    #pragma unroll
    for (int i = 0; i < 8; i++)
        #pragma unroll
        for (int e = 0; e < 4; e++) oacc[i][e] = 0.f;

    const int rloc0 = warp_q + gid;

    for (int t = 0; t <= qb; t++) {
        int buf = t & 1;
        if (t < qb) { load_kv(buf ^ 1, t + 1); CP_COMMIT(); }

        float sacc[8][4];
        #pragma unroll
        for (int i = 0; i < 8; i++)
            #pragma unroll
            for (int e = 0; e < 4; e++) sacc[i][e] = 0.f;
        {
            int rb = ((lane >> 4) & 1) * 8 + (lane & 7);
            int kc = (lane >> 3) & 1;
            #pragma unroll
            for (int ks = 0; ks < 4; ks++) {
                uint32_t kb[4][4];
                #pragma unroll
                for (int nb = 0; nb < 4; nb++) {
                    int r = nb*16 + rb;
                    int c = ks*2 + kc;
                    ldm4(kb[nb], sKb[buf] + r * 128 + ((c ^ (r & 7)) * 16));
                }
                #pragma unroll
                for (int nb = 0; nb < 4; nb++) {
                    mma16816h(sacc[nb*2],   qa[ks], kb[nb][0], kb[nb][1]);
                    mma16816h(sacc[nb*2+1], qa[ks], kb[nb][2], kb[nb][3]);
                }
            }
        }
        #pragma unroll
        for (int i = 0; i < 8; i++)
            #pragma unroll
            for (int e = 0; e < 4; e++) sacc[i][e] *= 0.125f;
        if (t == qb) {
            #pragma unroll
            for (int i = 0; i < 8; i++) {
                int col = i*8 + qid*2;
                #pragma unroll
                for (int e = 0; e < 4; e++) {
                    int cc = col + (e & 1);
                    int rr = rloc0 + ((e >> 1) * 8);
                    if (cc > rr) sacc[i][e] = -1e30f;
                }
            }
        }
        float rmax0 = -1e30f, rmax1 = -1e30f;
        #pragma unroll
        for (int i = 0; i < 8; i++) {
            rmax0 = fmaxf(rmax0, fmaxf(sacc[i][0], sacc[i][1]));
            rmax1 = fmaxf(rmax1, fmaxf(sacc[i][2], sacc[i][3]));
        }
        #pragma unroll
        for (int o = 1; o <= 2; o <<= 1) {
            rmax0 = fmaxf(rmax0, __shfl_xor_sync(0xffffffffu, rmax0, o));
            rmax1 = fmaxf(rmax1, __shfl_xor_sync(0xffffffffu, rmax1, o));
        }
        float mn0 = fmaxf(m0v, rmax0), mn1 = fmaxf(m1v, rmax1);
        float cor0 = __expf(m0v - mn0), cor1 = __expf(m1v - mn1);
        m0v = mn0; m1v = mn1;
        float rs0 = 0.f, rs1 = 0.f;
        float p[8][4];
        #pragma unroll
        for (int i = 0; i < 8; i++) {
            p[i][0] = __expf(sacc[i][0] - mn0);
            p[i][1] = __expf(sacc[i][1] - mn0);
            p[i][2] = __expf(sacc[i][2] - mn1);
            p[i][3] = __expf(sacc[i][3] - mn1);
            rs0 += p[i][0] + p[i][1];
            rs1 += p[i][2] + p[i][3];
        }
        #pragma unroll
        for (int o = 1; o <= 2; o <<= 1) {
            rs0 += __shfl_xor_sync(0xffffffffu, rs0, o);
            rs1 += __shfl_xor_sync(0xffffffffu, rs1, o);
        }
        l0 = l0 * cor0 + rs0;
        l1 = l1 * cor1 + rs1;
        #pragma unroll
        for (int i = 0; i < 8; i++) {
            oacc[i][0] *= cor0; oacc[i][1] *= cor0;
            oacc[i][2] *= cor1; oacc[i][3] *= cor1;
        }
        uint32_t pa[4][4];
        #pragma unroll
        for (int kk = 0; kk < 4; kk++) {
            pa[kk][0] = packh2(p[2*kk][0],   p[2*kk][1]);
            pa[kk][1] = packh2(p[2*kk][2],   p[2*kk][3]);
            pa[kk][2] = packh2(p[2*kk+1][0], p[2*kk+1][1]);
            pa[kk][3] = packh2(p[2*kk+1][2], p[2*kk+1][3]);
        }
        {
            int rv = ((lane >> 3) & 1) * 8 + (lane & 7);
            int cv = lane >> 4;
            #pragma unroll
            for (int kk = 0; kk < 4; kk++) {
                uint32_t vb[4][4];
                #pragma unroll
                for (int nd = 0; nd < 4; nd++) {
                    int r = kk*16 + rv;
                    int c = nd*2 + cv;
                    ldm4t(vb[nd], sVb[buf] + r * 128 + ((c ^ (r & 7)) * 16));
                }
                #pragma unroll
                for (int nd = 0; nd < 4; nd++) {
                    mma16816h(oacc[nd*2],   pa[kk], vb[nd][0], vb[nd][1]);
                    mma16816h(oacc[nd*2+1], pa[kk], vb[nd][2], vb[nd][3]);
                }
            }
        }
        if (t < qb) cp_wait<0>();
        __syncthreads();
    }

    float inv0 = 1.0f / l0, inv1 = 1.0f / l1;
    size_t tok0 = tokbase + qb*64 + rloc0;
    #pragma unroll
    for (int nd = 0; nd < 8; nd++) {
        int col = h*DH + nd*8 + qid*2;
        *reinterpret_cast<uint32_t*>(ctx + tok0 * DD + col) =
            packh2(oacc[nd][0] * inv0, oacc[nd][1] * inv0);
        *reinterpret_cast<uint32_t*>(ctx + (tok0 + 8) * DD + col) =
            packh2(oacc[nd][2] * inv1, oacc[nd][3] * inv1);
    }
}

// ---------------------------------------------------------------------------
// Host launch
// ---------------------------------------------------------------------------
extern "C" void kernel_launch(void* const* d_in, const int* in_sizes, int n_in,
                              void* d_out, int out_size) {
    const int*   ids   = (const int*)  d_in[0];
    const float* emb   = (const float*)d_in[1];
    const float* pe    = (const float*)d_in[2];
    const float* wq    = (const float*)d_in[3];
    const float* wk    = (const float*)d_in[4];
    const float* wv    = (const float*)d_in[5];
    const float* wo    = (const float*)d_in[6];
    const float* wo_b  = (const float*)d_in[7];
    const float* w1    = (const float*)d_in[8];
    const float* b1    = (const float*)d_in[9];
    const float* w2    = (const float*)d_in[10];
    const float* b2    = (const float*)d_in[11];
    const float* ln1_g = (const float*)d_in[12];
    const float* ln1_b = (const float*)d_in[13];
    const float* ln2_g = (const float*)d_in[14];
    const float* ln2_b = (const float*)d_in[15];
    const float* lnf_g = (const float*)d_in[16];
    const float* lnf_b = (const float*)d_in[17];
    float* out = (float*)d_out;

    float *x;
    __half *qkvh, *h16, *ctx, *ff;
    __half *wqkvT, *woT, *w1T, *w2T, *hf, *embH;
    cudaGetSymbolAddress((void**)&x, g_x);
    cudaGetSymbolAddress((void**)&qkvh, g_qkvh);
    cudaGetSymbolAddress((void**)&h16, g_h);
    cudaGetSymbolAddress((void**)&ctx, g_ctx);
    cudaGetSymbolAddress((void**)&ff, g_ff);
    cudaGetSymbolAddress((void**)&wqkvT, g_wqkvT);
    cudaGetSymbolAddress((void**)&woT, g_woT);
    cudaGetSymbolAddress((void**)&w1T, g_w1T);
    cudaGetSymbolAddress((void**)&w2T, g_w2T);
    cudaGetSymbolAddress((void**)&hf, g_hf);
    cudaGetSymbolAddress((void**)&embH, g_embH);

    cudaFuncSetAttribute((void*)gemm_w<3, 2, false, false>, cudaFuncAttributeMaxDynamicSharedMemorySize, GW_SMEM);
    cudaFuncSetAttribute((void*)gemm_w<0, 0, true, true  >, cudaFuncAttributeMaxDynamicSharedMemorySize, GW_SMEM);
    cudaFuncSetAttribute((void*)gemm_n<0>, cudaFuncAttributeMaxDynamicSharedMemorySize, GN_SMEM);
    cudaFuncSetAttribute((void*)gemm_n<2>, cudaFuncAttributeMaxDynamicSharedMemorySize, GN_SMEM);

    // weight conversions (fp16 single, transposed)
    dim3 cb(32, 8);
    conv_wTh<<<dim3(DD/32, DD/32), cb>>>(wq, wqkvT,           DD, DD);
    conv_wTh<<<dim3(DD/32, DD/32), cb>>>(wk, wqkvT + DD*DD,   DD, DD);
    conv_wTh<<<dim3(DD/32, DD/32), cb>>>(wv, wqkvT + 2*DD*DD, DD, DD);
    conv_wTh<<<dim3(DD/32, DD/32), cb>>>(wo, woT, DD, DD);
    conv_wTh<<<dim3(FFD/32, DD/32), cb>>>(w1, w1T, DD, FFD);
    conv_wTh<<<dim3(DD/32, FFD/32), cb>>>(w2, w2T, FFD, DD);
    {
        int n4 = VV * DD / 4;
        conv_half4<<<(n4 + 255) / 256, 256>>>(emb, embH, n4);
    }

    embed_kernel<<<NN, 128>>>(ids, emb, pe, x);

    dim3 gQKV(QKVD/128, NN/128);     // (12, 32) = 384 CTAs -> 86.5% quantization
    dim3 gProj(DD/128, NN/128);      // (4, 32)
    dim3 gFF1(FFD/256, NN/128);      // (8, 32)
    dim3 gAttn(SS/64, BB*HH);        // (16, 32)

    for (int layer = 0; layer < NLAYERS; layer++) {
        ln_kernel<<<NN, 128>>>(x, (uint32_t*)h16, ln1_g, ln1_b);
        gemm_n<2><<<gQKV, 256, GN_SMEM>>>(
            h16, wqkvT, nullptr, nullptr, nullptr, qkvh, QKVD, DD);
        attn_mma<<<gAttn, 128>>>(qkvh, ctx);
        gemm_n<0><<<gProj, 256, GN_SMEM>>>(
            ctx, woT, wo_b, x, x, nullptr, DD, DD);
        ln_kernel<<<NN, 128>>>(x, (uint32_t*)h16, ln2_g, ln2_b);
        gemm_w<3, 2, false, false><<<gFF1, 256, GW_SMEM>>>(
            h16, w1T, b1, nullptr, ff, FFD, DD);
        gemm_n<0><<<gProj, 256, GN_SMEM>>>(
            ff, w2T, b2, x, x, nullptr, DD, FFD);
    }

    ln_kernel<<<NN, 128>>>(x, (uint32_t*)hf, lnf_g, lnf_b);

    // LM head: M-fastest grid for B L2 reuse; streaming output stores.
    dim3 gLM(NN / 128, (VV + 255) / 256);   // (32, 197)
    gemm_w<0, 0, true, true><<<gLM, 256, GW_SMEM>>>(
        hf, embH, nullptr, out, nullptr, VV, DD);
}